// round 7
// baseline (speedup 1.0000x reference)
#include <cuda_runtime.h>
#include <cuda_bf16.h>
#include <math.h>
#include <cstdint>

// Problem constants
#define Bsz 2
#define Tt 2048
#define Cc 1024
#define Hh 16
#define HD 64
#define NTOK (Bsz*Tt)   // 4096
#define C3 (3*Cc)       // 3072
#define KEEP_INV (1.0f/0.9f)

// ---------------- scratch (device globals; no allocs allowed) ---------------
__device__ __nv_bfloat16 g_xh[(size_t)NTOK*Cc],  g_xl[(size_t)NTOK*Cc];
__device__ __nv_bfloat16 g_wqh[(size_t)C3*Cc],   g_wql[(size_t)C3*Cc];   // [N,K]
__device__ __nv_bfloat16 g_wph[(size_t)Cc*Cc],   g_wpl[(size_t)Cc*Cc];   // [N,K]
__device__ __nv_bfloat16 g_yh[(size_t)NTOK*Cc],  g_yl[(size_t)NTOK*Cc];
// split q/k: [bh][t][64]; v transposed: [bh][d][t]
__device__ __nv_bfloat16 g_qh[(size_t)32*Tt*HD], g_ql[(size_t)32*Tt*HD];
__device__ __nv_bfloat16 g_kh[(size_t)32*Tt*HD], g_kl[(size_t)32*Tt*HD];
__device__ __nv_bfloat16 g_vth[(size_t)32*HD*Tt], g_vtl[(size_t)32*HD*Tt];

// ---------------- helpers ----------------
__device__ __forceinline__ uint32_t smem_u32(const void* p) {
    uint32_t a;
    asm("{ .reg .u64 t; cvta.to.shared.u64 t, %1; cvt.u32.u64 %0, t; }" : "=r"(a) : "l"(p));
    return a;
}
__device__ __forceinline__ void cp_async16(uint32_t dst, const void* src) {
    asm volatile("cp.async.cg.shared.global [%0], [%1], 16;" :: "r"(dst), "l"(src) : "memory");
}
#define CP_COMMIT() asm volatile("cp.async.commit_group;" ::: "memory")
#define CP_WAIT(n)  asm volatile("cp.async.wait_group %0;" :: "n"(n) : "memory")

__device__ __forceinline__ void mma16816(float* c, const uint32_t* a, const uint32_t* b) {
    asm volatile("mma.sync.aligned.m16n8k16.row.col.f32.bf16.bf16.f32 "
        "{%0,%1,%2,%3}, {%4,%5,%6,%7}, {%8,%9}, {%0,%1,%2,%3};"
        : "+f"(c[0]), "+f"(c[1]), "+f"(c[2]), "+f"(c[3])
        : "r"(a[0]), "r"(a[1]), "r"(a[2]), "r"(a[3]), "r"(b[0]), "r"(b[1]));
}
__device__ __forceinline__ void ldsm4(uint32_t* r, uint32_t a) {
    asm volatile("ldmatrix.sync.aligned.m8n8.x4.shared.b16 {%0,%1,%2,%3}, [%4];"
        : "=r"(r[0]), "=r"(r[1]), "=r"(r[2]), "=r"(r[3]) : "r"(a));
}
// pack two floats into hi/lo bf16x2 (split)
__device__ __forceinline__ void split2(float a, float b, uint32_t& hi, uint32_t& lo) {
    __nv_bfloat16 ha = __float2bfloat16(a), hb = __float2bfloat16(b);
    __nv_bfloat162 H(ha, hb);
    hi = *(uint32_t*)&H;
    __nv_bfloat162 L(__float2bfloat16(a - __bfloat162float(ha)),
                     __float2bfloat16(b - __bfloat162float(hb)));
    lo = *(uint32_t*)&L;
}

// ---------------------------------------------------------------------------
// fp32 -> (hi,lo) bf16 split
// ---------------------------------------------------------------------------
__global__ __launch_bounds__(256) void cvt_split(const float4* __restrict__ in,
                                                 __nv_bfloat162* __restrict__ hi,
                                                 __nv_bfloat162* __restrict__ lo,
                                                 int n4) {
    int i = blockIdx.x * 256 + threadIdx.x;
    if (i >= n4) return;
    float4 v = in[i];
    __nv_bfloat16 hx = __float2bfloat16(v.x), hy = __float2bfloat16(v.y);
    __nv_bfloat16 hz = __float2bfloat16(v.z), hw = __float2bfloat16(v.w);
    hi[2*i]   = __nv_bfloat162(hx, hy);
    hi[2*i+1] = __nv_bfloat162(hz, hw);
    lo[2*i]   = __nv_bfloat162(__float2bfloat16(v.x - __bfloat162float(hx)),
                               __float2bfloat16(v.y - __bfloat162float(hy)));
    lo[2*i+1] = __nv_bfloat162(__float2bfloat16(v.z - __bfloat162float(hz)),
                               __float2bfloat16(v.w - __bfloat162float(hw)));
}

// fp32 W[K,N] -> transposed split bf16 [N,K]
__global__ __launch_bounds__(256) void cvt_split_T(const float* __restrict__ in,
                                                   __nv_bfloat16* __restrict__ hi,
                                                   __nv_bfloat16* __restrict__ lo,
                                                   int K, int N) {
    __shared__ float t[32][33];
    int nx = blockIdx.x * 32, kx = blockIdx.y * 32;
    int tx = threadIdx.x, ty = threadIdx.y;  // (32,8)
    #pragma unroll
    for (int r = 0; r < 4; ++r)
        t[ty + 8*r][tx] = in[(size_t)(kx + ty + 8*r) * N + nx + tx];
    __syncthreads();
    #pragma unroll
    for (int r = 0; r < 4; ++r) {
        float v = t[tx][ty + 8*r];
        size_t o = (size_t)(nx + ty + 8*r) * K + kx + tx;
        __nv_bfloat16 h = __float2bfloat16(v);
        hi[o] = h;
        lo[o] = __float2bfloat16(v - __bfloat162float(h));
    }
}

// ---------------------------------------------------------------------------
// mma.sync split-bf16 GEMM: 128x128 tile, K-chunk 32, 2-stage cp.async,
// ldmatrix.x4 fragment loads. 80KB smem -> 2 CTAs/SM.
// ---------------------------------------------------------------------------
#define SR 40
#define TILE_E (128*SR)
#define TILE_B (TILE_E*2)       // 10240 bytes
#define BUF_E  (4*TILE_E)
#define BUF_B  (4*TILE_B)       // 40960 bytes
#define GEMM_SMEM (2*BUF_B)     // 81920

__device__ __forceinline__ void gemm_issue(uint32_t sb, int buf,
                                           const __nv_bfloat16* Ah, const __nv_bfloat16* Al,
                                           const __nv_bfloat16* Bh, const __nv_bfloat16* Bl,
                                           int m0, int n0, int K, int ch, int tid) {
    #pragma unroll
    for (int it = 0; it < 8; ++it) {
        int u = tid + it * 256;
        int arr = u >> 9;
        int rem = u & 511;
        int row = rem >> 2;
        int c16 = rem & 3;
        const __nv_bfloat16* src = (arr == 0) ? Ah : (arr == 1) ? Al : (arr == 2) ? Bh : Bl;
        int grow = (arr < 2 ? m0 : n0) + row;
        uint32_t soff = (uint32_t)((buf * BUF_E + arr * TILE_E + row * SR + c16 * 8) * 2);
        cp_async16(sb + soff, src + (size_t)grow * K + ch * 32 + c16 * 8);
    }
    CP_COMMIT();
}

template<int MODE>
__global__ __launch_bounds__(256, 2) void gemm_mma(const __nv_bfloat16* __restrict__ Ah,
                                                   const __nv_bfloat16* __restrict__ Al,
                                                   const __nv_bfloat16* __restrict__ Bh,
                                                   const __nv_bfloat16* __restrict__ Bl,
                                                   const float* __restrict__ bias,
                                                   const unsigned* __restrict__ rmask,
                                                   float* __restrict__ out,
                                                   int K) {
    extern __shared__ __nv_bfloat16 smg[];
    uint32_t sb = smem_u32(smg);
    int tid = threadIdx.x, wid = tid >> 5, lane = tid & 31;
    int m0 = blockIdx.y * 128, n0 = blockIdx.x * 128;
    int wm = (wid & 3) * 32, wn = (wid >> 2) * 64;
    int qr = lane >> 2, qc = lane & 3;
    int g = lane >> 3, lr = lane & 7;

    uint32_t aoff[2], boff[4];
    #pragma unroll
    for (int i = 0; i < 2; ++i)
        aoff[i] = (uint32_t)(((wm + i*16 + lr + (g & 1)*8) * SR + (g >> 1)*8) * 2);
    #pragma unroll
    for (int jp = 0; jp < 4; ++jp)
        boff[jp] = (uint32_t)(((wn + jp*16 + lr + (g >> 1)*8) * SR + (g & 1)*8) * 2);

    float acc[2][8][4] = {};
    int nch = K >> 5;

    gemm_issue(sb, 0, Ah, Al, Bh, Bl, m0, n0, K, 0, tid);

    for (int ch = 0; ch < nch; ++ch) {
        int buf = ch & 1;
        if (ch + 1 < nch) {
            gemm_issue(sb, buf ^ 1, Ah, Al, Bh, Bl, m0, n0, K, ch + 1, tid);
            CP_WAIT(1);
        } else {
            CP_WAIT(0);
        }
        __syncthreads();

        uint32_t bAh = sb + buf * BUF_B;
        uint32_t bAl = bAh + TILE_B;
        uint32_t bBh = bAh + 2*TILE_B;
        uint32_t bBl = bAh + 3*TILE_B;

        #pragma unroll
        for (int ks = 0; ks < 2; ++ks) {
            uint32_t ksb = ks * 32;
            uint32_t ah[2][4], al[2][4];
            ldsm4(ah[0], bAh + aoff[0] + ksb);
            ldsm4(ah[1], bAh + aoff[1] + ksb);
            ldsm4(al[0], bAl + aoff[0] + ksb);
            ldsm4(al[1], bAl + aoff[1] + ksb);
            #pragma unroll
            for (int jp = 0; jp < 4; ++jp) {
                uint32_t bh4[4], bl4[4];
                ldsm4(bh4, bBh + boff[jp] + ksb);
                ldsm4(bl4, bBl + boff[jp] + ksb);
                #pragma unroll
                for (int jj = 0; jj < 2; ++jj) {
                    int j = jp*2 + jj;
                    #pragma unroll
                    for (int i = 0; i < 2; ++i) {
                        mma16816(acc[i][j], ah[i], bh4 + jj*2);
                        mma16816(acc[i][j], ah[i], bl4 + jj*2);
                        mma16816(acc[i][j], al[i], bh4 + jj*2);
                    }
                }
            }
        }
        __syncthreads();
    }

    // Epilogue
    #pragma unroll
    for (int i = 0; i < 2; ++i) {
        int R0 = m0 + wm + i * 16 + qr;
        #pragma unroll
        for (int j = 0; j < 8; ++j) {
            int C0 = n0 + wn + j * 8 + qc * 2;
            float b0 = bias[C0], b1 = bias[C0 + 1];
            #pragma unroll
            for (int hrow = 0; hrow < 2; ++hrow) {
                int m = R0 + hrow * 8;
                float v0 = acc[i][j][hrow*2 + 0] + b0;
                float v1 = acc[i][j][hrow*2 + 1] + b1;
                if (MODE == 0) {
                    int bb = m >> 11, t = m & (Tt - 1);
                    int which = C0 >> 10, cidx = C0 & 1023;
                    int h = cidx >> 6, dd = cidx & 63;
                    int bh = bb * Hh + h;
                    if (which == 0) { v0 *= 0.125f; v1 *= 0.125f; }
                    uint32_t hi, lo;
                    split2(v0, v1, hi, lo);
                    if (which == 2) {
                        size_t o0 = ((size_t)bh*HD + dd)*Tt + t;
                        size_t o1 = ((size_t)bh*HD + dd + 1)*Tt + t;
                        __nv_bfloat162 H = *(__nv_bfloat162*)&hi;
                        __nv_bfloat162 L = *(__nv_bfloat162*)&lo;
                        g_vth[o0] = H.x; g_vth[o1] = H.y;
                        g_vtl[o0] = L.x; g_vtl[o1] = L.y;
                    } else {
                        size_t o = ((size_t)bh*Tt + t)*HD + dd;
                        __nv_bfloat16* dh = (which == 0) ? g_qh : g_kh;
                        __nv_bfloat16* dl = (which == 0) ? g_ql : g_kl;
                        *(uint32_t*)&dh[o] = hi;
                        *(uint32_t*)&dl[o] = lo;
                    }
                } else {
                    size_t idx = (size_t)m * Cc + C0;
                    out[idx]     = rmask[idx]     ? v0 * KEEP_INV : 0.f;
                    out[idx + 1] = rmask[idx + 1] ? v1 * KEEP_INV : 0.f;
                }
            }
        }
    }
}

// ---------------------------------------------------------------------------
// Flash attention on HMMA + ldmatrix. Mask loaded from gmem then bit-packed
// into 2 registers before QK (kills the 32-reg live range -> no spills).
// 108KB smem -> 2 CTAs/SM.
// ---------------------------------------------------------------------------
#define SRK 72                       // bf16 row stride for 64-col tiles
#define OQH 0
#define OQL (128*SRK*2)              // 18432
#define OB0 (2*128*SRK*2)            // 36864
#define KVB (64*SRK*2)               // 9216
#define BUFB (4*KVB)                 // 36864
#define FLASH_SMEM (OB0 + 2*BUFB)    // 110592

__device__ __forceinline__ void flash_issue(uint32_t sb, int buf,
                                            int bh, int k0, int tid) {
    #pragma unroll
    for (int it = 0; it < 8; ++it) {
        int u = tid + it * 256;
        int arr = u >> 9;
        int rem = u & 511;
        int row = rem >> 3;
        int ck = rem & 7;
        const __nv_bfloat16* src;
        size_t gofs;
        if (arr < 2) {
            src = (arr == 0) ? g_kh : g_kl;
            gofs = ((size_t)bh*Tt + k0 + row)*HD + ck*8;
        } else {
            src = (arr == 2) ? g_vth : g_vtl;
            gofs = ((size_t)bh*HD + row)*Tt + k0 + ck*8;
        }
        uint32_t dst = sb + OB0 + buf*BUFB + arr*KVB + (uint32_t)(row*SRK + ck*8)*2;
        cp_async16(dst, src + gofs);
    }
    CP_COMMIT();
}

__global__ __launch_bounds__(256, 2) void flash_mma(const unsigned* __restrict__ amask) {
    extern __shared__ char smf[];
    uint32_t sb = smem_u32(smf);
    int tid = threadIdx.x, wid = tid >> 5, lane = tid & 31;
    int qr = lane >> 2, qc = lane & 3;
    int g = lane >> 3, lr = lane & 7;
    int bh = blockIdx.y;
    int qb = (gridDim.x - 1) - blockIdx.x;   // big tiles first
    int q0 = qb * 128;
    int nkt = qb * 2 + 2;

    // Q tile load (split) — same cp.async group as tile 0
    #pragma unroll
    for (int it = 0; it < 8; ++it) {
        int u = tid + it * 256;
        int arr = u >> 10;
        int rem = u & 1023;
        int row = rem >> 3;
        int ck = rem & 7;
        const __nv_bfloat16* src = arr ? g_ql : g_qh;
        uint32_t dst = sb + (arr ? OQL : OQH) + (uint32_t)(row*SRK + ck*8)*2;
        cp_async16(dst, src + ((size_t)bh*Tt + q0 + row)*HD + ck*8);
    }
    flash_issue(sb, 0, bh, 0, tid);

    uint32_t qaoff = (uint32_t)(((wid*16 + lr + (g & 1)*8) * SRK + (g >> 1)*8) * 2);
    uint32_t bofff[4];
    #pragma unroll
    for (int jp = 0; jp < 4; ++jp)
        bofff[jp] = (uint32_t)(((jp*16 + lr + (g >> 1)*8) * SRK + (g & 1)*8) * 2);

    int r = wid * 16 + qr;                  // q row within tile
    int rowmax = q0 + wid * 16 + 15;
    // gmem mask row base for this thread's two row-octets
    const unsigned* mrow0 = amask + ((size_t)bh*Tt + q0 + r)*Tt + qc*2;
    const unsigned* mrow1 = mrow0 + (size_t)8*Tt;

    float acc[8][4] = {};
    float m0 = -INFINITY, m1 = -INFINITY, l0 = 0.f, l1 = 0.f;

    for (int kt = 0; kt < nkt; ++kt) {
        int buf = kt & 1;
        int k0 = kt * 64;
        if (kt + 1 < nkt) {
            flash_issue(sb, buf ^ 1, bh, (kt+1)*64, tid);
            CP_WAIT(1);
        } else {
            CP_WAIT(0);
        }
        __syncthreads();

        if (k0 <= rowmax) {
            uint32_t kbh = sb + OB0 + buf*BUFB;
            uint32_t kbl = kbh + KVB;
            uint32_t vbh = kbh + 2*KVB;
            uint32_t vbl = kbh + 3*KVB;

            // ---- mask load + immediate bit-pack (2 regs live across QK) ----
            uint2 t0[8], t1[8];
            #pragma unroll
            for (int j = 0; j < 8; ++j) {
                t0[j] = *(const uint2*)(mrow0 + k0 + j*8);
                t1[j] = *(const uint2*)(mrow1 + k0 + j*8);
            }
            uint32_t bm0 = 0, bm1 = 0;
            #pragma unroll
            for (int j = 0; j < 8; ++j) {
                bm0 |= (t0[j].x ? 1u : 0u) << (2*j);
                bm0 |= (t0[j].y ? 1u : 0u) << (2*j + 1);
                bm1 |= (t1[j].x ? 1u : 0u) << (2*j);
                bm1 |= (t1[j].y ? 1u : 0u) << (2*j + 1);
            }
            // pin the pack before the MMAs (prevents ptxas sinking it,
            // which would re-extend the 32-reg mask live range)
            asm volatile("" : "+r"(bm0), "+r"(bm1));

            // ---- S = Q K^T (split 3-term) ----
            float s[8][4] = {};
            #pragma unroll
            for (int ks = 0; ks < 4; ++ks) {
                uint32_t ksb = ks * 32;
                uint32_t ah[4], al[4];
                ldsm4(ah, sb + OQH + qaoff + ksb);
                ldsm4(al, sb + OQL + qaoff + ksb);
                #pragma unroll
                for (int jp = 0; jp < 4; ++jp) {
                    uint32_t kh4[4], kl4[4];
                    ldsm4(kh4, kbh + bofff[jp] + ksb);
                    ldsm4(kl4, kbl + bofff[jp] + ksb);
                    #pragma unroll
                    for (int jj = 0; jj < 2; ++jj) {
                        mma16816(s[jp*2+jj], ah, kh4 + jj*2);
                        mma16816(s[jp*2+jj], ah, kl4 + jj*2);
                        mma16816(s[jp*2+jj], al, kh4 + jj*2);
                    }
                }
            }

            // ---- causal mask ----
            int row0 = q0 + r, row1 = row0 + 8;
            #pragma unroll
            for (int j = 0; j < 8; ++j) {
                int cg = k0 + j*8 + qc*2;
                if (cg     > row0) s[j][0] = -INFINITY;
                if (cg + 1 > row0) s[j][1] = -INFINITY;
                if (cg     > row1) s[j][2] = -INFINITY;
                if (cg + 1 > row1) s[j][3] = -INFINITY;
            }

            // ---- online softmax (undropped denominator) ----
            float mx0 = -INFINITY, mx1 = -INFINITY;
            #pragma unroll
            for (int j = 0; j < 8; ++j) {
                mx0 = fmaxf(mx0, fmaxf(s[j][0], s[j][1]));
                mx1 = fmaxf(mx1, fmaxf(s[j][2], s[j][3]));
            }
            mx0 = fmaxf(mx0, __shfl_xor_sync(0xffffffffu, mx0, 1));
            mx0 = fmaxf(mx0, __shfl_xor_sync(0xffffffffu, mx0, 2));
            mx1 = fmaxf(mx1, __shfl_xor_sync(0xffffffffu, mx1, 1));
            mx1 = fmaxf(mx1, __shfl_xor_sync(0xffffffffu, mx1, 2));
            float m0n = fmaxf(m0, mx0), m1n = fmaxf(m1, mx1);
            float a0 = __expf(m0 - m0n), a1 = __expf(m1 - m1n);
            float sum0 = 0.f, sum1 = 0.f;
            #pragma unroll
            for (int j = 0; j < 8; ++j) {
                float p0 = __expf(s[j][0] - m0n); sum0 += p0;
                float p1 = __expf(s[j][1] - m0n); sum0 += p1;
                float p2 = __expf(s[j][2] - m1n); sum1 += p2;
                float p3 = __expf(s[j][3] - m1n); sum1 += p3;
                s[j][0] = ((bm0 >> (2*j))     & 1u) ? p0 * KEEP_INV : 0.f;
                s[j][1] = ((bm0 >> (2*j + 1)) & 1u) ? p1 * KEEP_INV : 0.f;
                s[j][2] = ((bm1 >> (2*j))     & 1u) ? p2 * KEEP_INV : 0.f;
                s[j][3] = ((bm1 >> (2*j + 1)) & 1u) ? p3 * KEEP_INV : 0.f;
            }
            sum0 += __shfl_xor_sync(0xffffffffu, sum0, 1);
            sum0 += __shfl_xor_sync(0xffffffffu, sum0, 2);
            sum1 += __shfl_xor_sync(0xffffffffu, sum1, 1);
            sum1 += __shfl_xor_sync(0xffffffffu, sum1, 2);
            l0 = l0 * a0 + sum0;
            l1 = l1 * a1 + sum1;
            m0 = m0n; m1 = m1n;

            // ---- acc scale + P V (split 3-term, P from registers) ----
            #pragma unroll
            for (int j = 0; j < 8; ++j) {
                acc[j][0] *= a0; acc[j][1] *= a0;
                acc[j][2] *= a1; acc[j][3] *= a1;
            }
            #pragma unroll
            for (int s4 = 0; s4 < 4; ++s4) {
                uint32_t ph[4], pl[4];
                split2(s[2*s4][0],   s[2*s4][1],   ph[0], pl[0]);
                split2(s[2*s4][2],   s[2*s4][3],   ph[1], pl[1]);
                split2(s[2*s4+1][0], s[2*s4+1][1], ph[2], pl[2]);
                split2(s[2*s4+1][2], s[2*s4+1][3], ph[3], pl[3]);
                uint32_t ksb = s4 * 32;
                #pragma unroll
                for (int jp = 0; jp < 4; ++jp) {
                    uint32_t vh4[4], vl4[4];
                    ldsm4(vh4, vbh + bofff[jp] + ksb);
                    ldsm4(vl4, vbl + bofff[jp] + ksb);
                    #pragma unroll
                    for (int jj = 0; jj < 2; ++jj) {
                        mma16816(acc[jp*2+jj], ph, vh4 + jj*2);
                        mma16816(acc[jp*2+jj], ph, vl4 + jj*2);
                        mma16816(acc[jp*2+jj], pl, vh4 + jj*2);
                    }
                }
            }
        }
        __syncthreads();
    }

    // ---- epilogue: y = acc / l, write split bf16 [tok][C] ----
    int b = bh >> 4, h = bh & 15;
    float inv0 = 1.f / l0, inv1 = 1.f / l1;
    size_t tok0 = (size_t)b*Tt + q0 + r;
    size_t tok1 = tok0 + 8;
    #pragma unroll
    for (int j = 0; j < 8; ++j) {
        int col = h*HD + j*8 + qc*2;
        uint32_t hi, lo;
        split2(acc[j][0]*inv0, acc[j][1]*inv0, hi, lo);
        *(uint32_t*)&g_yh[tok0*Cc + col] = hi;
        *(uint32_t*)&g_yl[tok0*Cc + col] = lo;
        split2(acc[j][2]*inv1, acc[j][3]*inv1, hi, lo);
        *(uint32_t*)&g_yh[tok1*Cc + col] = hi;
        *(uint32_t*)&g_yl[tok1*Cc + col] = lo;
    }
}

// ---------------------------------------------------------------------------
extern "C" void kernel_launch(void* const* d_in, const int* in_sizes, int n_in,
                              void* d_out, int out_size) {
    const float* x     = (const float*)d_in[0];
    const float* Wqkv  = (const float*)d_in[1];
    const float* bqkv  = (const float*)d_in[2];
    const float* Wproj = (const float*)d_in[3];
    const float* bproj = (const float*)d_in[4];
    const unsigned* amask = (const unsigned*)d_in[5];
    const unsigned* rmask = (const unsigned*)d_in[6];
    float* out = (float*)d_out;

    cudaFuncSetAttribute(gemm_mma<0>, cudaFuncAttributeMaxDynamicSharedMemorySize, GEMM_SMEM);
    cudaFuncSetAttribute(gemm_mma<1>, cudaFuncAttributeMaxDynamicSharedMemorySize, GEMM_SMEM);
    cudaFuncSetAttribute(flash_mma, cudaFuncAttributeMaxDynamicSharedMemorySize, FLASH_SMEM);

    __nv_bfloat16 *xh, *xl, *wqh, *wql, *wph, *wpl, *yh, *yl;
    cudaGetSymbolAddress((void**)&xh,  g_xh);  cudaGetSymbolAddress((void**)&xl,  g_xl);
    cudaGetSymbolAddress((void**)&wqh, g_wqh); cudaGetSymbolAddress((void**)&wql, g_wql);
    cudaGetSymbolAddress((void**)&wph, g_wph); cudaGetSymbolAddress((void**)&wpl, g_wpl);
    cudaGetSymbolAddress((void**)&yh,  g_yh);  cudaGetSymbolAddress((void**)&yl,  g_yl);

    cvt_split<<<(NTOK*Cc/4 + 255)/256, 256>>>((const float4*)x, (__nv_bfloat162*)xh, (__nv_bfloat162*)xl, NTOK*Cc/4);
    cvt_split_T<<<dim3(C3/32, Cc/32), dim3(32,8)>>>(Wqkv, wqh, wql, Cc, C3);
    cvt_split_T<<<dim3(Cc/32, Cc/32), dim3(32,8)>>>(Wproj, wph, wpl, Cc, Cc);

    gemm_mma<0><<<dim3(C3/128, NTOK/128), 256, GEMM_SMEM>>>(xh, xl, wqh, wql, bqkv, nullptr, nullptr, Cc);

    flash_mma<<<dim3(Tt/128, Bsz*Hh), 256, FLASH_SMEM>>>(amask);

    gemm_mma<1><<<dim3(Cc/128, NTOK/128), 256, GEMM_SMEM>>>(yh, yl, wph, wpl, bproj, rmask, out, Cc);
}

// round 8
// speedup vs baseline: 1.0750x; 1.0750x over previous
#include <cuda_runtime.h>
#include <cuda_bf16.h>
#include <math.h>
#include <cstdint>

// Problem constants
#define Bsz 2
#define Tt 2048
#define Cc 1024
#define Hh 16
#define HD 64
#define NTOK (Bsz*Tt)   // 4096
#define C3 (3*Cc)       // 3072
#define KEEP_INV (1.0f/0.9f)

// ---------------- scratch (device globals; no allocs allowed) ---------------
__device__ __nv_bfloat16 g_xh[(size_t)NTOK*Cc],  g_xl[(size_t)NTOK*Cc];
__device__ __nv_bfloat16 g_wqh[(size_t)C3*Cc],   g_wql[(size_t)C3*Cc];   // [N,K]
__device__ __nv_bfloat16 g_wph[(size_t)Cc*Cc],   g_wpl[(size_t)Cc*Cc];   // [N,K]
__device__ __nv_bfloat16 g_yh[(size_t)NTOK*Cc],  g_yl[(size_t)NTOK*Cc];
// split q/k: [bh][t][64]; v transposed: [bh][d][t]
__device__ __nv_bfloat16 g_qh[(size_t)32*Tt*HD], g_ql[(size_t)32*Tt*HD];
__device__ __nv_bfloat16 g_kh[(size_t)32*Tt*HD], g_kl[(size_t)32*Tt*HD];
__device__ __nv_bfloat16 g_vth[(size_t)32*HD*Tt], g_vtl[(size_t)32*HD*Tt];

// ---------------- helpers ----------------
__device__ __forceinline__ uint32_t smem_u32(const void* p) {
    uint32_t a;
    asm("{ .reg .u64 t; cvta.to.shared.u64 t, %1; cvt.u32.u64 %0, t; }" : "=r"(a) : "l"(p));
    return a;
}
__device__ __forceinline__ void cp_async16(uint32_t dst, const void* src) {
    asm volatile("cp.async.cg.shared.global [%0], [%1], 16;" :: "r"(dst), "l"(src) : "memory");
}
#define CP_COMMIT() asm volatile("cp.async.commit_group;" ::: "memory")
#define CP_WAIT(n)  asm volatile("cp.async.wait_group %0;" :: "n"(n) : "memory")

__device__ __forceinline__ void mma16816(float* c, const uint32_t* a, const uint32_t* b) {
    asm volatile("mma.sync.aligned.m16n8k16.row.col.f32.bf16.bf16.f32 "
        "{%0,%1,%2,%3}, {%4,%5,%6,%7}, {%8,%9}, {%0,%1,%2,%3};"
        : "+f"(c[0]), "+f"(c[1]), "+f"(c[2]), "+f"(c[3])
        : "r"(a[0]), "r"(a[1]), "r"(a[2]), "r"(a[3]), "r"(b[0]), "r"(b[1]));
}
__device__ __forceinline__ void ldsm4(uint32_t* r, uint32_t a) {
    asm volatile("ldmatrix.sync.aligned.m8n8.x4.shared.b16 {%0,%1,%2,%3}, [%4];"
        : "=r"(r[0]), "=r"(r[1]), "=r"(r[2]), "=r"(r[3]) : "r"(a));
}
// pack two floats into hi/lo bf16x2 (split)
__device__ __forceinline__ void split2(float a, float b, uint32_t& hi, uint32_t& lo) {
    __nv_bfloat16 ha = __float2bfloat16(a), hb = __float2bfloat16(b);
    __nv_bfloat162 H(ha, hb);
    hi = *(uint32_t*)&H;
    __nv_bfloat162 L(__float2bfloat16(a - __bfloat162float(ha)),
                     __float2bfloat16(b - __bfloat162float(hb)));
    lo = *(uint32_t*)&L;
}

// ---------------------------------------------------------------------------
// fp32 -> (hi,lo) bf16 split
// ---------------------------------------------------------------------------
__global__ __launch_bounds__(256) void cvt_split(const float4* __restrict__ in,
                                                 __nv_bfloat162* __restrict__ hi,
                                                 __nv_bfloat162* __restrict__ lo,
                                                 int n4) {
    int i = blockIdx.x * 256 + threadIdx.x;
    if (i >= n4) return;
    float4 v = in[i];
    __nv_bfloat16 hx = __float2bfloat16(v.x), hy = __float2bfloat16(v.y);
    __nv_bfloat16 hz = __float2bfloat16(v.z), hw = __float2bfloat16(v.w);
    hi[2*i]   = __nv_bfloat162(hx, hy);
    hi[2*i+1] = __nv_bfloat162(hz, hw);
    lo[2*i]   = __nv_bfloat162(__float2bfloat16(v.x - __bfloat162float(hx)),
                               __float2bfloat16(v.y - __bfloat162float(hy)));
    lo[2*i+1] = __nv_bfloat162(__float2bfloat16(v.z - __bfloat162float(hz)),
                               __float2bfloat16(v.w - __bfloat162float(hw)));
}

// fp32 W[K,N] -> transposed split bf16 [N,K]
__global__ __launch_bounds__(256) void cvt_split_T(const float* __restrict__ in,
                                                   __nv_bfloat16* __restrict__ hi,
                                                   __nv_bfloat16* __restrict__ lo,
                                                   int K, int N) {
    __shared__ float t[32][33];
    int nx = blockIdx.x * 32, kx = blockIdx.y * 32;
    int tx = threadIdx.x, ty = threadIdx.y;  // (32,8)
    #pragma unroll
    for (int r = 0; r < 4; ++r)
        t[ty + 8*r][tx] = in[(size_t)(kx + ty + 8*r) * N + nx + tx];
    __syncthreads();
    #pragma unroll
    for (int r = 0; r < 4; ++r) {
        float v = t[tx][ty + 8*r];
        size_t o = (size_t)(nx + ty + 8*r) * K + kx + tx;
        __nv_bfloat16 h = __float2bfloat16(v);
        hi[o] = h;
        lo[o] = __float2bfloat16(v - __bfloat162float(h));
    }
}

// ---------------------------------------------------------------------------
// mma.sync split-bf16 GEMM: 128x128 tile, K-chunk 32, 2-stage cp.async,
// ldmatrix.x4, term-major MMA ordering (8-deep independent accumulator runs).
// ---------------------------------------------------------------------------
#define SR 40
#define TILE_E (128*SR)
#define TILE_B (TILE_E*2)       // 10240 bytes
#define BUF_E  (4*TILE_E)
#define BUF_B  (4*TILE_B)       // 40960 bytes
#define GEMM_SMEM (2*BUF_B)     // 81920

__device__ __forceinline__ void gemm_issue(uint32_t sb, int buf,
                                           const __nv_bfloat16* Ah, const __nv_bfloat16* Al,
                                           const __nv_bfloat16* Bh, const __nv_bfloat16* Bl,
                                           int m0, int n0, int K, int ch, int tid) {
    #pragma unroll
    for (int it = 0; it < 8; ++it) {
        int u = tid + it * 256;
        int arr = u >> 9;
        int rem = u & 511;
        int row = rem >> 2;
        int c16 = rem & 3;
        const __nv_bfloat16* src = (arr == 0) ? Ah : (arr == 1) ? Al : (arr == 2) ? Bh : Bl;
        int grow = (arr < 2 ? m0 : n0) + row;
        uint32_t soff = (uint32_t)((buf * BUF_E + arr * TILE_E + row * SR + c16 * 8) * 2);
        cp_async16(sb + soff, src + (size_t)grow * K + ch * 32 + c16 * 8);
    }
    CP_COMMIT();
}

template<int MODE>
__global__ __launch_bounds__(256, 2) void gemm_mma(const __nv_bfloat16* __restrict__ Ah,
                                                   const __nv_bfloat16* __restrict__ Al,
                                                   const __nv_bfloat16* __restrict__ Bh,
                                                   const __nv_bfloat16* __restrict__ Bl,
                                                   const float* __restrict__ bias,
                                                   const unsigned* __restrict__ rmask,
                                                   float* __restrict__ out,
                                                   int K) {
    extern __shared__ __nv_bfloat16 smg[];
    uint32_t sb = smem_u32(smg);
    int tid = threadIdx.x, wid = tid >> 5, lane = tid & 31;
    int m0 = blockIdx.y * 128, n0 = blockIdx.x * 128;
    int wm = (wid & 3) * 32, wn = (wid >> 2) * 64;
    int qr = lane >> 2, qc = lane & 3;
    int g = lane >> 3, lr = lane & 7;

    uint32_t aoff[2], boff[4];
    #pragma unroll
    for (int i = 0; i < 2; ++i)
        aoff[i] = (uint32_t)(((wm + i*16 + lr + (g & 1)*8) * SR + (g >> 1)*8) * 2);
    #pragma unroll
    for (int jp = 0; jp < 4; ++jp)
        boff[jp] = (uint32_t)(((wn + jp*16 + lr + (g >> 1)*8) * SR + (g & 1)*8) * 2);

    float acc[2][8][4] = {};
    int nch = K >> 5;

    gemm_issue(sb, 0, Ah, Al, Bh, Bl, m0, n0, K, 0, tid);

    for (int ch = 0; ch < nch; ++ch) {
        int buf = ch & 1;
        if (ch + 1 < nch) {
            gemm_issue(sb, buf ^ 1, Ah, Al, Bh, Bl, m0, n0, K, ch + 1, tid);
            CP_WAIT(1);
        } else {
            CP_WAIT(0);
        }
        __syncthreads();

        uint32_t bAh = sb + buf * BUF_B;
        uint32_t bAl = bAh + TILE_B;
        uint32_t bBh = bAh + 2*TILE_B;
        uint32_t bBl = bAh + 3*TILE_B;

        #pragma unroll
        for (int ks = 0; ks < 2; ++ks) {
            uint32_t ksb = ks * 32;
            uint32_t ah[2][4], al[2][4];
            ldsm4(ah[0], bAh + aoff[0] + ksb);
            ldsm4(ah[1], bAh + aoff[1] + ksb);
            ldsm4(al[0], bAl + aoff[0] + ksb);
            ldsm4(al[1], bAl + aoff[1] + ksb);
            #pragma unroll
            for (int jp2 = 0; jp2 < 2; ++jp2) {
                uint32_t bh4[2][4], bl4[2][4];
                ldsm4(bh4[0], bBh + boff[2*jp2]     + ksb);
                ldsm4(bh4[1], bBh + boff[2*jp2 + 1] + ksb);
                ldsm4(bl4[0], bBl + boff[2*jp2]     + ksb);
                ldsm4(bl4[1], bBl + boff[2*jp2 + 1] + ksb);
                // term-major: 8 independent accumulators per term sweep
                #pragma unroll
                for (int p = 0; p < 2; ++p)
                    #pragma unroll
                    for (int jj = 0; jj < 2; ++jj)
                        #pragma unroll
                        for (int i = 0; i < 2; ++i)
                            mma16816(acc[i][(2*jp2+p)*2+jj], ah[i], bh4[p] + jj*2);
                #pragma unroll
                for (int p = 0; p < 2; ++p)
                    #pragma unroll
                    for (int jj = 0; jj < 2; ++jj)
                        #pragma unroll
                        for (int i = 0; i < 2; ++i)
                            mma16816(acc[i][(2*jp2+p)*2+jj], ah[i], bl4[p] + jj*2);
                #pragma unroll
                for (int p = 0; p < 2; ++p)
                    #pragma unroll
                    for (int jj = 0; jj < 2; ++jj)
                        #pragma unroll
                        for (int i = 0; i < 2; ++i)
                            mma16816(acc[i][(2*jp2+p)*2+jj], al[i], bh4[p] + jj*2);
            }
        }
        __syncthreads();
    }

    // Epilogue
    #pragma unroll
    for (int i = 0; i < 2; ++i) {
        int R0 = m0 + wm + i * 16 + qr;
        #pragma unroll
        for (int j = 0; j < 8; ++j) {
            int C0 = n0 + wn + j * 8 + qc * 2;
            float b0 = bias[C0], b1 = bias[C0 + 1];
            #pragma unroll
            for (int hrow = 0; hrow < 2; ++hrow) {
                int m = R0 + hrow * 8;
                float v0 = acc[i][j][hrow*2 + 0] + b0;
                float v1 = acc[i][j][hrow*2 + 1] + b1;
                if (MODE == 0) {
                    int bb = m >> 11, t = m & (Tt - 1);
                    int which = C0 >> 10, cidx = C0 & 1023;
                    int h = cidx >> 6, dd = cidx & 63;
                    int bh = bb * Hh + h;
                    if (which == 0) { v0 *= 0.125f; v1 *= 0.125f; }
                    uint32_t hi, lo;
                    split2(v0, v1, hi, lo);
                    if (which == 2) {
                        size_t o0 = ((size_t)bh*HD + dd)*Tt + t;
                        size_t o1 = ((size_t)bh*HD + dd + 1)*Tt + t;
                        __nv_bfloat162 H = *(__nv_bfloat162*)&hi;
                        __nv_bfloat162 L = *(__nv_bfloat162*)&lo;
                        g_vth[o0] = H.x; g_vth[o1] = H.y;
                        g_vtl[o0] = L.x; g_vtl[o1] = L.y;
                    } else {
                        size_t o = ((size_t)bh*Tt + t)*HD + dd;
                        __nv_bfloat16* dh = (which == 0) ? g_qh : g_kh;
                        __nv_bfloat16* dl = (which == 0) ? g_ql : g_kl;
                        *(uint32_t*)&dh[o] = hi;
                        *(uint32_t*)&dl[o] = lo;
                    }
                } else {
                    size_t idx = (size_t)m * Cc + C0;
                    out[idx]     = rmask[idx]     ? v0 * KEEP_INV : 0.f;
                    out[idx + 1] = rmask[idx + 1] ? v1 * KEEP_INV : 0.f;
                }
            }
        }
    }
}

// ---------------------------------------------------------------------------
// Flash attention on HMMA + ldmatrix. Mask from gmem (consumed late, overlaps
// MMAs naturally — R7's pinning reverted). Term-major MMA ordering.
// 108KB smem -> 2 CTAs/SM.
// ---------------------------------------------------------------------------
#define SRK 72                       // bf16 row stride for 64-col tiles
#define OQH 0
#define OQL (128*SRK*2)              // 18432
#define OB0 (2*128*SRK*2)            // 36864
#define KVB (64*SRK*2)               // 9216
#define BUFB (4*KVB)                 // 36864
#define FLASH_SMEM (OB0 + 2*BUFB)    // 110592

__device__ __forceinline__ void flash_issue(uint32_t sb, int buf,
                                            int bh, int k0, int tid) {
    #pragma unroll
    for (int it = 0; it < 8; ++it) {
        int u = tid + it * 256;
        int arr = u >> 9;
        int rem = u & 511;
        int row = rem >> 3;
        int ck = rem & 7;
        const __nv_bfloat16* src;
        size_t gofs;
        if (arr < 2) {
            src = (arr == 0) ? g_kh : g_kl;
            gofs = ((size_t)bh*Tt + k0 + row)*HD + ck*8;
        } else {
            src = (arr == 2) ? g_vth : g_vtl;
            gofs = ((size_t)bh*HD + row)*Tt + k0 + ck*8;
        }
        uint32_t dst = sb + OB0 + buf*BUFB + arr*KVB + (uint32_t)(row*SRK + ck*8)*2;
        cp_async16(dst, src + gofs);
    }
    CP_COMMIT();
}

__global__ __launch_bounds__(256, 2) void flash_mma(const unsigned* __restrict__ amask) {
    extern __shared__ char smf[];
    uint32_t sb = smem_u32(smf);
    int tid = threadIdx.x, wid = tid >> 5, lane = tid & 31;
    int qr = lane >> 2, qc = lane & 3;
    int g = lane >> 3, lr = lane & 7;
    int bh = blockIdx.y;
    int qb = (gridDim.x - 1) - blockIdx.x;   // big tiles first
    int q0 = qb * 128;
    int nkt = qb * 2 + 2;

    // Q tile load (split) — same cp.async group as tile 0
    #pragma unroll
    for (int it = 0; it < 8; ++it) {
        int u = tid + it * 256;
        int arr = u >> 10;
        int rem = u & 1023;
        int row = rem >> 3;
        int ck = rem & 7;
        const __nv_bfloat16* src = arr ? g_ql : g_qh;
        uint32_t dst = sb + (arr ? OQL : OQH) + (uint32_t)(row*SRK + ck*8)*2;
        cp_async16(dst, src + ((size_t)bh*Tt + q0 + row)*HD + ck*8);
    }
    flash_issue(sb, 0, bh, 0, tid);

    uint32_t qaoff = (uint32_t)(((wid*16 + lr + (g & 1)*8) * SRK + (g >> 1)*8) * 2);
    uint32_t bofff[4];
    #pragma unroll
    for (int jp = 0; jp < 4; ++jp)
        bofff[jp] = (uint32_t)(((jp*16 + lr + (g >> 1)*8) * SRK + (g & 1)*8) * 2);

    int r = wid * 16 + qr;                  // q row within tile
    int rowmax = q0 + wid * 16 + 15;
    const unsigned* mrow0 = amask + ((size_t)bh*Tt + q0 + r)*Tt + qc*2;
    const unsigned* mrow1 = mrow0 + (size_t)8*Tt;

    float acc[8][4] = {};
    float m0 = -INFINITY, m1 = -INFINITY, l0 = 0.f, l1 = 0.f;

    for (int kt = 0; kt < nkt; ++kt) {
        int buf = kt & 1;
        int k0 = kt * 64;
        if (kt + 1 < nkt) {
            flash_issue(sb, buf ^ 1, bh, (kt+1)*64, tid);
            CP_WAIT(1);
        } else {
            CP_WAIT(0);
        }
        __syncthreads();

        if (k0 <= rowmax) {
            uint32_t kbh = sb + OB0 + buf*BUFB;
            uint32_t kbl = kbh + KVB;
            uint32_t vbh = kbh + 2*KVB;
            uint32_t vbl = kbh + 3*KVB;

            // ---- mask prefetch (gmem -> regs), consumed at softmax ----
            uint2 km0[8], km1[8];
            #pragma unroll
            for (int j = 0; j < 8; ++j) {
                km0[j] = *(const uint2*)(mrow0 + k0 + j*8);
                km1[j] = *(const uint2*)(mrow1 + k0 + j*8);
            }

            // ---- S = Q K^T (split 3-term, term-major over jp pairs) ----
            float s[8][4] = {};
            #pragma unroll
            for (int ks = 0; ks < 4; ++ks) {
                uint32_t ksb = ks * 32;
                uint32_t ah[4], al[4];
                ldsm4(ah, sb + OQH + qaoff + ksb);
                ldsm4(al, sb + OQL + qaoff + ksb);
                #pragma unroll
                for (int jp2 = 0; jp2 < 2; ++jp2) {
                    uint32_t kh4[2][4], kl4[2][4];
                    ldsm4(kh4[0], kbh + bofff[2*jp2]     + ksb);
                    ldsm4(kh4[1], kbh + bofff[2*jp2 + 1] + ksb);
                    ldsm4(kl4[0], kbl + bofff[2*jp2]     + ksb);
                    ldsm4(kl4[1], kbl + bofff[2*jp2 + 1] + ksb);
                    #pragma unroll
                    for (int p = 0; p < 2; ++p)
                        #pragma unroll
                        for (int jj = 0; jj < 2; ++jj)
                            mma16816(s[(2*jp2+p)*2+jj], ah, kh4[p] + jj*2);
                    #pragma unroll
                    for (int p = 0; p < 2; ++p)
                        #pragma unroll
                        for (int jj = 0; jj < 2; ++jj)
                            mma16816(s[(2*jp2+p)*2+jj], ah, kl4[p] + jj*2);
                    #pragma unroll
                    for (int p = 0; p < 2; ++p)
                        #pragma unroll
                        for (int jj = 0; jj < 2; ++jj)
                            mma16816(s[(2*jp2+p)*2+jj], al, kh4[p] + jj*2);
                }
            }

            // ---- causal mask ----
            int row0 = q0 + r, row1 = row0 + 8;
            #pragma unroll
            for (int j = 0; j < 8; ++j) {
                int cg = k0 + j*8 + qc*2;
                if (cg     > row0) s[j][0] = -INFINITY;
                if (cg + 1 > row0) s[j][1] = -INFINITY;
                if (cg     > row1) s[j][2] = -INFINITY;
                if (cg + 1 > row1) s[j][3] = -INFINITY;
            }

            // ---- online softmax (undropped denominator) ----
            float mx0 = -INFINITY, mx1 = -INFINITY;
            #pragma unroll
            for (int j = 0; j < 8; ++j) {
                mx0 = fmaxf(mx0, fmaxf(s[j][0], s[j][1]));
                mx1 = fmaxf(mx1, fmaxf(s[j][2], s[j][3]));
            }
            mx0 = fmaxf(mx0, __shfl_xor_sync(0xffffffffu, mx0, 1));
            mx0 = fmaxf(mx0, __shfl_xor_sync(0xffffffffu, mx0, 2));
            mx1 = fmaxf(mx1, __shfl_xor_sync(0xffffffffu, mx1, 1));
            mx1 = fmaxf(mx1, __shfl_xor_sync(0xffffffffu, mx1, 2));
            float m0n = fmaxf(m0, mx0), m1n = fmaxf(m1, mx1);
            float a0 = __expf(m0 - m0n), a1 = __expf(m1 - m1n);
            float sum0 = 0.f, sum1 = 0.f;
            #pragma unroll
            for (int j = 0; j < 8; ++j) {
                float p0 = __expf(s[j][0] - m0n); sum0 += p0;
                float p1 = __expf(s[j][1] - m0n); sum0 += p1;
                float p2 = __expf(s[j][2] - m1n); sum1 += p2;
                float p3 = __expf(s[j][3] - m1n); sum1 += p3;
                s[j][0] = km0[j].x ? p0 * KEEP_INV : 0.f;
                s[j][1] = km0[j].y ? p1 * KEEP_INV : 0.f;
                s[j][2] = km1[j].x ? p2 * KEEP_INV : 0.f;
                s[j][3] = km1[j].y ? p3 * KEEP_INV : 0.f;
            }
            sum0 += __shfl_xor_sync(0xffffffffu, sum0, 1);
            sum0 += __shfl_xor_sync(0xffffffffu, sum0, 2);
            sum1 += __shfl_xor_sync(0xffffffffu, sum1, 1);
            sum1 += __shfl_xor_sync(0xffffffffu, sum1, 2);
            l0 = l0 * a0 + sum0;
            l1 = l1 * a1 + sum1;
            m0 = m0n; m1 = m1n;

            // ---- acc scale + P V (split 3-term, term-major over jp pairs) ----
            #pragma unroll
            for (int j = 0; j < 8; ++j) {
                acc[j][0] *= a0; acc[j][1] *= a0;
                acc[j][2] *= a1; acc[j][3] *= a1;
            }
            #pragma unroll
            for (int s4 = 0; s4 < 4; ++s4) {
                uint32_t ph[4], pl[4];
                split2(s[2*s4][0],   s[2*s4][1],   ph[0], pl[0]);
                split2(s[2*s4][2],   s[2*s4][3],   ph[1], pl[1]);
                split2(s[2*s4+1][0], s[2*s4+1][1], ph[2], pl[2]);
                split2(s[2*s4+1][2], s[2*s4+1][3], ph[3], pl[3]);
                uint32_t ksb = s4 * 32;
                #pragma unroll
                for (int jp2 = 0; jp2 < 2; ++jp2) {
                    uint32_t vh4[2][4], vl4[2][4];
                    ldsm4(vh4[0], vbh + bofff[2*jp2]     + ksb);
                    ldsm4(vh4[1], vbh + bofff[2*jp2 + 1] + ksb);
                    ldsm4(vl4[0], vbl + bofff[2*jp2]     + ksb);
                    ldsm4(vl4[1], vbl + bofff[2*jp2 + 1] + ksb);
                    #pragma unroll
                    for (int p = 0; p < 2; ++p)
                        #pragma unroll
                        for (int jj = 0; jj < 2; ++jj)
                            mma16816(acc[(2*jp2+p)*2+jj], ph, vh4[p] + jj*2);
                    #pragma unroll
                    for (int p = 0; p < 2; ++p)
                        #pragma unroll
                        for (int jj = 0; jj < 2; ++jj)
                            mma16816(acc[(2*jp2+p)*2+jj], ph, vl4[p] + jj*2);
                    #pragma unroll
                    for (int p = 0; p < 2; ++p)
                        #pragma unroll
                        for (int jj = 0; jj < 2; ++jj)
                            mma16816(acc[(2*jp2+p)*2+jj], pl, vh4[p] + jj*2);
                }
            }
        }
        __syncthreads();
    }

    // ---- epilogue: y = acc / l, write split bf16 [tok][C] ----
    int b = bh >> 4, h = bh & 15;
    float inv0 = 1.f / l0, inv1 = 1.f / l1;
    size_t tok0 = (size_t)b*Tt + q0 + r;
    size_t tok1 = tok0 + 8;
    #pragma unroll
    for (int j = 0; j < 8; ++j) {
        int col = h*HD + j*8 + qc*2;
        uint32_t hi, lo;
        split2(acc[j][0]*inv0, acc[j][1]*inv0, hi, lo);
        *(uint32_t*)&g_yh[tok0*Cc + col] = hi;
        *(uint32_t*)&g_yl[tok0*Cc + col] = lo;
        split2(acc[j][2]*inv1, acc[j][3]*inv1, hi, lo);
        *(uint32_t*)&g_yh[tok1*Cc + col] = hi;
        *(uint32_t*)&g_yl[tok1*Cc + col] = lo;
    }
}

// ---------------------------------------------------------------------------
extern "C" void kernel_launch(void* const* d_in, const int* in_sizes, int n_in,
                              void* d_out, int out_size) {
    const float* x     = (const float*)d_in[0];
    const float* Wqkv  = (const float*)d_in[1];
    const float* bqkv  = (const float*)d_in[2];
    const float* Wproj = (const float*)d_in[3];
    const float* bproj = (const float*)d_in[4];
    const unsigned* amask = (const unsigned*)d_in[5];
    const unsigned* rmask = (const unsigned*)d_in[6];
    float* out = (float*)d_out;

    cudaFuncSetAttribute(gemm_mma<0>, cudaFuncAttributeMaxDynamicSharedMemorySize, GEMM_SMEM);
    cudaFuncSetAttribute(gemm_mma<1>, cudaFuncAttributeMaxDynamicSharedMemorySize, GEMM_SMEM);
    cudaFuncSetAttribute(flash_mma, cudaFuncAttributeMaxDynamicSharedMemorySize, FLASH_SMEM);

    __nv_bfloat16 *xh, *xl, *wqh, *wql, *wph, *wpl, *yh, *yl;
    cudaGetSymbolAddress((void**)&xh,  g_xh);  cudaGetSymbolAddress((void**)&xl,  g_xl);
    cudaGetSymbolAddress((void**)&wqh, g_wqh); cudaGetSymbolAddress((void**)&wql, g_wql);
    cudaGetSymbolAddress((void**)&wph, g_wph); cudaGetSymbolAddress((void**)&wpl, g_wpl);
    cudaGetSymbolAddress((void**)&yh,  g_yh);  cudaGetSymbolAddress((void**)&yl,  g_yl);

    cvt_split<<<(NTOK*Cc/4 + 255)/256, 256>>>((const float4*)x, (__nv_bfloat162*)xh, (__nv_bfloat162*)xl, NTOK*Cc/4);
    cvt_split_T<<<dim3(C3/32, Cc/32), dim3(32,8)>>>(Wqkv, wqh, wql, Cc, C3);
    cvt_split_T<<<dim3(Cc/32, Cc/32), dim3(32,8)>>>(Wproj, wph, wpl, Cc, Cc);

    gemm_mma<0><<<dim3(C3/128, NTOK/128), 256, GEMM_SMEM>>>(xh, xl, wqh, wql, bqkv, nullptr, nullptr, Cc);

    flash_mma<<<dim3(Tt/128, Bsz*Hh), 256, FLASH_SMEM>>>(amask);

    gemm_mma<1><<<dim3(Cc/128, NTOK/128), 256, GEMM_SMEM>>>(yh, yl, wph, wpl, bproj, rmask, out, Cc);
}

// round 9
// speedup vs baseline: 1.5208x; 1.4147x over previous
#include <cuda_runtime.h>
#include <cuda_fp16.h>
#include <math.h>
#include <cstdint>

// Problem constants
#define Bsz 2
#define Tt 2048
#define Cc 1024
#define Hh 16
#define HD 64
#define NTOK (Bsz*Tt)   // 4096
#define C3 (3*Cc)       // 3072
#define KEEP_INV (1.0f/0.9f)

// ---------------- scratch (device globals; no allocs allowed) ---------------
__device__ __half g_xh[(size_t)NTOK*Cc], g_xl[(size_t)NTOK*Cc];
__device__ __half g_wqh[(size_t)C3*Cc];                    // [N,K] transposed, truncated
__device__ __half g_wph[(size_t)Cc*Cc];                    // [N,K] transposed, truncated
__device__ __half g_yh[(size_t)NTOK*Cc], g_yl[(size_t)NTOK*Cc];
__device__ __half g_qh[(size_t)32*Tt*HD], g_ql[(size_t)32*Tt*HD];  // q split, scaled
__device__ __half g_kh[(size_t)32*Tt*HD];                  // k truncated
__device__ __half g_vth[(size_t)32*HD*Tt];                 // v transposed, truncated

// ---------------- helpers ----------------
__device__ __forceinline__ uint32_t smem_u32(const void* p) {
    uint32_t a;
    asm("{ .reg .u64 t; cvta.to.shared.u64 t, %1; cvt.u32.u64 %0, t; }" : "=r"(a) : "l"(p));
    return a;
}
__device__ __forceinline__ void cp_async16(uint32_t dst, const void* src) {
    asm volatile("cp.async.cg.shared.global [%0], [%1], 16;" :: "r"(dst), "l"(src) : "memory");
}
#define CP_COMMIT() asm volatile("cp.async.commit_group;" ::: "memory")
#define CP_WAIT(n)  asm volatile("cp.async.wait_group %0;" :: "n"(n) : "memory")

__device__ __forceinline__ void mma16816(float* c, const uint32_t* a, const uint32_t* b) {
    asm volatile("mma.sync.aligned.m16n8k16.row.col.f32.f16.f16.f32 "
        "{%0,%1,%2,%3}, {%4,%5,%6,%7}, {%8,%9}, {%0,%1,%2,%3};"
        : "+f"(c[0]), "+f"(c[1]), "+f"(c[2]), "+f"(c[3])
        : "r"(a[0]), "r"(a[1]), "r"(a[2]), "r"(a[3]), "r"(b[0]), "r"(b[1]));
}
__device__ __forceinline__ void ldsm4(uint32_t* r, uint32_t a) {
    asm volatile("ldmatrix.sync.aligned.m8n8.x4.shared.b16 {%0,%1,%2,%3}, [%4];"
        : "=r"(r[0]), "=r"(r[1]), "=r"(r[2]), "=r"(r[3]) : "r"(a));
}
// pack two floats into hi/lo fp16x2 (split)
__device__ __forceinline__ void split2h(float a, float b, uint32_t& hi, uint32_t& lo) {
    __half ha = __float2half_rn(a), hb = __float2half_rn(b);
    __half2 H(ha, hb);
    hi = *(uint32_t*)&H;
    __half2 L(__float2half_rn(a - __half2float(ha)),
              __float2half_rn(b - __half2float(hb)));
    lo = *(uint32_t*)&L;
}
__device__ __forceinline__ uint32_t pack2h(float a, float b) {
    __half2 H(__float2half_rn(a), __float2half_rn(b));
    return *(uint32_t*)&H;
}

// ---------------------------------------------------------------------------
// fp32 -> (hi,lo) fp16 split
// ---------------------------------------------------------------------------
__global__ __launch_bounds__(256) void cvt_split(const float4* __restrict__ in,
                                                 __half2* __restrict__ hi,
                                                 __half2* __restrict__ lo,
                                                 int n4) {
    int i = blockIdx.x * 256 + threadIdx.x;
    if (i >= n4) return;
    float4 v = in[i];
    uint32_t h0, l0, h1, l1;
    split2h(v.x, v.y, h0, l0);
    split2h(v.z, v.w, h1, l1);
    hi[2*i]   = *(__half2*)&h0;
    hi[2*i+1] = *(__half2*)&h1;
    lo[2*i]   = *(__half2*)&l0;
    lo[2*i+1] = *(__half2*)&l1;
}

// fp32 W[K,N] -> transposed truncated fp16 [N,K]
__global__ __launch_bounds__(256) void cvt_trunc_T(const float* __restrict__ in,
                                                   __half* __restrict__ hi,
                                                   int K, int N) {
    __shared__ float t[32][33];
    int nx = blockIdx.x * 32, kx = blockIdx.y * 32;
    int tx = threadIdx.x, ty = threadIdx.y;  // (32,8)
    #pragma unroll
    for (int r = 0; r < 4; ++r)
        t[ty + 8*r][tx] = in[(size_t)(kx + ty + 8*r) * N + nx + tx];
    __syncthreads();
    #pragma unroll
    for (int r = 0; r < 4; ++r)
        hi[(size_t)(nx + ty + 8*r) * K + kx + tx] = __float2half_rn(t[tx][ty + 8*r]);
}

// ---------------------------------------------------------------------------
// mma.sync fp16 2-term GEMM: C = (Ah+Al)[M,K] * Bt[N,K]^T  (+bias, +epilogue)
// 128x128 tile, K-chunk 32, 2-stage cp.async, ldmatrix.x4.
// 3 smem tiles per chunk (Ah, Al, B). 60KB smem -> 2 CTAs/SM.
// MODE 0: qkv -> q split (scaled 1/8), k truncated, v transposed truncated.
// MODE 1: proj + resid dropout -> out (fp32).
// ---------------------------------------------------------------------------
#define SR 40
#define TILE_E (128*SR)
#define TILE_B (TILE_E*2)       // 10240 bytes
#define BUF_E  (3*TILE_E)
#define BUF_B  (3*TILE_B)       // 30720 bytes
#define GEMM_SMEM (2*BUF_B)     // 61440

__device__ __forceinline__ void gemm_issue(uint32_t sb, int buf,
                                           const __half* Ah, const __half* Al,
                                           const __half* B,
                                           int m0, int n0, int K, int ch, int tid) {
    #pragma unroll
    for (int it = 0; it < 6; ++it) {
        int u = tid + it * 256;           // 0..1535
        int arr = u >> 9;                 // 0..2
        int rem = u & 511;
        int row = rem >> 2;
        int c16 = rem & 3;
        const __half* src = (arr == 0) ? Ah : (arr == 1) ? Al : B;
        int grow = (arr < 2 ? m0 : n0) + row;
        uint32_t soff = (uint32_t)((buf * BUF_E + arr * TILE_E + row * SR + c16 * 8) * 2);
        cp_async16(sb + soff, src + (size_t)grow * K + ch * 32 + c16 * 8);
    }
    CP_COMMIT();
}

template<int MODE>
__global__ __launch_bounds__(256, 2) void gemm_mma(const __half* __restrict__ Ah,
                                                   const __half* __restrict__ Al,
                                                   const __half* __restrict__ B,
                                                   const float* __restrict__ bias,
                                                   const unsigned* __restrict__ rmask,
                                                   float* __restrict__ out,
                                                   int K) {
    extern __shared__ __half smg[];
    uint32_t sb = smem_u32(smg);
    int tid = threadIdx.x, wid = tid >> 5, lane = tid & 31;
    int m0 = blockIdx.y * 128, n0 = blockIdx.x * 128;
    int wm = (wid & 3) * 32, wn = (wid >> 2) * 64;
    int qr = lane >> 2, qc = lane & 3;
    int g = lane >> 3, lr = lane & 7;

    uint32_t aoff[2], boff[4];
    #pragma unroll
    for (int i = 0; i < 2; ++i)
        aoff[i] = (uint32_t)(((wm + i*16 + lr + (g & 1)*8) * SR + (g >> 1)*8) * 2);
    #pragma unroll
    for (int jp = 0; jp < 4; ++jp)
        boff[jp] = (uint32_t)(((wn + jp*16 + lr + (g >> 1)*8) * SR + (g & 1)*8) * 2);

    float acc[2][8][4] = {};
    int nch = K >> 5;

    gemm_issue(sb, 0, Ah, Al, B, m0, n0, K, 0, tid);

    for (int ch = 0; ch < nch; ++ch) {
        int buf = ch & 1;
        if (ch + 1 < nch) {
            gemm_issue(sb, buf ^ 1, Ah, Al, B, m0, n0, K, ch + 1, tid);
            CP_WAIT(1);
        } else {
            CP_WAIT(0);
        }
        __syncthreads();

        uint32_t bAh = sb + buf * BUF_B;
        uint32_t bAl = bAh + TILE_B;
        uint32_t bB  = bAh + 2*TILE_B;

        #pragma unroll
        for (int ks = 0; ks < 2; ++ks) {
            uint32_t ksb = ks * 32;
            uint32_t ah[2][4], al[2][4];
            ldsm4(ah[0], bAh + aoff[0] + ksb);
            ldsm4(ah[1], bAh + aoff[1] + ksb);
            ldsm4(al[0], bAl + aoff[0] + ksb);
            ldsm4(al[1], bAl + aoff[1] + ksb);
            #pragma unroll
            for (int jp2 = 0; jp2 < 2; ++jp2) {
                uint32_t b4[2][4];
                ldsm4(b4[0], bB + boff[2*jp2]     + ksb);
                ldsm4(b4[1], bB + boff[2*jp2 + 1] + ksb);
                #pragma unroll
                for (int p = 0; p < 2; ++p)
                    #pragma unroll
                    for (int jj = 0; jj < 2; ++jj)
                        #pragma unroll
                        for (int i = 0; i < 2; ++i)
                            mma16816(acc[i][(2*jp2+p)*2+jj], ah[i], b4[p] + jj*2);
                #pragma unroll
                for (int p = 0; p < 2; ++p)
                    #pragma unroll
                    for (int jj = 0; jj < 2; ++jj)
                        #pragma unroll
                        for (int i = 0; i < 2; ++i)
                            mma16816(acc[i][(2*jp2+p)*2+jj], al[i], b4[p] + jj*2);
            }
        }
        __syncthreads();
    }

    // Epilogue
    #pragma unroll
    for (int i = 0; i < 2; ++i) {
        int R0 = m0 + wm + i * 16 + qr;
        #pragma unroll
        for (int j = 0; j < 8; ++j) {
            int C0 = n0 + wn + j * 8 + qc * 2;
            float b0 = bias[C0], b1 = bias[C0 + 1];
            #pragma unroll
            for (int hrow = 0; hrow < 2; ++hrow) {
                int m = R0 + hrow * 8;
                float v0 = acc[i][j][hrow*2 + 0] + b0;
                float v1 = acc[i][j][hrow*2 + 1] + b1;
                if (MODE == 0) {
                    int bb = m >> 11, t = m & (Tt - 1);
                    int which = C0 >> 10, cidx = C0 & 1023;
                    int h = cidx >> 6, dd = cidx & 63;
                    int bh = bb * Hh + h;
                    if (which == 0) {
                        // q: scaled split pair
                        uint32_t hi, lo;
                        split2h(v0 * 0.125f, v1 * 0.125f, hi, lo);
                        size_t o = ((size_t)bh*Tt + t)*HD + dd;
                        *(uint32_t*)&g_qh[o] = hi;
                        *(uint32_t*)&g_ql[o] = lo;
                    } else if (which == 1) {
                        // k: truncated
                        size_t o = ((size_t)bh*Tt + t)*HD + dd;
                        *(uint32_t*)&g_kh[o] = pack2h(v0, v1);
                    } else {
                        // v: transposed truncated
                        g_vth[((size_t)bh*HD + dd)*Tt + t]     = __float2half_rn(v0);
                        g_vth[((size_t)bh*HD + dd + 1)*Tt + t] = __float2half_rn(v1);
                    }
                } else {
                    size_t idx = (size_t)m * Cc + C0;
                    out[idx]     = rmask[idx]     ? v0 * KEEP_INV : 0.f;
                    out[idx + 1] = rmask[idx + 1] ? v1 * KEEP_INV : 0.f;
                }
            }
        }
    }
}

// ---------------------------------------------------------------------------
// Flash attention, fp16 2-term: QK = (Qh+Ql)*Kt, PV = (Ph+Pl)*Vt.
// K/V tiles truncated (1 array each). 72KB smem -> 2 CTAs/SM.
// ---------------------------------------------------------------------------
#define SRK 72                       // fp16 row stride for 64-col tiles
#define OQH 0
#define OQL (128*SRK*2)              // 18432
#define OB0 (2*128*SRK*2)            // 36864
#define KVB (64*SRK*2)               // 9216
#define BUFB (2*KVB)                 // 18432
#define FLASH_SMEM (OB0 + 2*BUFB)    // 73728

__device__ __forceinline__ void flash_issue(uint32_t sb, int buf,
                                            int bh, int k0, int tid) {
    #pragma unroll
    for (int it = 0; it < 4; ++it) {
        int u = tid + it * 256;           // 0..1023
        int arr = u >> 9;                 // 0: k, 1: v
        int rem = u & 511;
        int row = rem >> 3;
        int ck = rem & 7;
        const __half* src;
        size_t gofs;
        if (arr == 0) {
            src = g_kh;
            gofs = ((size_t)bh*Tt + k0 + row)*HD + ck*8;
        } else {
            src = g_vth;
            gofs = ((size_t)bh*HD + row)*Tt + k0 + ck*8;
        }
        uint32_t dst = sb + OB0 + buf*BUFB + arr*KVB + (uint32_t)(row*SRK + ck*8)*2;
        cp_async16(dst, src + gofs);
    }
    CP_COMMIT();
}

__global__ __launch_bounds__(256, 2) void flash_mma(const unsigned* __restrict__ amask) {
    extern __shared__ char smf[];
    uint32_t sb = smem_u32(smf);
    int tid = threadIdx.x, wid = tid >> 5, lane = tid & 31;
    int qr = lane >> 2, qc = lane & 3;
    int g = lane >> 3, lr = lane & 7;
    int bh = blockIdx.y;
    int qb = (gridDim.x - 1) - blockIdx.x;   // big tiles first
    int q0 = qb * 128;
    int nkt = qb * 2 + 2;

    // Q pair tile load — same cp.async group as tile 0
    #pragma unroll
    for (int it = 0; it < 8; ++it) {
        int u = tid + it * 256;
        int arr = u >> 10;
        int rem = u & 1023;
        int row = rem >> 3;
        int ck = rem & 7;
        const __half* src = arr ? g_ql : g_qh;
        uint32_t dst = sb + (arr ? OQL : OQH) + (uint32_t)(row*SRK + ck*8)*2;
        cp_async16(dst, src + ((size_t)bh*Tt + q0 + row)*HD + ck*8);
    }
    flash_issue(sb, 0, bh, 0, tid);

    uint32_t qaoff = (uint32_t)(((wid*16 + lr + (g & 1)*8) * SRK + (g >> 1)*8) * 2);
    uint32_t bofff[4];
    #pragma unroll
    for (int jp = 0; jp < 4; ++jp)
        bofff[jp] = (uint32_t)(((jp*16 + lr + (g >> 1)*8) * SRK + (g & 1)*8) * 2);

    int r = wid * 16 + qr;                  // q row within tile
    int rowmax = q0 + wid * 16 + 15;
    const unsigned* mrow0 = amask + ((size_t)bh*Tt + q0 + r)*Tt + qc*2;
    const unsigned* mrow1 = mrow0 + (size_t)8*Tt;

    float acc[8][4] = {};
    float m0 = -INFINITY, m1 = -INFINITY, l0 = 0.f, l1 = 0.f;

    for (int kt = 0; kt < nkt; ++kt) {
        int buf = kt & 1;
        int k0 = kt * 64;
        if (kt + 1 < nkt) {
            flash_issue(sb, buf ^ 1, bh, (kt+1)*64, tid);
            CP_WAIT(1);
        } else {
            CP_WAIT(0);
        }
        __syncthreads();

        if (k0 <= rowmax) {
            uint32_t kb = sb + OB0 + buf*BUFB;
            uint32_t vb = kb + KVB;

            // ---- mask prefetch (gmem -> regs), consumed at softmax ----
            uint2 km0[8], km1[8];
            #pragma unroll
            for (int j = 0; j < 8; ++j) {
                km0[j] = *(const uint2*)(mrow0 + k0 + j*8);
                km1[j] = *(const uint2*)(mrow1 + k0 + j*8);
            }

            // ---- S = (Qh+Ql) K^T ----
            float s[8][4] = {};
            #pragma unroll
            for (int ks = 0; ks < 4; ++ks) {
                uint32_t ksb = ks * 32;
                uint32_t ah[4], al[4];
                ldsm4(ah, sb + OQH + qaoff + ksb);
                ldsm4(al, sb + OQL + qaoff + ksb);
                #pragma unroll
                for (int jp2 = 0; jp2 < 2; ++jp2) {
                    uint32_t k4[2][4];
                    ldsm4(k4[0], kb + bofff[2*jp2]     + ksb);
                    ldsm4(k4[1], kb + bofff[2*jp2 + 1] + ksb);
                    #pragma unroll
                    for (int p = 0; p < 2; ++p)
                        #pragma unroll
                        for (int jj = 0; jj < 2; ++jj)
                            mma16816(s[(2*jp2+p)*2+jj], ah, k4[p] + jj*2);
                    #pragma unroll
                    for (int p = 0; p < 2; ++p)
                        #pragma unroll
                        for (int jj = 0; jj < 2; ++jj)
                            mma16816(s[(2*jp2+p)*2+jj], al, k4[p] + jj*2);
                }
            }

            // ---- causal mask ----
            int row0 = q0 + r, row1 = row0 + 8;
            #pragma unroll
            for (int j = 0; j < 8; ++j) {
                int cg = k0 + j*8 + qc*2;
                if (cg     > row0) s[j][0] = -INFINITY;
                if (cg + 1 > row0) s[j][1] = -INFINITY;
                if (cg     > row1) s[j][2] = -INFINITY;
                if (cg + 1 > row1) s[j][3] = -INFINITY;
            }

            // ---- online softmax (undropped denominator) ----
            float mx0 = -INFINITY, mx1 = -INFINITY;
            #pragma unroll
            for (int j = 0; j < 8; ++j) {
                mx0 = fmaxf(mx0, fmaxf(s[j][0], s[j][1]));
                mx1 = fmaxf(mx1, fmaxf(s[j][2], s[j][3]));
            }
            mx0 = fmaxf(mx0, __shfl_xor_sync(0xffffffffu, mx0, 1));
            mx0 = fmaxf(mx0, __shfl_xor_sync(0xffffffffu, mx0, 2));
            mx1 = fmaxf(mx1, __shfl_xor_sync(0xffffffffu, mx1, 1));
            mx1 = fmaxf(mx1, __shfl_xor_sync(0xffffffffu, mx1, 2));
            float m0n = fmaxf(m0, mx0), m1n = fmaxf(m1, mx1);
            float a0 = __expf(m0 - m0n), a1 = __expf(m1 - m1n);
            float sum0 = 0.f, sum1 = 0.f;
            #pragma unroll
            for (int j = 0; j < 8; ++j) {
                float p0 = __expf(s[j][0] - m0n); sum0 += p0;
                float p1 = __expf(s[j][1] - m0n); sum0 += p1;
                float p2 = __expf(s[j][2] - m1n); sum1 += p2;
                float p3 = __expf(s[j][3] - m1n); sum1 += p3;
                s[j][0] = km0[j].x ? p0 * KEEP_INV : 0.f;
                s[j][1] = km0[j].y ? p1 * KEEP_INV : 0.f;
                s[j][2] = km1[j].x ? p2 * KEEP_INV : 0.f;
                s[j][3] = km1[j].y ? p3 * KEEP_INV : 0.f;
            }
            sum0 += __shfl_xor_sync(0xffffffffu, sum0, 1);
            sum0 += __shfl_xor_sync(0xffffffffu, sum0, 2);
            sum1 += __shfl_xor_sync(0xffffffffu, sum1, 1);
            sum1 += __shfl_xor_sync(0xffffffffu, sum1, 2);
            l0 = l0 * a0 + sum0;
            l1 = l1 * a1 + sum1;
            m0 = m0n; m1 = m1n;

            // ---- acc scale + (Ph+Pl) V ----
            #pragma unroll
            for (int j = 0; j < 8; ++j) {
                acc[j][0] *= a0; acc[j][1] *= a0;
                acc[j][2] *= a1; acc[j][3] *= a1;
            }
            #pragma unroll
            for (int s4 = 0; s4 < 4; ++s4) {
                uint32_t ph[4], pl[4];
                split2h(s[2*s4][0],   s[2*s4][1],   ph[0], pl[0]);
                split2h(s[2*s4][2],   s[2*s4][3],   ph[1], pl[1]);
                split2h(s[2*s4+1][0], s[2*s4+1][1], ph[2], pl[2]);
                split2h(s[2*s4+1][2], s[2*s4+1][3], ph[3], pl[3]);
                uint32_t ksb = s4 * 32;
                #pragma unroll
                for (int jp2 = 0; jp2 < 2; ++jp2) {
                    uint32_t v4[2][4];
                    ldsm4(v4[0], vb + bofff[2*jp2]     + ksb);
                    ldsm4(v4[1], vb + bofff[2*jp2 + 1] + ksb);
                    #pragma unroll
                    for (int p = 0; p < 2; ++p)
                        #pragma unroll
                        for (int jj = 0; jj < 2; ++jj)
                            mma16816(acc[(2*jp2+p)*2+jj], ph, v4[p] + jj*2);
                    #pragma unroll
                    for (int p = 0; p < 2; ++p)
                        #pragma unroll
                        for (int jj = 0; jj < 2; ++jj)
                            mma16816(acc[(2*jp2+p)*2+jj], pl, v4[p] + jj*2);
                }
            }
        }
        __syncthreads();
    }

    // ---- epilogue: y = acc / l, write split fp16 pair [tok][C] ----
    int b = bh >> 4, h = bh & 15;
    float inv0 = 1.f / l0, inv1 = 1.f / l1;
    size_t tok0 = (size_t)b*Tt + q0 + r;
    size_t tok1 = tok0 + 8;
    #pragma unroll
    for (int j = 0; j < 8; ++j) {
        int col = h*HD + j*8 + qc*2;
        uint32_t hi, lo;
        split2h(acc[j][0]*inv0, acc[j][1]*inv0, hi, lo);
        *(uint32_t*)&g_yh[tok0*Cc + col] = hi;
        *(uint32_t*)&g_yl[tok0*Cc + col] = lo;
        split2h(acc[j][2]*inv1, acc[j][3]*inv1, hi, lo);
        *(uint32_t*)&g_yh[tok1*Cc + col] = hi;
        *(uint32_t*)&g_yl[tok1*Cc + col] = lo;
    }
}

// ---------------------------------------------------------------------------
extern "C" void kernel_launch(void* const* d_in, const int* in_sizes, int n_in,
                              void* d_out, int out_size) {
    const float* x     = (const float*)d_in[0];
    const float* Wqkv  = (const float*)d_in[1];
    const float* bqkv  = (const float*)d_in[2];
    const float* Wproj = (const float*)d_in[3];
    const float* bproj = (const float*)d_in[4];
    const unsigned* amask = (const unsigned*)d_in[5];
    const unsigned* rmask = (const unsigned*)d_in[6];
    float* out = (float*)d_out;

    cudaFuncSetAttribute(gemm_mma<0>, cudaFuncAttributeMaxDynamicSharedMemorySize, GEMM_SMEM);
    cudaFuncSetAttribute(gemm_mma<1>, cudaFuncAttributeMaxDynamicSharedMemorySize, GEMM_SMEM);
    cudaFuncSetAttribute(flash_mma, cudaFuncAttributeMaxDynamicSharedMemorySize, FLASH_SMEM);

    __half *xh, *xl, *wqh, *wph, *yh, *yl;
    cudaGetSymbolAddress((void**)&xh,  g_xh);  cudaGetSymbolAddress((void**)&xl,  g_xl);
    cudaGetSymbolAddress((void**)&wqh, g_wqh); cudaGetSymbolAddress((void**)&wph, g_wph);
    cudaGetSymbolAddress((void**)&yh,  g_yh);  cudaGetSymbolAddress((void**)&yl,  g_yl);

    cvt_split<<<(NTOK*Cc/4 + 255)/256, 256>>>((const float4*)x, (__half2*)xh, (__half2*)xl, NTOK*Cc/4);
    cvt_trunc_T<<<dim3(C3/32, Cc/32), dim3(32,8)>>>(Wqkv, wqh, Cc, C3);
    cvt_trunc_T<<<dim3(Cc/32, Cc/32), dim3(32,8)>>>(Wproj, wph, Cc, Cc);

    gemm_mma<0><<<dim3(C3/128, NTOK/128), 256, GEMM_SMEM>>>(xh, xl, wqh, bqkv, nullptr, nullptr, Cc);

    flash_mma<<<dim3(Tt/128, Bsz*Hh), 256, FLASH_SMEM>>>(amask);

    gemm_mma<1><<<dim3(Cc/128, NTOK/128), 256, GEMM_SMEM>>>(yh, yl, wph, bproj, rmask, out, Cc);
}

// round 10
// speedup vs baseline: 1.5707x; 1.0328x over previous
#include <cuda_runtime.h>
#include <cuda_fp16.h>
#include <math.h>
#include <cstdint>

// Problem constants
#define Bsz 2
#define Tt 2048
#define Cc 1024
#define Hh 16
#define HD 64
#define NTOK (Bsz*Tt)   // 4096
#define C3 (3*Cc)       // 3072
#define KEEP_INV (1.0f/0.9f)

// ---------------- scratch (device globals; no allocs allowed) ---------------
__device__ __half g_xh[(size_t)NTOK*Cc], g_xl[(size_t)NTOK*Cc];
__device__ __half g_wqh[(size_t)C3*Cc];                    // [N,K] transposed, truncated
__device__ __half g_wph[(size_t)Cc*Cc];                    // [N,K] transposed, truncated
__device__ __half g_yh[(size_t)NTOK*Cc], g_yl[(size_t)NTOK*Cc];
__device__ __half g_qh[(size_t)32*Tt*HD], g_ql[(size_t)32*Tt*HD];  // q split, scaled
__device__ __half g_kh[(size_t)32*Tt*HD];                  // k truncated
__device__ __half g_vth[(size_t)32*HD*Tt];                 // v transposed, truncated

// ---------------- helpers ----------------
__device__ __forceinline__ uint32_t smem_u32(const void* p) {
    uint32_t a;
    asm("{ .reg .u64 t; cvta.to.shared.u64 t, %1; cvt.u32.u64 %0, t; }" : "=r"(a) : "l"(p));
    return a;
}
__device__ __forceinline__ void cp_async16(uint32_t dst, const void* src) {
    asm volatile("cp.async.cg.shared.global [%0], [%1], 16;" :: "r"(dst), "l"(src) : "memory");
}
#define CP_COMMIT() asm volatile("cp.async.commit_group;" ::: "memory")
#define CP_WAIT(n)  asm volatile("cp.async.wait_group %0;" :: "n"(n) : "memory")

__device__ __forceinline__ void mma16816(float* c, const uint32_t* a, const uint32_t* b) {
    asm volatile("mma.sync.aligned.m16n8k16.row.col.f32.f16.f16.f32 "
        "{%0,%1,%2,%3}, {%4,%5,%6,%7}, {%8,%9}, {%0,%1,%2,%3};"
        : "+f"(c[0]), "+f"(c[1]), "+f"(c[2]), "+f"(c[3])
        : "r"(a[0]), "r"(a[1]), "r"(a[2]), "r"(a[3]), "r"(b[0]), "r"(b[1]));
}
__device__ __forceinline__ void ldsm4(uint32_t* r, uint32_t a) {
    asm volatile("ldmatrix.sync.aligned.m8n8.x4.shared.b16 {%0,%1,%2,%3}, [%4];"
        : "=r"(r[0]), "=r"(r[1]), "=r"(r[2]), "=r"(r[3]) : "r"(a));
}
// pack two floats into hi/lo fp16x2 (split)
__device__ __forceinline__ void split2h(float a, float b, uint32_t& hi, uint32_t& lo) {
    __half ha = __float2half_rn(a), hb = __float2half_rn(b);
    __half2 H(ha, hb);
    hi = *(uint32_t*)&H;
    __half2 L(__float2half_rn(a - __half2float(ha)),
              __float2half_rn(b - __half2float(hb)));
    lo = *(uint32_t*)&L;
}
__device__ __forceinline__ uint32_t pack2h(float a, float b) {
    __half2 H(__float2half_rn(a), __float2half_rn(b));
    return *(uint32_t*)&H;
}

// ---------------------------------------------------------------------------
// fp32 -> (hi,lo) fp16 split
// ---------------------------------------------------------------------------
__global__ __launch_bounds__(256) void cvt_split(const float4* __restrict__ in,
                                                 __half2* __restrict__ hi,
                                                 __half2* __restrict__ lo,
                                                 int n4) {
    int i = blockIdx.x * 256 + threadIdx.x;
    if (i >= n4) return;
    float4 v = in[i];
    uint32_t h0, l0, h1, l1;
    split2h(v.x, v.y, h0, l0);
    split2h(v.z, v.w, h1, l1);
    hi[2*i]   = *(__half2*)&h0;
    hi[2*i+1] = *(__half2*)&h1;
    lo[2*i]   = *(__half2*)&l0;
    lo[2*i+1] = *(__half2*)&l1;
}

// fp32 W[K,N] -> transposed truncated fp16 [N,K]
__global__ __launch_bounds__(256) void cvt_trunc_T(const float* __restrict__ in,
                                                   __half* __restrict__ hi,
                                                   int K, int N) {
    __shared__ float t[32][33];
    int nx = blockIdx.x * 32, kx = blockIdx.y * 32;
    int tx = threadIdx.x, ty = threadIdx.y;  // (32,8)
    #pragma unroll
    for (int r = 0; r < 4; ++r)
        t[ty + 8*r][tx] = in[(size_t)(kx + ty + 8*r) * N + nx + tx];
    __syncthreads();
    #pragma unroll
    for (int r = 0; r < 4; ++r)
        hi[(size_t)(nx + ty + 8*r) * K + kx + tx] = __float2half_rn(t[tx][ty + 8*r]);
}

// ---------------------------------------------------------------------------
// mma.sync fp16 2-term GEMM: C = (Ah+Al)[M,K] * Bt[N,K]^T  (+bias, +epilogue)
// 128x128 tile, K-chunk 64 (halved barrier count), 2-stage cp.async,
// ldmatrix.x4. 108KB smem -> 2 CTAs/SM.
// MODE 0: qkv -> q split (scaled 1/8), k truncated, v transposed truncated.
// MODE 1: proj + resid dropout -> out (fp32).
// ---------------------------------------------------------------------------
#define SR 72                   // halves per row (64 + 8 pad) -> 144B stride
#define TILE_E (128*SR)
#define TILE_B (TILE_E*2)       // 18432 bytes
#define BUF_E  (3*TILE_E)
#define BUF_B  (3*TILE_B)       // 55296 bytes
#define GEMM_SMEM (2*BUF_B)     // 110592

__device__ __forceinline__ void gemm_issue(uint32_t sb, int buf,
                                           const __half* Ah, const __half* Al,
                                           const __half* B,
                                           int m0, int n0, int K, int ch, int tid) {
    #pragma unroll
    for (int it = 0; it < 12; ++it) {
        int u = tid + it * 256;           // 0..3071
        int arr = u >> 10;                // 0..2
        int rem = u & 1023;
        int row = rem >> 3;
        int c16 = rem & 7;                // 16B unit (8 halves)
        const __half* src = (arr == 0) ? Ah : (arr == 1) ? Al : B;
        int grow = (arr < 2 ? m0 : n0) + row;
        uint32_t soff = (uint32_t)((buf * BUF_E + arr * TILE_E + row * SR + c16 * 8) * 2);
        cp_async16(sb + soff, src + (size_t)grow * K + ch * 64 + c16 * 8);
    }
    CP_COMMIT();
}

template<int MODE>
__global__ __launch_bounds__(256, 2) void gemm_mma(const __half* __restrict__ Ah,
                                                   const __half* __restrict__ Al,
                                                   const __half* __restrict__ B,
                                                   const float* __restrict__ bias,
                                                   const unsigned* __restrict__ rmask,
                                                   float* __restrict__ out,
                                                   int K) {
    extern __shared__ __half smg[];
    uint32_t sb = smem_u32(smg);
    int tid = threadIdx.x, wid = tid >> 5, lane = tid & 31;
    int m0 = blockIdx.y * 128, n0 = blockIdx.x * 128;
    int wm = (wid & 3) * 32, wn = (wid >> 2) * 64;
    int qr = lane >> 2, qc = lane & 3;
    int g = lane >> 3, lr = lane & 7;

    uint32_t aoff[2], boff[4];
    #pragma unroll
    for (int i = 0; i < 2; ++i)
        aoff[i] = (uint32_t)(((wm + i*16 + lr + (g & 1)*8) * SR + (g >> 1)*8) * 2);
    #pragma unroll
    for (int jp = 0; jp < 4; ++jp)
        boff[jp] = (uint32_t)(((wn + jp*16 + lr + (g >> 1)*8) * SR + (g & 1)*8) * 2);

    float acc[2][8][4] = {};
    int nch = K >> 6;

    gemm_issue(sb, 0, Ah, Al, B, m0, n0, K, 0, tid);

    for (int ch = 0; ch < nch; ++ch) {
        int buf = ch & 1;
        if (ch + 1 < nch) {
            gemm_issue(sb, buf ^ 1, Ah, Al, B, m0, n0, K, ch + 1, tid);
            CP_WAIT(1);
        } else {
            CP_WAIT(0);
        }
        __syncthreads();

        uint32_t bAh = sb + buf * BUF_B;
        uint32_t bAl = bAh + TILE_B;
        uint32_t bB  = bAh + 2*TILE_B;

        #pragma unroll
        for (int ks = 0; ks < 4; ++ks) {
            uint32_t ksb = ks * 32;
            uint32_t ah[2][4], al[2][4];
            ldsm4(ah[0], bAh + aoff[0] + ksb);
            ldsm4(ah[1], bAh + aoff[1] + ksb);
            ldsm4(al[0], bAl + aoff[0] + ksb);
            ldsm4(al[1], bAl + aoff[1] + ksb);
            #pragma unroll
            for (int jp2 = 0; jp2 < 2; ++jp2) {
                uint32_t b4[2][4];
                ldsm4(b4[0], bB + boff[2*jp2]     + ksb);
                ldsm4(b4[1], bB + boff[2*jp2 + 1] + ksb);
                #pragma unroll
                for (int p = 0; p < 2; ++p)
                    #pragma unroll
                    for (int jj = 0; jj < 2; ++jj)
                        #pragma unroll
                        for (int i = 0; i < 2; ++i)
                            mma16816(acc[i][(2*jp2+p)*2+jj], ah[i], b4[p] + jj*2);
                #pragma unroll
                for (int p = 0; p < 2; ++p)
                    #pragma unroll
                    for (int jj = 0; jj < 2; ++jj)
                        #pragma unroll
                        for (int i = 0; i < 2; ++i)
                            mma16816(acc[i][(2*jp2+p)*2+jj], al[i], b4[p] + jj*2);
            }
        }
        __syncthreads();
    }

    // Epilogue
    #pragma unroll
    for (int i = 0; i < 2; ++i) {
        int R0 = m0 + wm + i * 16 + qr;
        #pragma unroll
        for (int j = 0; j < 8; ++j) {
            int C0 = n0 + wn + j * 8 + qc * 2;
            float b0 = bias[C0], b1 = bias[C0 + 1];
            #pragma unroll
            for (int hrow = 0; hrow < 2; ++hrow) {
                int m = R0 + hrow * 8;
                float v0 = acc[i][j][hrow*2 + 0] + b0;
                float v1 = acc[i][j][hrow*2 + 1] + b1;
                if (MODE == 0) {
                    int bb = m >> 11, t = m & (Tt - 1);
                    int which = C0 >> 10, cidx = C0 & 1023;
                    int h = cidx >> 6, dd = cidx & 63;
                    int bh = bb * Hh + h;
                    if (which == 0) {
                        uint32_t hi, lo;
                        split2h(v0 * 0.125f, v1 * 0.125f, hi, lo);
                        size_t o = ((size_t)bh*Tt + t)*HD + dd;
                        *(uint32_t*)&g_qh[o] = hi;
                        *(uint32_t*)&g_ql[o] = lo;
                    } else if (which == 1) {
                        size_t o = ((size_t)bh*Tt + t)*HD + dd;
                        *(uint32_t*)&g_kh[o] = pack2h(v0, v1);
                    } else {
                        g_vth[((size_t)bh*HD + dd)*Tt + t]     = __float2half_rn(v0);
                        g_vth[((size_t)bh*HD + dd + 1)*Tt + t] = __float2half_rn(v1);
                    }
                } else {
                    size_t idx = (size_t)m * Cc + C0;
                    out[idx]     = rmask[idx]     ? v0 * KEEP_INV : 0.f;
                    out[idx + 1] = rmask[idx + 1] ? v1 * KEEP_INV : 0.f;
                }
            }
        }
    }
}

// ---------------------------------------------------------------------------
// Flash attention, fp16 2-term: QK = (Qh+Ql)*Kt, PV = (Ph+Pl)*Vt.
// K/V tiles truncated (1 array each). 72KB smem -> 2 CTAs/SM.
// ---------------------------------------------------------------------------
#define SRK 72                       // fp16 row stride for 64-col tiles
#define OQH 0
#define OQL (128*SRK*2)              // 18432
#define OB0 (2*128*SRK*2)            // 36864
#define KVB (64*SRK*2)               // 9216
#define BUFB (2*KVB)                 // 18432
#define FLASH_SMEM (OB0 + 2*BUFB)    // 73728

__device__ __forceinline__ void flash_issue(uint32_t sb, int buf,
                                            int bh, int k0, int tid) {
    #pragma unroll
    for (int it = 0; it < 4; ++it) {
        int u = tid + it * 256;           // 0..1023
        int arr = u >> 9;                 // 0: k, 1: v
        int rem = u & 511;
        int row = rem >> 3;
        int ck = rem & 7;
        const __half* src;
        size_t gofs;
        if (arr == 0) {
            src = g_kh;
            gofs = ((size_t)bh*Tt + k0 + row)*HD + ck*8;
        } else {
            src = g_vth;
            gofs = ((size_t)bh*HD + row)*Tt + k0 + ck*8;
        }
        uint32_t dst = sb + OB0 + buf*BUFB + arr*KVB + (uint32_t)(row*SRK + ck*8)*2;
        cp_async16(dst, src + gofs);
    }
    CP_COMMIT();
}

__global__ __launch_bounds__(256, 2) void flash_mma(const unsigned* __restrict__ amask) {
    extern __shared__ char smf[];
    uint32_t sb = smem_u32(smf);
    int tid = threadIdx.x, wid = tid >> 5, lane = tid & 31;
    int qr = lane >> 2, qc = lane & 3;
    int g = lane >> 3, lr = lane & 7;
    int bh = blockIdx.y;
    int qb = (gridDim.x - 1) - blockIdx.x;   // big tiles first
    int q0 = qb * 128;
    int nkt = qb * 2 + 2;

    // Q pair tile load — same cp.async group as tile 0
    #pragma unroll
    for (int it = 0; it < 8; ++it) {
        int u = tid + it * 256;
        int arr = u >> 10;
        int rem = u & 1023;
        int row = rem >> 3;
        int ck = rem & 7;
        const __half* src = arr ? g_ql : g_qh;
        uint32_t dst = sb + (arr ? OQL : OQH) + (uint32_t)(row*SRK + ck*8)*2;
        cp_async16(dst, src + ((size_t)bh*Tt + q0 + row)*HD + ck*8);
    }
    flash_issue(sb, 0, bh, 0, tid);

    uint32_t qaoff = (uint32_t)(((wid*16 + lr + (g & 1)*8) * SRK + (g >> 1)*8) * 2);
    uint32_t bofff[4];
    #pragma unroll
    for (int jp = 0; jp < 4; ++jp)
        bofff[jp] = (uint32_t)(((jp*16 + lr + (g >> 1)*8) * SRK + (g & 1)*8) * 2);

    int r = wid * 16 + qr;                  // q row within tile
    int rowmax = q0 + wid * 16 + 15;
    const unsigned* mrow0 = amask + ((size_t)bh*Tt + q0 + r)*Tt + qc*2;
    const unsigned* mrow1 = mrow0 + (size_t)8*Tt;

    float acc[8][4] = {};
    float m0 = -INFINITY, m1 = -INFINITY, l0 = 0.f, l1 = 0.f;

    for (int kt = 0; kt < nkt; ++kt) {
        int buf = kt & 1;
        int k0 = kt * 64;
        if (kt + 1 < nkt) {
            flash_issue(sb, buf ^ 1, bh, (kt+1)*64, tid);
            CP_WAIT(1);
        } else {
            CP_WAIT(0);
        }
        __syncthreads();

        if (k0 <= rowmax) {
            uint32_t kb = sb + OB0 + buf*BUFB;
            uint32_t vb = kb + KVB;

            // ---- mask prefetch (gmem -> regs), consumed at softmax ----
            uint2 km0[8], km1[8];
            #pragma unroll
            for (int j = 0; j < 8; ++j) {
                km0[j] = *(const uint2*)(mrow0 + k0 + j*8);
                km1[j] = *(const uint2*)(mrow1 + k0 + j*8);
            }

            // ---- S = (Qh+Ql) K^T ----
            float s[8][4] = {};
            #pragma unroll
            for (int ks = 0; ks < 4; ++ks) {
                uint32_t ksb = ks * 32;
                uint32_t ah[4], al[4];
                ldsm4(ah, sb + OQH + qaoff + ksb);
                ldsm4(al, sb + OQL + qaoff + ksb);
                #pragma unroll
                for (int jp2 = 0; jp2 < 2; ++jp2) {
                    uint32_t k4[2][4];
                    ldsm4(k4[0], kb + bofff[2*jp2]     + ksb);
                    ldsm4(k4[1], kb + bofff[2*jp2 + 1] + ksb);
                    #pragma unroll
                    for (int p = 0; p < 2; ++p)
                        #pragma unroll
                        for (int jj = 0; jj < 2; ++jj)
                            mma16816(s[(2*jp2+p)*2+jj], ah, k4[p] + jj*2);
                    #pragma unroll
                    for (int p = 0; p < 2; ++p)
                        #pragma unroll
                        for (int jj = 0; jj < 2; ++jj)
                            mma16816(s[(2*jp2+p)*2+jj], al, k4[p] + jj*2);
                }
            }

            // ---- causal mask ----
            int row0 = q0 + r, row1 = row0 + 8;
            #pragma unroll
            for (int j = 0; j < 8; ++j) {
                int cg = k0 + j*8 + qc*2;
                if (cg     > row0) s[j][0] = -INFINITY;
                if (cg + 1 > row0) s[j][1] = -INFINITY;
                if (cg     > row1) s[j][2] = -INFINITY;
                if (cg + 1 > row1) s[j][3] = -INFINITY;
            }

            // ---- online softmax (undropped denominator) ----
            float mx0 = -INFINITY, mx1 = -INFINITY;
            #pragma unroll
            for (int j = 0; j < 8; ++j) {
                mx0 = fmaxf(mx0, fmaxf(s[j][0], s[j][1]));
                mx1 = fmaxf(mx1, fmaxf(s[j][2], s[j][3]));
            }
            mx0 = fmaxf(mx0, __shfl_xor_sync(0xffffffffu, mx0, 1));
            mx0 = fmaxf(mx0, __shfl_xor_sync(0xffffffffu, mx0, 2));
            mx1 = fmaxf(mx1, __shfl_xor_sync(0xffffffffu, mx1, 1));
            mx1 = fmaxf(mx1, __shfl_xor_sync(0xffffffffu, mx1, 2));
            float m0n = fmaxf(m0, mx0), m1n = fmaxf(m1, mx1);
            float a0 = __expf(m0 - m0n), a1 = __expf(m1 - m1n);
            float sum0 = 0.f, sum1 = 0.f;
            #pragma unroll
            for (int j = 0; j < 8; ++j) {
                float p0 = __expf(s[j][0] - m0n); sum0 += p0;
                float p1 = __expf(s[j][1] - m0n); sum0 += p1;
                float p2 = __expf(s[j][2] - m1n); sum1 += p2;
                float p3 = __expf(s[j][3] - m1n); sum1 += p3;
                s[j][0] = km0[j].x ? p0 * KEEP_INV : 0.f;
                s[j][1] = km0[j].y ? p1 * KEEP_INV : 0.f;
                s[j][2] = km1[j].x ? p2 * KEEP_INV : 0.f;
                s[j][3] = km1[j].y ? p3 * KEEP_INV : 0.f;
            }
            sum0 += __shfl_xor_sync(0xffffffffu, sum0, 1);
            sum0 += __shfl_xor_sync(0xffffffffu, sum0, 2);
            sum1 += __shfl_xor_sync(0xffffffffu, sum1, 1);
            sum1 += __shfl_xor_sync(0xffffffffu, sum1, 2);
            l0 = l0 * a0 + sum0;
            l1 = l1 * a1 + sum1;
            m0 = m0n; m1 = m1n;

            // ---- acc scale + (Ph+Pl) V ----
            #pragma unroll
            for (int j = 0; j < 8; ++j) {
                acc[j][0] *= a0; acc[j][1] *= a0;
                acc[j][2] *= a1; acc[j][3] *= a1;
            }
            #pragma unroll
            for (int s4 = 0; s4 < 4; ++s4) {
                uint32_t ph[4], pl[4];
                split2h(s[2*s4][0],   s[2*s4][1],   ph[0], pl[0]);
                split2h(s[2*s4][2],   s[2*s4][3],   ph[1], pl[1]);
                split2h(s[2*s4+1][0], s[2*s4+1][1], ph[2], pl[2]);
                split2h(s[2*s4+1][2], s[2*s4+1][3], ph[3], pl[3]);
                uint32_t ksb = s4 * 32;
                #pragma unroll
                for (int jp2 = 0; jp2 < 2; ++jp2) {
                    uint32_t v4[2][4];
                    ldsm4(v4[0], vb + bofff[2*jp2]     + ksb);
                    ldsm4(v4[1], vb + bofff[2*jp2 + 1] + ksb);
                    #pragma unroll
                    for (int p = 0; p < 2; ++p)
                        #pragma unroll
                        for (int jj = 0; jj < 2; ++jj)
                            mma16816(acc[(2*jp2+p)*2+jj], ph, v4[p] + jj*2);
                    #pragma unroll
                    for (int p = 0; p < 2; ++p)
                        #pragma unroll
                        for (int jj = 0; jj < 2; ++jj)
                            mma16816(acc[(2*jp2+p)*2+jj], pl, v4[p] + jj*2);
                }
            }
        }
        __syncthreads();
    }

    // ---- epilogue: y = acc / l, write split fp16 pair [tok][C] ----
    int b = bh >> 4, h = bh & 15;
    float inv0 = 1.f / l0, inv1 = 1.f / l1;
    size_t tok0 = (size_t)b*Tt + q0 + r;
    size_t tok1 = tok0 + 8;
    #pragma unroll
    for (int j = 0; j < 8; ++j) {
        int col = h*HD + j*8 + qc*2;
        uint32_t hi, lo;
        split2h(acc[j][0]*inv0, acc[j][1]*inv0, hi, lo);
        *(uint32_t*)&g_yh[tok0*Cc + col] = hi;
        *(uint32_t*)&g_yl[tok0*Cc + col] = lo;
        split2h(acc[j][2]*inv1, acc[j][3]*inv1, hi, lo);
        *(uint32_t*)&g_yh[tok1*Cc + col] = hi;
        *(uint32_t*)&g_yl[tok1*Cc + col] = lo;
    }
}

// ---------------------------------------------------------------------------
extern "C" void kernel_launch(void* const* d_in, const int* in_sizes, int n_in,
                              void* d_out, int out_size) {
    const float* x     = (const float*)d_in[0];
    const float* Wqkv  = (const float*)d_in[1];
    const float* bqkv  = (const float*)d_in[2];
    const float* Wproj = (const float*)d_in[3];
    const float* bproj = (const float*)d_in[4];
    const unsigned* amask = (const unsigned*)d_in[5];
    const unsigned* rmask = (const unsigned*)d_in[6];
    float* out = (float*)d_out;

    cudaFuncSetAttribute(gemm_mma<0>, cudaFuncAttributeMaxDynamicSharedMemorySize, GEMM_SMEM);
    cudaFuncSetAttribute(gemm_mma<1>, cudaFuncAttributeMaxDynamicSharedMemorySize, GEMM_SMEM);
    cudaFuncSetAttribute(flash_mma, cudaFuncAttributeMaxDynamicSharedMemorySize, FLASH_SMEM);

    __half *xh, *xl, *wqh, *wph, *yh, *yl;
    cudaGetSymbolAddress((void**)&xh,  g_xh);  cudaGetSymbolAddress((void**)&xl,  g_xl);
    cudaGetSymbolAddress((void**)&wqh, g_wqh); cudaGetSymbolAddress((void**)&wph, g_wph);
    cudaGetSymbolAddress((void**)&yh,  g_yh);  cudaGetSymbolAddress((void**)&yl,  g_yl);

    cvt_split<<<(NTOK*Cc/4 + 255)/256, 256>>>((const float4*)x, (__half2*)xh, (__half2*)xl, NTOK*Cc/4);
    cvt_trunc_T<<<dim3(C3/32, Cc/32), dim3(32,8)>>>(Wqkv, wqh, Cc, C3);
    cvt_trunc_T<<<dim3(Cc/32, Cc/32), dim3(32,8)>>>(Wproj, wph, Cc, Cc);

    gemm_mma<0><<<dim3(C3/128, NTOK/128), 256, GEMM_SMEM>>>(xh, xl, wqh, bqkv, nullptr, nullptr, Cc);

    flash_mma<<<dim3(Tt/128, Bsz*Hh), 256, FLASH_SMEM>>>(amask);

    gemm_mma<1><<<dim3(Cc/128, NTOK/128), 256, GEMM_SMEM>>>(yh, yl, wph, bproj, rmask, out, Cc);
}

// round 11
// speedup vs baseline: 1.6023x; 1.0201x over previous
#include <cuda_runtime.h>
#include <cuda_fp16.h>
#include <math.h>
#include <cstdint>

// Problem constants
#define Bsz 2
#define Tt 2048
#define Cc 1024
#define Hh 16
#define HD 64
#define NTOK (Bsz*Tt)   // 4096
#define C3 (3*Cc)       // 3072
#define KEEP_INV (1.0f/0.9f)

// ---------------- scratch (device globals; no allocs allowed) ---------------
__device__ __half g_xh[(size_t)NTOK*Cc], g_xl[(size_t)NTOK*Cc];
__device__ __half g_wqh[(size_t)C3*Cc];                    // [N,K] transposed, truncated
__device__ __half g_wph[(size_t)Cc*Cc];                    // [N,K] transposed, truncated
__device__ __half g_yh[(size_t)NTOK*Cc], g_yl[(size_t)NTOK*Cc];
__device__ __half g_qh[(size_t)32*Tt*HD], g_ql[(size_t)32*Tt*HD];  // q split, scaled
__device__ __half g_kh[(size_t)32*Tt*HD];                  // k truncated
__device__ __half g_vth[(size_t)32*HD*Tt];                 // v transposed, truncated

// ---------------- helpers ----------------
__device__ __forceinline__ uint32_t smem_u32(const void* p) {
    uint32_t a;
    asm("{ .reg .u64 t; cvta.to.shared.u64 t, %1; cvt.u32.u64 %0, t; }" : "=r"(a) : "l"(p));
    return a;
}
__device__ __forceinline__ void cp_async16(uint32_t dst, const void* src) {
    asm volatile("cp.async.cg.shared.global [%0], [%1], 16;" :: "r"(dst), "l"(src) : "memory");
}
#define CP_COMMIT() asm volatile("cp.async.commit_group;" ::: "memory")
#define CP_WAIT(n)  asm volatile("cp.async.wait_group %0;" :: "n"(n) : "memory")

__device__ __forceinline__ void mma16816(float* c, const uint32_t* a, const uint32_t* b) {
    asm volatile("mma.sync.aligned.m16n8k16.row.col.f32.f16.f16.f32 "
        "{%0,%1,%2,%3}, {%4,%5,%6,%7}, {%8,%9}, {%0,%1,%2,%3};"
        : "+f"(c[0]), "+f"(c[1]), "+f"(c[2]), "+f"(c[3])
        : "r"(a[0]), "r"(a[1]), "r"(a[2]), "r"(a[3]), "r"(b[0]), "r"(b[1]));
}
__device__ __forceinline__ void ldsm4(uint32_t* r, uint32_t a) {
    asm volatile("ldmatrix.sync.aligned.m8n8.x4.shared.b16 {%0,%1,%2,%3}, [%4];"
        : "=r"(r[0]), "=r"(r[1]), "=r"(r[2]), "=r"(r[3]) : "r"(a));
}
// pack two floats into hi/lo fp16x2 (split)
__device__ __forceinline__ void split2h(float a, float b, uint32_t& hi, uint32_t& lo) {
    __half ha = __float2half_rn(a), hb = __float2half_rn(b);
    __half2 H(ha, hb);
    hi = *(uint32_t*)&H;
    __half2 L(__float2half_rn(a - __half2float(ha)),
              __float2half_rn(b - __half2float(hb)));
    lo = *(uint32_t*)&L;
}
__device__ __forceinline__ uint32_t pack2h(float a, float b) {
    __half2 H(__float2half_rn(a), __float2half_rn(b));
    return *(uint32_t*)&H;
}

// ---------------------------------------------------------------------------
// fp32 -> (hi,lo) fp16 split
// ---------------------------------------------------------------------------
__global__ __launch_bounds__(256) void cvt_split(const float4* __restrict__ in,
                                                 __half2* __restrict__ hi,
                                                 __half2* __restrict__ lo,
                                                 int n4) {
    int i = blockIdx.x * 256 + threadIdx.x;
    if (i >= n4) return;
    float4 v = in[i];
    uint32_t h0, l0, h1, l1;
    split2h(v.x, v.y, h0, l0);
    split2h(v.z, v.w, h1, l1);
    hi[2*i]   = *(__half2*)&h0;
    hi[2*i+1] = *(__half2*)&h1;
    lo[2*i]   = *(__half2*)&l0;
    lo[2*i+1] = *(__half2*)&l1;
}

// fp32 W[K,N] -> transposed truncated fp16 [N,K]
__global__ __launch_bounds__(256) void cvt_trunc_T(const float* __restrict__ in,
                                                   __half* __restrict__ hi,
                                                   int K, int N) {
    __shared__ float t[32][33];
    int nx = blockIdx.x * 32, kx = blockIdx.y * 32;
    int tx = threadIdx.x, ty = threadIdx.y;  // (32,8)
    #pragma unroll
    for (int r = 0; r < 4; ++r)
        t[ty + 8*r][tx] = in[(size_t)(kx + ty + 8*r) * N + nx + tx];
    __syncthreads();
    #pragma unroll
    for (int r = 0; r < 4; ++r)
        hi[(size_t)(nx + ty + 8*r) * K + kx + tx] = __float2half_rn(t[tx][ty + 8*r]);
}

// ---------------------------------------------------------------------------
// mma.sync fp16 2-term GEMM: C = (Ah+Al)[M,K] * Bt[N,K]^T  (+bias, +epilogue)
// 128x128 tile, K-chunk 64, 2-stage cp.async, ldmatrix.x4. 108KB smem.
// MODE 0: qkv -> q split (scaled 1/8), k truncated, v via smem transpose.
// MODE 1: proj + resid dropout -> out (fp32).
// ---------------------------------------------------------------------------
#define SR 72                   // halves per row (64 + 8 pad) -> 144B stride
#define TILE_E (128*SR)
#define TILE_B (TILE_E*2)       // 18432 bytes
#define BUF_E  (3*TILE_E)
#define BUF_B  (3*TILE_B)       // 55296 bytes
#define GEMM_SMEM (2*BUF_B)     // 110592
#define TSR 136                 // transpose smem stride in halves (272B)

__device__ __forceinline__ void gemm_issue(uint32_t sb, int buf,
                                           const __half* Ah, const __half* Al,
                                           const __half* B,
                                           int m0, int n0, int K, int ch, int tid) {
    #pragma unroll
    for (int it = 0; it < 12; ++it) {
        int u = tid + it * 256;           // 0..3071
        int arr = u >> 10;                // 0..2
        int rem = u & 1023;
        int row = rem >> 3;
        int c16 = rem & 7;                // 16B unit (8 halves)
        const __half* src = (arr == 0) ? Ah : (arr == 1) ? Al : B;
        int grow = (arr < 2 ? m0 : n0) + row;
        uint32_t soff = (uint32_t)((buf * BUF_E + arr * TILE_E + row * SR + c16 * 8) * 2);
        cp_async16(sb + soff, src + (size_t)grow * K + ch * 64 + c16 * 8);
    }
    CP_COMMIT();
}

template<int MODE>
__global__ __launch_bounds__(256, 2) void gemm_mma(const __half* __restrict__ Ah,
                                                   const __half* __restrict__ Al,
                                                   const __half* __restrict__ B,
                                                   const float* __restrict__ bias,
                                                   const unsigned* __restrict__ rmask,
                                                   float* __restrict__ out,
                                                   int K) {
    extern __shared__ __half smg[];
    uint32_t sb = smem_u32(smg);
    int tid = threadIdx.x, wid = tid >> 5, lane = tid & 31;
    int m0 = blockIdx.y * 128, n0 = blockIdx.x * 128;
    int wm = (wid & 3) * 32, wn = (wid >> 2) * 64;
    int qr = lane >> 2, qc = lane & 3;
    int g = lane >> 3, lr = lane & 7;

    uint32_t aoff[2], boff[4];
    #pragma unroll
    for (int i = 0; i < 2; ++i)
        aoff[i] = (uint32_t)(((wm + i*16 + lr + (g & 1)*8) * SR + (g >> 1)*8) * 2);
    #pragma unroll
    for (int jp = 0; jp < 4; ++jp)
        boff[jp] = (uint32_t)(((wn + jp*16 + lr + (g >> 1)*8) * SR + (g & 1)*8) * 2);

    float acc[2][8][4] = {};
    int nch = K >> 6;

    gemm_issue(sb, 0, Ah, Al, B, m0, n0, K, 0, tid);

    for (int ch = 0; ch < nch; ++ch) {
        int buf = ch & 1;
        if (ch + 1 < nch) {
            gemm_issue(sb, buf ^ 1, Ah, Al, B, m0, n0, K, ch + 1, tid);
            CP_WAIT(1);
        } else {
            CP_WAIT(0);
        }
        __syncthreads();

        uint32_t bAh = sb + buf * BUF_B;
        uint32_t bAl = bAh + TILE_B;
        uint32_t bB  = bAh + 2*TILE_B;

        #pragma unroll
        for (int ks = 0; ks < 4; ++ks) {
            uint32_t ksb = ks * 32;
            uint32_t ah[2][4], al[2][4];
            ldsm4(ah[0], bAh + aoff[0] + ksb);
            ldsm4(ah[1], bAh + aoff[1] + ksb);
            ldsm4(al[0], bAl + aoff[0] + ksb);
            ldsm4(al[1], bAl + aoff[1] + ksb);
            #pragma unroll
            for (int jp2 = 0; jp2 < 2; ++jp2) {
                uint32_t b4[2][4];
                ldsm4(b4[0], bB + boff[2*jp2]     + ksb);
                ldsm4(b4[1], bB + boff[2*jp2 + 1] + ksb);
                #pragma unroll
                for (int p = 0; p < 2; ++p)
                    #pragma unroll
                    for (int jj = 0; jj < 2; ++jj)
                        #pragma unroll
                        for (int i = 0; i < 2; ++i)
                            mma16816(acc[i][(2*jp2+p)*2+jj], ah[i], b4[p] + jj*2);
                #pragma unroll
                for (int p = 0; p < 2; ++p)
                    #pragma unroll
                    for (int jj = 0; jj < 2; ++jj)
                        #pragma unroll
                        for (int i = 0; i < 2; ++i)
                            mma16816(acc[i][(2*jp2+p)*2+jj], al[i], b4[p] + jj*2);
            }
        }
        __syncthreads();
    }

    if (MODE == 0 && n0 >= 2*Cc) {
        // ---- V block: smem-bounce transpose, coalesced [d][t] store ----
        // write acc (with bias) transposed into smem: ts[col_local][row_local]
        #pragma unroll
        for (int i = 0; i < 2; ++i) {
            #pragma unroll
            for (int j = 0; j < 8; ++j) {
                int col0 = wn + j*8 + qc*2;
                float b0 = bias[n0 + col0], b1 = bias[n0 + col0 + 1];
                #pragma unroll
                for (int hrow = 0; hrow < 2; ++hrow) {
                    int rowl = wm + i*16 + qr + hrow*8;
                    smg[col0*TSR + rowl]     = __float2half_rn(acc[i][j][hrow*2+0] + b0);
                    smg[(col0+1)*TSR + rowl] = __float2half_rn(acc[i][j][hrow*2+1] + b1);
                }
            }
        }
        __syncthreads();
        int t0 = m0 & (Tt - 1);
        int b  = m0 >> 11;
        #pragma unroll
        for (int it = 0; it < 8; ++it) {
            int u = tid + it * 256;       // 0..2047
            int col = u >> 4, c8 = u & 15;
            uint4 val = *(uint4*)&smg[col*TSR + c8*8];
            int vcol = (n0 - 2*Cc) + col;
            int h = vcol >> 6, dd = vcol & 63;
            int bh = b*Hh + h;
            *(uint4*)&g_vth[((size_t)bh*HD + dd)*Tt + t0 + c8*8] = val;
        }
        return;
    }

    // Epilogue (q, k, proj)
    #pragma unroll
    for (int i = 0; i < 2; ++i) {
        int R0 = m0 + wm + i * 16 + qr;
        #pragma unroll
        for (int j = 0; j < 8; ++j) {
            int C0 = n0 + wn + j * 8 + qc * 2;
            float b0 = bias[C0], b1 = bias[C0 + 1];
            #pragma unroll
            for (int hrow = 0; hrow < 2; ++hrow) {
                int m = R0 + hrow * 8;
                float v0 = acc[i][j][hrow*2 + 0] + b0;
                float v1 = acc[i][j][hrow*2 + 1] + b1;
                if (MODE == 0) {
                    int bb = m >> 11, t = m & (Tt - 1);
                    int which = C0 >> 10, cidx = C0 & 1023;
                    int h = cidx >> 6, dd = cidx & 63;
                    int bh = bb * Hh + h;
                    if (which == 0) {
                        uint32_t hi, lo;
                        split2h(v0 * 0.125f, v1 * 0.125f, hi, lo);
                        size_t o = ((size_t)bh*Tt + t)*HD + dd;
                        *(uint32_t*)&g_qh[o] = hi;
                        *(uint32_t*)&g_ql[o] = lo;
                    } else {
                        size_t o = ((size_t)bh*Tt + t)*HD + dd;
                        *(uint32_t*)&g_kh[o] = pack2h(v0, v1);
                    }
                } else {
                    size_t idx = (size_t)m * Cc + C0;
                    out[idx]     = rmask[idx]     ? v0 * KEEP_INV : 0.f;
                    out[idx + 1] = rmask[idx + 1] ? v1 * KEEP_INV : 0.f;
                }
            }
        }
    }
}

// ---------------------------------------------------------------------------
// Flash attention, fp16 2-term, 128-wide k-tiles (2 x 64 halves per sync).
// K/V truncated. 108KB smem -> 2 CTAs/SM.
// ---------------------------------------------------------------------------
#define SRK 72                       // fp16 row stride for 64-col tiles
#define OQH 0
#define OQL (128*SRK*2)              // 18432
#define OB0 (2*128*SRK*2)            // 36864
#define KVB (64*SRK*2)               // 9216
#define BUFB (4*KVB)                 // 36864 : [K0,V0,K1,V1]
#define FLASH_SMEM (OB0 + 2*BUFB)    // 110592

__device__ __forceinline__ void flash_issue(uint32_t sb, int buf,
                                            int bh, int k0, int tid) {
    // K: 128 rows x 64 halves (two 64-row subtiles)
    #pragma unroll
    for (int it = 0; it < 4; ++it) {
        int u = tid + it * 256;           // 0..1023
        int row = u >> 3, ck = u & 7;
        int half = row >> 6, lr_ = row & 63;
        uint32_t dst = sb + OB0 + buf*BUFB + (2*half)*KVB + (uint32_t)(lr_*SRK + ck*8)*2;
        cp_async16(dst, g_kh + ((size_t)bh*Tt + k0 + row)*HD + ck*8);
    }
    // V: 64 d-rows x 128 t (two 64-t subtiles)
    #pragma unroll
    for (int it = 0; it < 4; ++it) {
        int u = tid + it * 256;
        int d = u >> 4, ct = u & 15;
        int thalf = ct >> 3, tc = ct & 7;
        uint32_t dst = sb + OB0 + buf*BUFB + (2*thalf+1)*KVB + (uint32_t)(d*SRK + tc*8)*2;
        cp_async16(dst, g_vth + ((size_t)bh*HD + d)*Tt + k0 + ct*8);
    }
    CP_COMMIT();
}

__global__ __launch_bounds__(256, 2) void flash_mma(const unsigned* __restrict__ amask) {
    extern __shared__ char smf[];
    uint32_t sb = smem_u32(smf);
    int tid = threadIdx.x, wid = tid >> 5, lane = tid & 31;
    int qr = lane >> 2, qc = lane & 3;
    int g = lane >> 3, lr = lane & 7;
    int bh = blockIdx.y;
    int qb = (gridDim.x - 1) - blockIdx.x;   // big tiles first
    int q0 = qb * 128;
    int nkt = qb + 1;                        // 128-wide tiles

    // Q pair tile load — same cp.async group as tile 0
    #pragma unroll
    for (int it = 0; it < 8; ++it) {
        int u = tid + it * 256;
        int arr = u >> 10;
        int rem = u & 1023;
        int row = rem >> 3;
        int ck = rem & 7;
        const __half* src = arr ? g_ql : g_qh;
        uint32_t dst = sb + (arr ? OQL : OQH) + (uint32_t)(row*SRK + ck*8)*2;
        cp_async16(dst, src + ((size_t)bh*Tt + q0 + row)*HD + ck*8);
    }
    flash_issue(sb, 0, bh, 0, tid);

    uint32_t qaoff = (uint32_t)(((wid*16 + lr + (g & 1)*8) * SRK + (g >> 1)*8) * 2);
    uint32_t bofff[4];
    #pragma unroll
    for (int jp = 0; jp < 4; ++jp)
        bofff[jp] = (uint32_t)(((jp*16 + lr + (g >> 1)*8) * SRK + (g & 1)*8) * 2);

    int r = wid * 16 + qr;                  // q row within tile
    int rowmax = q0 + wid * 16 + 15;
    const unsigned* mrow0 = amask + ((size_t)bh*Tt + q0 + r)*Tt + qc*2;
    const unsigned* mrow1 = mrow0 + (size_t)8*Tt;

    float acc[8][4] = {};
    float m0 = -INFINITY, m1 = -INFINITY, l0 = 0.f, l1 = 0.f;

    for (int kt = 0; kt < nkt; ++kt) {
        int buf = kt & 1;
        if (kt + 1 < nkt) {
            flash_issue(sb, buf ^ 1, bh, (kt+1)*128, tid);
            CP_WAIT(1);
        } else {
            CP_WAIT(0);
        }
        __syncthreads();

        #pragma unroll
        for (int half = 0; half < 2; ++half) {
            int k0 = kt * 128 + half * 64;
            if (k0 > rowmax) continue;
            uint32_t kb = sb + OB0 + buf*BUFB + (2*half)*KVB;
            uint32_t vb = kb + KVB;

            // ---- mask prefetch (gmem -> regs), consumed at softmax ----
            uint2 km0[8], km1[8];
            #pragma unroll
            for (int j = 0; j < 8; ++j) {
                km0[j] = *(const uint2*)(mrow0 + k0 + j*8);
                km1[j] = *(const uint2*)(mrow1 + k0 + j*8);
            }

            // ---- S = (Qh+Ql) K^T ----
            float s[8][4] = {};
            #pragma unroll
            for (int ks = 0; ks < 4; ++ks) {
                uint32_t ksb = ks * 32;
                uint32_t ah[4], al[4];
                ldsm4(ah, sb + OQH + qaoff + ksb);
                ldsm4(al, sb + OQL + qaoff + ksb);
                #pragma unroll
                for (int jp2 = 0; jp2 < 2; ++jp2) {
                    uint32_t k4[2][4];
                    ldsm4(k4[0], kb + bofff[2*jp2]     + ksb);
                    ldsm4(k4[1], kb + bofff[2*jp2 + 1] + ksb);
                    #pragma unroll
                    for (int p = 0; p < 2; ++p)
                        #pragma unroll
                        for (int jj = 0; jj < 2; ++jj)
                            mma16816(s[(2*jp2+p)*2+jj], ah, k4[p] + jj*2);
                    #pragma unroll
                    for (int p = 0; p < 2; ++p)
                        #pragma unroll
                        for (int jj = 0; jj < 2; ++jj)
                            mma16816(s[(2*jp2+p)*2+jj], al, k4[p] + jj*2);
                }
            }

            // ---- causal mask ----
            int row0 = q0 + r, row1 = row0 + 8;
            #pragma unroll
            for (int j = 0; j < 8; ++j) {
                int cg = k0 + j*8 + qc*2;
                if (cg     > row0) s[j][0] = -INFINITY;
                if (cg + 1 > row0) s[j][1] = -INFINITY;
                if (cg     > row1) s[j][2] = -INFINITY;
                if (cg + 1 > row1) s[j][3] = -INFINITY;
            }

            // ---- online softmax (undropped denominator) ----
            float mx0 = -INFINITY, mx1 = -INFINITY;
            #pragma unroll
            for (int j = 0; j < 8; ++j) {
                mx0 = fmaxf(mx0, fmaxf(s[j][0], s[j][1]));
                mx1 = fmaxf(mx1, fmaxf(s[j][2], s[j][3]));
            }
            mx0 = fmaxf(mx0, __shfl_xor_sync(0xffffffffu, mx0, 1));
            mx0 = fmaxf(mx0, __shfl_xor_sync(0xffffffffu, mx0, 2));
            mx1 = fmaxf(mx1, __shfl_xor_sync(0xffffffffu, mx1, 1));
            mx1 = fmaxf(mx1, __shfl_xor_sync(0xffffffffu, mx1, 2));
            float m0n = fmaxf(m0, mx0), m1n = fmaxf(m1, mx1);
            float a0 = __expf(m0 - m0n), a1 = __expf(m1 - m1n);
            float sum0 = 0.f, sum1 = 0.f;
            #pragma unroll
            for (int j = 0; j < 8; ++j) {
                float p0 = __expf(s[j][0] - m0n); sum0 += p0;
                float p1 = __expf(s[j][1] - m0n); sum0 += p1;
                float p2 = __expf(s[j][2] - m1n); sum1 += p2;
                float p3 = __expf(s[j][3] - m1n); sum1 += p3;
                s[j][0] = km0[j].x ? p0 * KEEP_INV : 0.f;
                s[j][1] = km0[j].y ? p1 * KEEP_INV : 0.f;
                s[j][2] = km1[j].x ? p2 * KEEP_INV : 0.f;
                s[j][3] = km1[j].y ? p3 * KEEP_INV : 0.f;
            }
            sum0 += __shfl_xor_sync(0xffffffffu, sum0, 1);
            sum0 += __shfl_xor_sync(0xffffffffu, sum0, 2);
            sum1 += __shfl_xor_sync(0xffffffffu, sum1, 1);
            sum1 += __shfl_xor_sync(0xffffffffu, sum1, 2);
            l0 = l0 * a0 + sum0;
            l1 = l1 * a1 + sum1;
            m0 = m0n; m1 = m1n;

            // ---- acc scale + (Ph+Pl) V ----
            #pragma unroll
            for (int j = 0; j < 8; ++j) {
                acc[j][0] *= a0; acc[j][1] *= a0;
                acc[j][2] *= a1; acc[j][3] *= a1;
            }
            #pragma unroll
            for (int s4 = 0; s4 < 4; ++s4) {
                uint32_t ph[4], pl[4];
                split2h(s[2*s4][0],   s[2*s4][1],   ph[0], pl[0]);
                split2h(s[2*s4][2],   s[2*s4][3],   ph[1], pl[1]);
                split2h(s[2*s4+1][0], s[2*s4+1][1], ph[2], pl[2]);
                split2h(s[2*s4+1][2], s[2*s4+1][3], ph[3], pl[3]);
                uint32_t ksb = s4 * 32;
                #pragma unroll
                for (int jp2 = 0; jp2 < 2; ++jp2) {
                    uint32_t v4[2][4];
                    ldsm4(v4[0], vb + bofff[2*jp2]     + ksb);
                    ldsm4(v4[1], vb + bofff[2*jp2 + 1] + ksb);
                    #pragma unroll
                    for (int p = 0; p < 2; ++p)
                        #pragma unroll
                        for (int jj = 0; jj < 2; ++jj)
                            mma16816(acc[(2*jp2+p)*2+jj], ph, v4[p] + jj*2);
                    #pragma unroll
                    for (int p = 0; p < 2; ++p)
                        #pragma unroll
                        for (int jj = 0; jj < 2; ++jj)
                            mma16816(acc[(2*jp2+p)*2+jj], pl, v4[p] + jj*2);
                }
            }
        }
        __syncthreads();
    }

    // ---- epilogue: y = acc / l, write split fp16 pair [tok][C] ----
    int b = bh >> 4, h = bh & 15;
    float inv0 = 1.f / l0, inv1 = 1.f / l1;
    size_t tok0 = (size_t)b*Tt + q0 + r;
    size_t tok1 = tok0 + 8;
    #pragma unroll
    for (int j = 0; j < 8; ++j) {
        int col = h*HD + j*8 + qc*2;
        uint32_t hi, lo;
        split2h(acc[j][0]*inv0, acc[j][1]*inv0, hi, lo);
        *(uint32_t*)&g_yh[tok0*Cc + col] = hi;
        *(uint32_t*)&g_yl[tok0*Cc + col] = lo;
        split2h(acc[j][2]*inv1, acc[j][3]*inv1, hi, lo);
        *(uint32_t*)&g_yh[tok1*Cc + col] = hi;
        *(uint32_t*)&g_yl[tok1*Cc + col] = lo;
    }
}

// ---------------------------------------------------------------------------
extern "C" void kernel_launch(void* const* d_in, const int* in_sizes, int n_in,
                              void* d_out, int out_size) {
    const float* x     = (const float*)d_in[0];
    const float* Wqkv  = (const float*)d_in[1];
    const float* bqkv  = (const float*)d_in[2];
    const float* Wproj = (const float*)d_in[3];
    const float* bproj = (const float*)d_in[4];
    const unsigned* amask = (const unsigned*)d_in[5];
    const unsigned* rmask = (const unsigned*)d_in[6];
    float* out = (float*)d_out;

    cudaFuncSetAttribute(gemm_mma<0>, cudaFuncAttributeMaxDynamicSharedMemorySize, GEMM_SMEM);
    cudaFuncSetAttribute(gemm_mma<1>, cudaFuncAttributeMaxDynamicSharedMemorySize, GEMM_SMEM);
    cudaFuncSetAttribute(flash_mma, cudaFuncAttributeMaxDynamicSharedMemorySize, FLASH_SMEM);

    __half *xh, *xl, *wqh, *wph, *yh, *yl;
    cudaGetSymbolAddress((void**)&xh,  g_xh);  cudaGetSymbolAddress((void**)&xl,  g_xl);
    cudaGetSymbolAddress((void**)&wqh, g_wqh); cudaGetSymbolAddress((void**)&wph, g_wph);
    cudaGetSymbolAddress((void**)&yh,  g_yh);  cudaGetSymbolAddress((void**)&yl,  g_yl);

    cvt_split<<<(NTOK*Cc/4 + 255)/256, 256>>>((const float4*)x, (__half2*)xh, (__half2*)xl, NTOK*Cc/4);
    cvt_trunc_T<<<dim3(C3/32, Cc/32), dim3(32,8)>>>(Wqkv, wqh, Cc, C3);
    cvt_trunc_T<<<dim3(Cc/32, Cc/32), dim3(32,8)>>>(Wproj, wph, Cc, Cc);

    gemm_mma<0><<<dim3(C3/128, NTOK/128), 256, GEMM_SMEM>>>(xh, xl, wqh, bqkv, nullptr, nullptr, Cc);

    flash_mma<<<dim3(Tt/128, Bsz*Hh), 256, FLASH_SMEM>>>(amask);

    gemm_mma<1><<<dim3(Cc/128, NTOK/128), 256, GEMM_SMEM>>>(yh, yl, wph, bproj, rmask, out, Cc);
}

// round 12
// speedup vs baseline: 1.7208x; 1.0740x over previous
#include <cuda_runtime.h>
#include <cuda_fp16.h>
#include <math.h>
#include <cstdint>

// Problem constants
#define Bsz 2
#define Tt 2048
#define Cc 1024
#define Hh 16
#define HD 64
#define NTOK (Bsz*Tt)   // 4096
#define C3 (3*Cc)       // 3072
#define KEEP_INV (1.0f/0.9f)
#define NQB 16          // q-tiles of 128

// ---------------- scratch (device globals; no allocs allowed) ---------------
__device__ __half g_xh[(size_t)NTOK*Cc], g_xl[(size_t)NTOK*Cc];
__device__ __half g_wqh[(size_t)C3*Cc];                    // [N,K] transposed, truncated
__device__ __half g_wph[(size_t)Cc*Cc];                    // [N,K] transposed, truncated
__device__ __half g_yh[(size_t)NTOK*Cc], g_yl[(size_t)NTOK*Cc];
__device__ __half g_qh[(size_t)32*Tt*HD], g_ql[(size_t)32*Tt*HD];  // q split, scaled
__device__ __half g_kh[(size_t)32*Tt*HD];                  // k truncated
__device__ __half g_vth[(size_t)32*HD*Tt];                 // v transposed, truncated

// ---------------- helpers ----------------
__device__ __forceinline__ uint32_t smem_u32(const void* p) {
    uint32_t a;
    asm("{ .reg .u64 t; cvta.to.shared.u64 t, %1; cvt.u32.u64 %0, t; }" : "=r"(a) : "l"(p));
    return a;
}
__device__ __forceinline__ void cp_async16(uint32_t dst, const void* src) {
    asm volatile("cp.async.cg.shared.global [%0], [%1], 16;" :: "r"(dst), "l"(src) : "memory");
}
#define CP_COMMIT() asm volatile("cp.async.commit_group;" ::: "memory")
#define CP_WAIT(n)  asm volatile("cp.async.wait_group %0;" :: "n"(n) : "memory")

__device__ __forceinline__ void mma16816(float* c, const uint32_t* a, const uint32_t* b) {
    asm volatile("mma.sync.aligned.m16n8k16.row.col.f32.f16.f16.f32 "
        "{%0,%1,%2,%3}, {%4,%5,%6,%7}, {%8,%9}, {%0,%1,%2,%3};"
        : "+f"(c[0]), "+f"(c[1]), "+f"(c[2]), "+f"(c[3])
        : "r"(a[0]), "r"(a[1]), "r"(a[2]), "r"(a[3]), "r"(b[0]), "r"(b[1]));
}
__device__ __forceinline__ void ldsm4(uint32_t* r, uint32_t a) {
    asm volatile("ldmatrix.sync.aligned.m8n8.x4.shared.b16 {%0,%1,%2,%3}, [%4];"
        : "=r"(r[0]), "=r"(r[1]), "=r"(r[2]), "=r"(r[3]) : "r"(a));
}
// pack two floats into hi/lo fp16x2 (split)
__device__ __forceinline__ void split2h(float a, float b, uint32_t& hi, uint32_t& lo) {
    __half ha = __float2half_rn(a), hb = __float2half_rn(b);
    __half2 H(ha, hb);
    hi = *(uint32_t*)&H;
    __half2 L(__float2half_rn(a - __half2float(ha)),
              __float2half_rn(b - __half2float(hb)));
    lo = *(uint32_t*)&L;
}
__device__ __forceinline__ uint32_t pack2h(float a, float b) {
    __half2 H(__float2half_rn(a), __float2half_rn(b));
    return *(uint32_t*)&H;
}

// ---------------------------------------------------------------------------
// fp32 -> (hi,lo) fp16 split
// ---------------------------------------------------------------------------
__global__ __launch_bounds__(256) void cvt_split(const float4* __restrict__ in,
                                                 __half2* __restrict__ hi,
                                                 __half2* __restrict__ lo,
                                                 int n4) {
    int i = blockIdx.x * 256 + threadIdx.x;
    if (i >= n4) return;
    float4 v = in[i];
    uint32_t h0, l0, h1, l1;
    split2h(v.x, v.y, h0, l0);
    split2h(v.z, v.w, h1, l1);
    hi[2*i]   = *(__half2*)&h0;
    hi[2*i+1] = *(__half2*)&h1;
    lo[2*i]   = *(__half2*)&l0;
    lo[2*i+1] = *(__half2*)&l1;
}

// fp32 W[K,N] -> transposed truncated fp16 [N,K]
__global__ __launch_bounds__(256) void cvt_trunc_T(const float* __restrict__ in,
                                                   __half* __restrict__ hi,
                                                   int K, int N) {
    __shared__ float t[32][33];
    int nx = blockIdx.x * 32, kx = blockIdx.y * 32;
    int tx = threadIdx.x, ty = threadIdx.y;  // (32,8)
    #pragma unroll
    for (int r = 0; r < 4; ++r)
        t[ty + 8*r][tx] = in[(size_t)(kx + ty + 8*r) * N + nx + tx];
    __syncthreads();
    #pragma unroll
    for (int r = 0; r < 4; ++r)
        hi[(size_t)(nx + ty + 8*r) * K + kx + tx] = __float2half_rn(t[tx][ty + 8*r]);
}

// ---------------------------------------------------------------------------
// mma.sync fp16 2-term GEMM: C = (Ah+Al)[M,K] * Bt[N,K]^T  (+bias, +epilogue)
// 128x128 tile, K-chunk 64, 2-stage cp.async, ldmatrix.x4. 108KB smem.
// MODE 0: qkv -> q split (scaled 1/8), k truncated, v via smem transpose.
// MODE 1: proj + resid dropout -> out (fp32).
// ---------------------------------------------------------------------------
#define SR 72                   // halves per row (64 + 8 pad) -> 144B stride
#define TILE_E (128*SR)
#define TILE_B (TILE_E*2)       // 18432 bytes
#define BUF_E  (3*TILE_E)
#define BUF_B  (3*TILE_B)       // 55296 bytes
#define GEMM_SMEM (2*BUF_B)     // 110592
#define TSR 136                 // transpose smem stride in halves (272B)

__device__ __forceinline__ void gemm_issue(uint32_t sb, int buf,
                                           const __half* Ah, const __half* Al,
                                           const __half* B,
                                           int m0, int n0, int K, int ch, int tid) {
    #pragma unroll
    for (int it = 0; it < 12; ++it) {
        int u = tid + it * 256;           // 0..3071
        int arr = u >> 10;                // 0..2
        int rem = u & 1023;
        int row = rem >> 3;
        int c16 = rem & 7;                // 16B unit (8 halves)
        const __half* src = (arr == 0) ? Ah : (arr == 1) ? Al : B;
        int grow = (arr < 2 ? m0 : n0) + row;
        uint32_t soff = (uint32_t)((buf * BUF_E + arr * TILE_E + row * SR + c16 * 8) * 2);
        cp_async16(sb + soff, src + (size_t)grow * K + ch * 64 + c16 * 8);
    }
    CP_COMMIT();
}

template<int MODE>
__global__ __launch_bounds__(256, 2) void gemm_mma(const __half* __restrict__ Ah,
                                                   const __half* __restrict__ Al,
                                                   const __half* __restrict__ B,
                                                   const float* __restrict__ bias,
                                                   const unsigned* __restrict__ rmask,
                                                   float* __restrict__ out,
                                                   int K) {
    extern __shared__ __half smg[];
    uint32_t sb = smem_u32(smg);
    int tid = threadIdx.x, wid = tid >> 5, lane = tid & 31;
    int m0 = blockIdx.y * 128, n0 = blockIdx.x * 128;
    int wm = (wid & 3) * 32, wn = (wid >> 2) * 64;
    int qr = lane >> 2, qc = lane & 3;
    int g = lane >> 3, lr = lane & 7;

    uint32_t aoff[2], boff[4];
    #pragma unroll
    for (int i = 0; i < 2; ++i)
        aoff[i] = (uint32_t)(((wm + i*16 + lr + (g & 1)*8) * SR + (g >> 1)*8) * 2);
    #pragma unroll
    for (int jp = 0; jp < 4; ++jp)
        boff[jp] = (uint32_t)(((wn + jp*16 + lr + (g >> 1)*8) * SR + (g & 1)*8) * 2);

    float acc[2][8][4] = {};
    int nch = K >> 6;

    gemm_issue(sb, 0, Ah, Al, B, m0, n0, K, 0, tid);

    for (int ch = 0; ch < nch; ++ch) {
        int buf = ch & 1;
        if (ch + 1 < nch) {
            gemm_issue(sb, buf ^ 1, Ah, Al, B, m0, n0, K, ch + 1, tid);
            CP_WAIT(1);
        } else {
            CP_WAIT(0);
        }
        __syncthreads();

        uint32_t bAh = sb + buf * BUF_B;
        uint32_t bAl = bAh + TILE_B;
        uint32_t bB  = bAh + 2*TILE_B;

        #pragma unroll
        for (int ks = 0; ks < 4; ++ks) {
            uint32_t ksb = ks * 32;
            uint32_t ah[2][4], al[2][4];
            ldsm4(ah[0], bAh + aoff[0] + ksb);
            ldsm4(ah[1], bAh + aoff[1] + ksb);
            ldsm4(al[0], bAl + aoff[0] + ksb);
            ldsm4(al[1], bAl + aoff[1] + ksb);
            #pragma unroll
            for (int jp2 = 0; jp2 < 2; ++jp2) {
                uint32_t b4[2][4];
                ldsm4(b4[0], bB + boff[2*jp2]     + ksb);
                ldsm4(b4[1], bB + boff[2*jp2 + 1] + ksb);
                #pragma unroll
                for (int p = 0; p < 2; ++p)
                    #pragma unroll
                    for (int jj = 0; jj < 2; ++jj)
                        #pragma unroll
                        for (int i = 0; i < 2; ++i)
                            mma16816(acc[i][(2*jp2+p)*2+jj], ah[i], b4[p] + jj*2);
                #pragma unroll
                for (int p = 0; p < 2; ++p)
                    #pragma unroll
                    for (int jj = 0; jj < 2; ++jj)
                        #pragma unroll
                        for (int i = 0; i < 2; ++i)
                            mma16816(acc[i][(2*jp2+p)*2+jj], al[i], b4[p] + jj*2);
            }
        }
        __syncthreads();
    }

    if (MODE == 0 && n0 >= 2*Cc) {
        // ---- V block: smem-bounce transpose, coalesced [d][t] store ----
        #pragma unroll
        for (int i = 0; i < 2; ++i) {
            #pragma unroll
            for (int j = 0; j < 8; ++j) {
                int col0 = wn + j*8 + qc*2;
                float b0 = bias[n0 + col0], b1 = bias[n0 + col0 + 1];
                #pragma unroll
                for (int hrow = 0; hrow < 2; ++hrow) {
                    int rowl = wm + i*16 + qr + hrow*8;
                    smg[col0*TSR + rowl]     = __float2half_rn(acc[i][j][hrow*2+0] + b0);
                    smg[(col0+1)*TSR + rowl] = __float2half_rn(acc[i][j][hrow*2+1] + b1);
                }
            }
        }
        __syncthreads();
        int t0 = m0 & (Tt - 1);
        int b  = m0 >> 11;
        #pragma unroll
        for (int it = 0; it < 8; ++it) {
            int u = tid + it * 256;       // 0..2047
            int col = u >> 4, c8 = u & 15;
            uint4 val = *(uint4*)&smg[col*TSR + c8*8];
            int vcol = (n0 - 2*Cc) + col;
            int h = vcol >> 6, dd = vcol & 63;
            int bh = b*Hh + h;
            *(uint4*)&g_vth[((size_t)bh*HD + dd)*Tt + t0 + c8*8] = val;
        }
        return;
    }

    // Epilogue (q, k, proj)
    #pragma unroll
    for (int i = 0; i < 2; ++i) {
        int R0 = m0 + wm + i * 16 + qr;
        #pragma unroll
        for (int j = 0; j < 8; ++j) {
            int C0 = n0 + wn + j * 8 + qc * 2;
            float b0 = bias[C0], b1 = bias[C0 + 1];
            #pragma unroll
            for (int hrow = 0; hrow < 2; ++hrow) {
                int m = R0 + hrow * 8;
                float v0 = acc[i][j][hrow*2 + 0] + b0;
                float v1 = acc[i][j][hrow*2 + 1] + b1;
                if (MODE == 0) {
                    int bb = m >> 11, t = m & (Tt - 1);
                    int which = C0 >> 10, cidx = C0 & 1023;
                    int h = cidx >> 6, dd = cidx & 63;
                    int bh = bb * Hh + h;
                    if (which == 0) {
                        uint32_t hi, lo;
                        split2h(v0 * 0.125f, v1 * 0.125f, hi, lo);
                        size_t o = ((size_t)bh*Tt + t)*HD + dd;
                        *(uint32_t*)&g_qh[o] = hi;
                        *(uint32_t*)&g_ql[o] = lo;
                    } else {
                        size_t o = ((size_t)bh*Tt + t)*HD + dd;
                        *(uint32_t*)&g_kh[o] = pack2h(v0, v1);
                    }
                } else {
                    size_t idx = (size_t)m * Cc + C0;
                    out[idx]     = rmask[idx]     ? v0 * KEEP_INV : 0.f;
                    out[idx + 1] = rmask[idx + 1] ? v1 * KEEP_INV : 0.f;
                }
            }
        }
    }
}

// ---------------------------------------------------------------------------
// Flash attention, fp16 2-term, 128-wide k-tiles, PAIRED q-tiles per CTA:
// CTA bx processes qb = (NQB-1-bx) then qb = bx -> every CTA does exactly
// NQB+1 = 17 tile-units; grid 8x32 = 256 CTAs = one balanced wave.
// ---------------------------------------------------------------------------
#define SRK 72                       // fp16 row stride for 64-col tiles
#define OQH 0
#define OQL (128*SRK*2)              // 18432
#define OB0 (2*128*SRK*2)            // 36864
#define KVB (64*SRK*2)               // 9216
#define BUFB (4*KVB)                 // 36864 : [K0,V0,K1,V1]
#define FLASH_SMEM (OB0 + 2*BUFB)    // 110592

__device__ __forceinline__ void flash_issue(uint32_t sb, int buf,
                                            int bh, int k0, int tid) {
    // K: 128 rows x 64 halves (two 64-row subtiles)
    #pragma unroll
    for (int it = 0; it < 4; ++it) {
        int u = tid + it * 256;           // 0..1023
        int row = u >> 3, ck = u & 7;
        int half = row >> 6, lr_ = row & 63;
        uint32_t dst = sb + OB0 + buf*BUFB + (2*half)*KVB + (uint32_t)(lr_*SRK + ck*8)*2;
        cp_async16(dst, g_kh + ((size_t)bh*Tt + k0 + row)*HD + ck*8);
    }
    // V: 64 d-rows x 128 t (two 64-t subtiles)
    #pragma unroll
    for (int it = 0; it < 4; ++it) {
        int u = tid + it * 256;
        int d = u >> 4, ct = u & 15;
        int thalf = ct >> 3, tc = ct & 7;
        uint32_t dst = sb + OB0 + buf*BUFB + (2*thalf+1)*KVB + (uint32_t)(d*SRK + tc*8)*2;
        cp_async16(dst, g_vth + ((size_t)bh*HD + d)*Tt + k0 + ct*8);
    }
    CP_COMMIT();
}

__global__ __launch_bounds__(256, 2) void flash_mma(const unsigned* __restrict__ amask) {
    extern __shared__ char smf[];
    uint32_t sb = smem_u32(smf);
    int tid = threadIdx.x, wid = tid >> 5, lane = tid & 31;
    int qr = lane >> 2, qc = lane & 3;
    int g = lane >> 3, lr = lane & 7;
    int bh = blockIdx.y;

    uint32_t qaoff = (uint32_t)(((wid*16 + lr + (g & 1)*8) * SRK + (g >> 1)*8) * 2);
    uint32_t bofff[4];
    #pragma unroll
    for (int jp = 0; jp < 4; ++jp)
        bofff[jp] = (uint32_t)(((jp*16 + lr + (g >> 1)*8) * SRK + (g & 1)*8) * 2);

    int r = wid * 16 + qr;                  // q row within tile

    for (int ph = 0; ph < 2; ++ph) {
        int qb = ph ? (int)blockIdx.x : (NQB - 1 - (int)blockIdx.x);
        int q0 = qb * 128;
        int nkt = qb + 1;                   // 128-wide tiles
        int rowmax = q0 + wid * 16 + 15;
        const unsigned* mrow0 = amask + ((size_t)bh*Tt + q0 + r)*Tt + qc*2;
        const unsigned* mrow1 = mrow0 + (size_t)8*Tt;

        // Q pair tile load — same cp.async group as tile 0
        #pragma unroll
        for (int it = 0; it < 8; ++it) {
            int u = tid + it * 256;
            int arr = u >> 10;
            int rem = u & 1023;
            int row = rem >> 3;
            int ck = rem & 7;
            const __half* src = arr ? g_ql : g_qh;
            uint32_t dst = sb + (arr ? OQL : OQH) + (uint32_t)(row*SRK + ck*8)*2;
            cp_async16(dst, src + ((size_t)bh*Tt + q0 + row)*HD + ck*8);
        }
        flash_issue(sb, 0, bh, 0, tid);

        float acc[8][4] = {};
        float m0 = -INFINITY, m1 = -INFINITY, l0 = 0.f, l1 = 0.f;

        for (int kt = 0; kt < nkt; ++kt) {
            int buf = kt & 1;
            if (kt + 1 < nkt) {
                flash_issue(sb, buf ^ 1, bh, (kt+1)*128, tid);
                CP_WAIT(1);
            } else {
                CP_WAIT(0);
            }
            __syncthreads();

            #pragma unroll
            for (int half = 0; half < 2; ++half) {
                int k0 = kt * 128 + half * 64;
                if (k0 > rowmax) continue;
                uint32_t kb = sb + OB0 + buf*BUFB + (2*half)*KVB;
                uint32_t vb = kb + KVB;

                // ---- mask prefetch (gmem -> regs), consumed at softmax ----
                uint2 km0[8], km1[8];
                #pragma unroll
                for (int j = 0; j < 8; ++j) {
                    km0[j] = *(const uint2*)(mrow0 + k0 + j*8);
                    km1[j] = *(const uint2*)(mrow1 + k0 + j*8);
                }

                // ---- S = (Qh+Ql) K^T ----
                float s[8][4] = {};
                #pragma unroll
                for (int ks = 0; ks < 4; ++ks) {
                    uint32_t ksb = ks * 32;
                    uint32_t ah[4], al[4];
                    ldsm4(ah, sb + OQH + qaoff + ksb);
                    ldsm4(al, sb + OQL + qaoff + ksb);
                    #pragma unroll
                    for (int jp2 = 0; jp2 < 2; ++jp2) {
                        uint32_t k4[2][4];
                        ldsm4(k4[0], kb + bofff[2*jp2]     + ksb);
                        ldsm4(k4[1], kb + bofff[2*jp2 + 1] + ksb);
                        #pragma unroll
                        for (int p = 0; p < 2; ++p)
                            #pragma unroll
                            for (int jj = 0; jj < 2; ++jj)
                                mma16816(s[(2*jp2+p)*2+jj], ah, k4[p] + jj*2);
                        #pragma unroll
                        for (int p = 0; p < 2; ++p)
                            #pragma unroll
                            for (int jj = 0; jj < 2; ++jj)
                                mma16816(s[(2*jp2+p)*2+jj], al, k4[p] + jj*2);
                    }
                }

                // ---- causal mask ----
                int row0 = q0 + r, row1 = row0 + 8;
                #pragma unroll
                for (int j = 0; j < 8; ++j) {
                    int cg = k0 + j*8 + qc*2;
                    if (cg     > row0) s[j][0] = -INFINITY;
                    if (cg + 1 > row0) s[j][1] = -INFINITY;
                    if (cg     > row1) s[j][2] = -INFINITY;
                    if (cg + 1 > row1) s[j][3] = -INFINITY;
                }

                // ---- online softmax (undropped denominator) ----
                float mx0 = -INFINITY, mx1 = -INFINITY;
                #pragma unroll
                for (int j = 0; j < 8; ++j) {
                    mx0 = fmaxf(mx0, fmaxf(s[j][0], s[j][1]));
                    mx1 = fmaxf(mx1, fmaxf(s[j][2], s[j][3]));
                }
                mx0 = fmaxf(mx0, __shfl_xor_sync(0xffffffffu, mx0, 1));
                mx0 = fmaxf(mx0, __shfl_xor_sync(0xffffffffu, mx0, 2));
                mx1 = fmaxf(mx1, __shfl_xor_sync(0xffffffffu, mx1, 1));
                mx1 = fmaxf(mx1, __shfl_xor_sync(0xffffffffu, mx1, 2));
                float m0n = fmaxf(m0, mx0), m1n = fmaxf(m1, mx1);
                float a0 = __expf(m0 - m0n), a1 = __expf(m1 - m1n);
                float sum0 = 0.f, sum1 = 0.f;
                #pragma unroll
                for (int j = 0; j < 8; ++j) {
                    float p0 = __expf(s[j][0] - m0n); sum0 += p0;
                    float p1 = __expf(s[j][1] - m0n); sum0 += p1;
                    float p2 = __expf(s[j][2] - m1n); sum1 += p2;
                    float p3 = __expf(s[j][3] - m1n); sum1 += p3;
                    s[j][0] = km0[j].x ? p0 * KEEP_INV : 0.f;
                    s[j][1] = km0[j].y ? p1 * KEEP_INV : 0.f;
                    s[j][2] = km1[j].x ? p2 * KEEP_INV : 0.f;
                    s[j][3] = km1[j].y ? p3 * KEEP_INV : 0.f;
                }
                sum0 += __shfl_xor_sync(0xffffffffu, sum0, 1);
                sum0 += __shfl_xor_sync(0xffffffffu, sum0, 2);
                sum1 += __shfl_xor_sync(0xffffffffu, sum1, 1);
                sum1 += __shfl_xor_sync(0xffffffffu, sum1, 2);
                l0 = l0 * a0 + sum0;
                l1 = l1 * a1 + sum1;
                m0 = m0n; m1 = m1n;

                // ---- acc scale + (Ph+Pl) V ----
                #pragma unroll
                for (int j = 0; j < 8; ++j) {
                    acc[j][0] *= a0; acc[j][1] *= a0;
                    acc[j][2] *= a1; acc[j][3] *= a1;
                }
                #pragma unroll
                for (int s4 = 0; s4 < 4; ++s4) {
                    uint32_t ph_[4], pl_[4];
                    split2h(s[2*s4][0],   s[2*s4][1],   ph_[0], pl_[0]);
                    split2h(s[2*s4][2],   s[2*s4][3],   ph_[1], pl_[1]);
                    split2h(s[2*s4+1][0], s[2*s4+1][1], ph_[2], pl_[2]);
                    split2h(s[2*s4+1][2], s[2*s4+1][3], ph_[3], pl_[3]);
                    uint32_t ksb = s4 * 32;
                    #pragma unroll
                    for (int jp2 = 0; jp2 < 2; ++jp2) {
                        uint32_t v4[2][4];
                        ldsm4(v4[0], vb + bofff[2*jp2]     + ksb);
                        ldsm4(v4[1], vb + bofff[2*jp2 + 1] + ksb);
                        #pragma unroll
                        for (int p = 0; p < 2; ++p)
                            #pragma unroll
                            for (int jj = 0; jj < 2; ++jj)
                                mma16816(acc[(2*jp2+p)*2+jj], ph_, v4[p] + jj*2);
                        #pragma unroll
                        for (int p = 0; p < 2; ++p)
                            #pragma unroll
                            for (int jj = 0; jj < 2; ++jj)
                                mma16816(acc[(2*jp2+p)*2+jj], pl_, v4[p] + jj*2);
                    }
                }
            }
            __syncthreads();
        }

        // ---- epilogue: y = acc / l, write split fp16 pair [tok][C] ----
        int b = bh >> 4, h = bh & 15;
        float inv0 = 1.f / l0, inv1 = 1.f / l1;
        size_t tok0 = (size_t)b*Tt + q0 + r;
        size_t tok1 = tok0 + 8;
        #pragma unroll
        for (int j = 0; j < 8; ++j) {
            int col = h*HD + j*8 + qc*2;
            uint32_t hi, lo;
            split2h(acc[j][0]*inv0, acc[j][1]*inv0, hi, lo);
            *(uint32_t*)&g_yh[tok0*Cc + col] = hi;
            *(uint32_t*)&g_yl[tok0*Cc + col] = lo;
            split2h(acc[j][2]*inv1, acc[j][3]*inv1, hi, lo);
            *(uint32_t*)&g_yh[tok1*Cc + col] = hi;
            *(uint32_t*)&g_yl[tok1*Cc + col] = lo;
        }
    }
}

// ---------------------------------------------------------------------------
extern "C" void kernel_launch(void* const* d_in, const int* in_sizes, int n_in,
                              void* d_out, int out_size) {
    const float* x     = (const float*)d_in[0];
    const float* Wqkv  = (const float*)d_in[1];
    const float* bqkv  = (const float*)d_in[2];
    const float* Wproj = (const float*)d_in[3];
    const float* bproj = (const float*)d_in[4];
    const unsigned* amask = (const unsigned*)d_in[5];
    const unsigned* rmask = (const unsigned*)d_in[6];
    float* out = (float*)d_out;

    cudaFuncSetAttribute(gemm_mma<0>, cudaFuncAttributeMaxDynamicSharedMemorySize, GEMM_SMEM);
    cudaFuncSetAttribute(gemm_mma<1>, cudaFuncAttributeMaxDynamicSharedMemorySize, GEMM_SMEM);
    cudaFuncSetAttribute(flash_mma, cudaFuncAttributeMaxDynamicSharedMemorySize, FLASH_SMEM);

    __half *xh, *xl, *wqh, *wph, *yh, *yl;
    cudaGetSymbolAddress((void**)&xh,  g_xh);  cudaGetSymbolAddress((void**)&xl,  g_xl);
    cudaGetSymbolAddress((void**)&wqh, g_wqh); cudaGetSymbolAddress((void**)&wph, g_wph);
    cudaGetSymbolAddress((void**)&yh,  g_yh);  cudaGetSymbolAddress((void**)&yl,  g_yl);

    cvt_split<<<(NTOK*Cc/4 + 255)/256, 256>>>((const float4*)x, (__half2*)xh, (__half2*)xl, NTOK*Cc/4);
    cvt_trunc_T<<<dim3(C3/32, Cc/32), dim3(32,8)>>>(Wqkv, wqh, Cc, C3);
    cvt_trunc_T<<<dim3(Cc/32, Cc/32), dim3(32,8)>>>(Wproj, wph, Cc, Cc);

    gemm_mma<0><<<dim3(C3/128, NTOK/128), 256, GEMM_SMEM>>>(xh, xl, wqh, bqkv, nullptr, nullptr, Cc);

    flash_mma<<<dim3(NQB/2, Bsz*Hh), 256, FLASH_SMEM>>>(amask);

    gemm_mma<1><<<dim3(Cc/128, NTOK/128), 256, GEMM_SMEM>>>(yh, yl, wph, bproj, rmask, out, Cc);
}

// round 13
// speedup vs baseline: 2.0539x; 1.1935x over previous
#include <cuda_runtime.h>
#include <cuda_fp16.h>
#include <math.h>
#include <cstdint>

// Problem constants
#define Bsz 2
#define Tt 2048
#define Cc 1024
#define Hh 16
#define HD 64
#define NTOK (Bsz*Tt)   // 4096
#define C3 (3*Cc)       // 3072
#define KEEP_INV (1.0f/0.9f)
#define NQB 16          // q-tiles of 128

// ---------------- scratch (device globals; no allocs allowed) ---------------
__device__ __half g_xh[(size_t)NTOK*Cc];                   // x truncated
__device__ __half g_wqh[(size_t)C3*Cc];                    // [N,K] transposed, truncated
__device__ __half g_wph[(size_t)Cc*Cc];                    // [N,K] transposed, truncated
__device__ __half g_yh[(size_t)NTOK*Cc], g_yl[(size_t)NTOK*Cc];
__device__ __half g_qh[(size_t)32*Tt*HD], g_ql[(size_t)32*Tt*HD];  // q split, scaled
__device__ __half g_kh[(size_t)32*Tt*HD];                  // k truncated
__device__ __half g_vth[(size_t)32*HD*Tt];                 // v transposed, truncated

// ---------------- helpers ----------------
__device__ __forceinline__ uint32_t smem_u32(const void* p) {
    uint32_t a;
    asm("{ .reg .u64 t; cvta.to.shared.u64 t, %1; cvt.u32.u64 %0, t; }" : "=r"(a) : "l"(p));
    return a;
}
__device__ __forceinline__ void cp_async16(uint32_t dst, const void* src) {
    asm volatile("cp.async.cg.shared.global [%0], [%1], 16;" :: "r"(dst), "l"(src) : "memory");
}
#define CP_COMMIT() asm volatile("cp.async.commit_group;" ::: "memory")
#define CP_WAIT(n)  asm volatile("cp.async.wait_group %0;" :: "n"(n) : "memory")

__device__ __forceinline__ void mma16816(float* c, const uint32_t* a, const uint32_t* b) {
    asm volatile("mma.sync.aligned.m16n8k16.row.col.f32.f16.f16.f32 "
        "{%0,%1,%2,%3}, {%4,%5,%6,%7}, {%8,%9}, {%0,%1,%2,%3};"
        : "+f"(c[0]), "+f"(c[1]), "+f"(c[2]), "+f"(c[3])
        : "r"(a[0]), "r"(a[1]), "r"(a[2]), "r"(a[3]), "r"(b[0]), "r"(b[1]));
}
__device__ __forceinline__ void ldsm4(uint32_t* r, uint32_t a) {
    asm volatile("ldmatrix.sync.aligned.m8n8.x4.shared.b16 {%0,%1,%2,%3}, [%4];"
        : "=r"(r[0]), "=r"(r[1]), "=r"(r[2]), "=r"(r[3]) : "r"(a));
}
// pack two floats into hi/lo fp16x2 (split)
__device__ __forceinline__ void split2h(float a, float b, uint32_t& hi, uint32_t& lo) {
    __half ha = __float2half_rn(a), hb = __float2half_rn(b);
    __half2 H(ha, hb);
    hi = *(uint32_t*)&H;
    __half2 L(__float2half_rn(a - __half2float(ha)),
              __float2half_rn(b - __half2float(hb)));
    lo = *(uint32_t*)&L;
}
__device__ __forceinline__ uint32_t pack2h(float a, float b) {
    __half2 H(__float2half_rn(a), __float2half_rn(b));
    return *(uint32_t*)&H;
}

// ---------------------------------------------------------------------------
// fp32 -> truncated fp16 (row-major passthrough)
// ---------------------------------------------------------------------------
__global__ __launch_bounds__(256) void cvt_trunc(const float4* __restrict__ in,
                                                 __half2* __restrict__ hi,
                                                 int n4) {
    int i = blockIdx.x * 256 + threadIdx.x;
    if (i >= n4) return;
    float4 v = in[i];
    hi[2*i]   = __half2(__float2half_rn(v.x), __float2half_rn(v.y));
    hi[2*i+1] = __half2(__float2half_rn(v.z), __float2half_rn(v.w));
}

// fp32 W[K,N] -> transposed truncated fp16 [N,K]
__global__ __launch_bounds__(256) void cvt_trunc_T(const float* __restrict__ in,
                                                   __half* __restrict__ hi,
                                                   int K, int N) {
    __shared__ float t[32][33];
    int nx = blockIdx.x * 32, kx = blockIdx.y * 32;
    int tx = threadIdx.x, ty = threadIdx.y;  // (32,8)
    #pragma unroll
    for (int r = 0; r < 4; ++r)
        t[ty + 8*r][tx] = in[(size_t)(kx + ty + 8*r) * N + nx + tx];
    __syncthreads();
    #pragma unroll
    for (int r = 0; r < 4; ++r)
        hi[(size_t)(nx + ty + 8*r) * K + kx + tx] = __float2half_rn(t[tx][ty + 8*r]);
}

// ---------------------------------------------------------------------------
// mma.sync fp16 GEMM, TERMS-term A: C = (Ah[+Al])[M,K] * Bt[N,K]^T
// 128x128 tile, K-chunk 64, 2-stage cp.async, ldmatrix.x4.
// MODE 0 (TERMS=1): qkv -> q split (scaled 1/8), k trunc, v smem-transpose.
// MODE 1 (TERMS=2): proj + resid dropout -> out (fp32).
// ---------------------------------------------------------------------------
#define SR 72                   // halves per row (64 + 8 pad) -> 144B stride
#define TILE_E (128*SR)
#define TILE_B (TILE_E*2)       // 18432 bytes
#define TSR 136                 // transpose smem stride in halves (272B)
#define GEMM_SMEM(T) (2*((T)+1)*TILE_B)   // T=1: 73728, T=2: 110592

template<int TERMS>
__device__ __forceinline__ void gemm_issue(uint32_t sb, int buf,
                                           const __half* Ah, const __half* Al,
                                           const __half* B,
                                           int m0, int n0, int K, int ch, int tid) {
    const int NT = TERMS + 1;
    #pragma unroll
    for (int it = 0; it < NT*4; ++it) {
        int u = tid + it * 256;           // 0..NT*1024-1
        int arr = u >> 10;                // 0..NT-1
        int rem = u & 1023;
        int row = rem >> 3;
        int c16 = rem & 7;                // 16B unit (8 halves)
        const __half* src = (arr == 0) ? Ah : (arr == TERMS) ? B : Al;
        int grow = (arr < TERMS ? m0 : n0) + row;
        uint32_t soff = (uint32_t)((buf * NT * TILE_E + arr * TILE_E + row * SR + c16 * 8) * 2);
        cp_async16(sb + soff, src + (size_t)grow * K + ch * 64 + c16 * 8);
    }
    CP_COMMIT();
}

template<int MODE, int TERMS>
__global__ __launch_bounds__(256, 2) void gemm_mma(const __half* __restrict__ Ah,
                                                   const __half* __restrict__ Al,
                                                   const __half* __restrict__ B,
                                                   const float* __restrict__ bias,
                                                   const unsigned* __restrict__ rmask,
                                                   float* __restrict__ out,
                                                   int K) {
    extern __shared__ __half smg[];
    const int NT = TERMS + 1;
    const int BUF_B_L = NT * TILE_B;
    uint32_t sb = smem_u32(smg);
    int tid = threadIdx.x, wid = tid >> 5, lane = tid & 31;
    int m0 = blockIdx.y * 128, n0 = blockIdx.x * 128;
    int wm = (wid & 3) * 32, wn = (wid >> 2) * 64;
    int qr = lane >> 2, qc = lane & 3;
    int g = lane >> 3, lr = lane & 7;

    uint32_t aoff[2], boff[4];
    #pragma unroll
    for (int i = 0; i < 2; ++i)
        aoff[i] = (uint32_t)(((wm + i*16 + lr + (g & 1)*8) * SR + (g >> 1)*8) * 2);
    #pragma unroll
    for (int jp = 0; jp < 4; ++jp)
        boff[jp] = (uint32_t)(((wn + jp*16 + lr + (g >> 1)*8) * SR + (g & 1)*8) * 2);

    float acc[2][8][4] = {};
    int nch = K >> 6;

    gemm_issue<TERMS>(sb, 0, Ah, Al, B, m0, n0, K, 0, tid);

    for (int ch = 0; ch < nch; ++ch) {
        int buf = ch & 1;
        if (ch + 1 < nch) {
            gemm_issue<TERMS>(sb, buf ^ 1, Ah, Al, B, m0, n0, K, ch + 1, tid);
            CP_WAIT(1);
        } else {
            CP_WAIT(0);
        }
        __syncthreads();

        uint32_t bAh = sb + buf * BUF_B_L;
        uint32_t bAl = bAh + TILE_B;                 // valid only if TERMS==2
        uint32_t bB  = bAh + TERMS*TILE_B;

        #pragma unroll
        for (int ks = 0; ks < 4; ++ks) {
            uint32_t ksb = ks * 32;
            uint32_t ah[2][4], al[2][4];
            ldsm4(ah[0], bAh + aoff[0] + ksb);
            ldsm4(ah[1], bAh + aoff[1] + ksb);
            if (TERMS == 2) {
                ldsm4(al[0], bAl + aoff[0] + ksb);
                ldsm4(al[1], bAl + aoff[1] + ksb);
            }
            #pragma unroll
            for (int jp2 = 0; jp2 < 2; ++jp2) {
                uint32_t b4[2][4];
                ldsm4(b4[0], bB + boff[2*jp2]     + ksb);
                ldsm4(b4[1], bB + boff[2*jp2 + 1] + ksb);
                #pragma unroll
                for (int p = 0; p < 2; ++p)
                    #pragma unroll
                    for (int jj = 0; jj < 2; ++jj)
                        #pragma unroll
                        for (int i = 0; i < 2; ++i)
                            mma16816(acc[i][(2*jp2+p)*2+jj], ah[i], b4[p] + jj*2);
                if (TERMS == 2) {
                    #pragma unroll
                    for (int p = 0; p < 2; ++p)
                        #pragma unroll
                        for (int jj = 0; jj < 2; ++jj)
                            #pragma unroll
                            for (int i = 0; i < 2; ++i)
                                mma16816(acc[i][(2*jp2+p)*2+jj], al[i], b4[p] + jj*2);
                }
            }
        }
        __syncthreads();
    }

    if (MODE == 0 && n0 >= 2*Cc) {
        // ---- V block: smem-bounce transpose, coalesced [d][t] store ----
        #pragma unroll
        for (int i = 0; i < 2; ++i) {
            #pragma unroll
            for (int j = 0; j < 8; ++j) {
                int col0 = wn + j*8 + qc*2;
                float b0 = bias[n0 + col0], b1 = bias[n0 + col0 + 1];
                #pragma unroll
                for (int hrow = 0; hrow < 2; ++hrow) {
                    int rowl = wm + i*16 + qr + hrow*8;
                    smg[col0*TSR + rowl]     = __float2half_rn(acc[i][j][hrow*2+0] + b0);
                    smg[(col0+1)*TSR + rowl] = __float2half_rn(acc[i][j][hrow*2+1] + b1);
                }
            }
        }
        __syncthreads();
        int t0 = m0 & (Tt - 1);
        int b  = m0 >> 11;
        #pragma unroll
        for (int it = 0; it < 8; ++it) {
            int u = tid + it * 256;       // 0..2047
            int col = u >> 4, c8 = u & 15;
            uint4 val = *(uint4*)&smg[col*TSR + c8*8];
            int vcol = (n0 - 2*Cc) + col;
            int h = vcol >> 6, dd = vcol & 63;
            int bh = b*Hh + h;
            *(uint4*)&g_vth[((size_t)bh*HD + dd)*Tt + t0 + c8*8] = val;
        }
        return;
    }

    // Epilogue (q, k, proj)
    #pragma unroll
    for (int i = 0; i < 2; ++i) {
        int R0 = m0 + wm + i * 16 + qr;
        #pragma unroll
        for (int j = 0; j < 8; ++j) {
            int C0 = n0 + wn + j * 8 + qc * 2;
            float b0 = bias[C0], b1 = bias[C0 + 1];
            #pragma unroll
            for (int hrow = 0; hrow < 2; ++hrow) {
                int m = R0 + hrow * 8;
                float v0 = acc[i][j][hrow*2 + 0] + b0;
                float v1 = acc[i][j][hrow*2 + 1] + b1;
                if (MODE == 0) {
                    int bb = m >> 11, t = m & (Tt - 1);
                    int which = C0 >> 10, cidx = C0 & 1023;
                    int h = cidx >> 6, dd = cidx & 63;
                    int bh = bb * Hh + h;
                    if (which == 0) {
                        uint32_t hi, lo;
                        split2h(v0 * 0.125f, v1 * 0.125f, hi, lo);
                        size_t o = ((size_t)bh*Tt + t)*HD + dd;
                        *(uint32_t*)&g_qh[o] = hi;
                        *(uint32_t*)&g_ql[o] = lo;
                    } else {
                        size_t o = ((size_t)bh*Tt + t)*HD + dd;
                        *(uint32_t*)&g_kh[o] = pack2h(v0, v1);
                    }
                } else {
                    size_t idx = (size_t)m * Cc + C0;
                    out[idx]     = rmask[idx]     ? v0 * KEEP_INV : 0.f;
                    out[idx + 1] = rmask[idx + 1] ? v1 * KEEP_INV : 0.f;
                }
            }
        }
    }
}

// ---------------------------------------------------------------------------
// Flash attention, fp16 2-term, 128-wide k-tiles, PAIRED q-tiles per CTA
// (qb = NQB-1-bx then bx): every CTA does exactly 17 tile-units; one wave.
// ---------------------------------------------------------------------------
#define SRK 72                       // fp16 row stride for 64-col tiles
#define OQH 0
#define OQL (128*SRK*2)              // 18432
#define OB0 (2*128*SRK*2)            // 36864
#define KVB (64*SRK*2)               // 9216
#define BUFB (4*KVB)                 // 36864 : [K0,V0,K1,V1]
#define FLASH_SMEM (OB0 + 2*BUFB)    // 110592

__device__ __forceinline__ void flash_issue(uint32_t sb, int buf,
                                            int bh, int k0, int tid) {
    // K: 128 rows x 64 halves (two 64-row subtiles)
    #pragma unroll
    for (int it = 0; it < 4; ++it) {
        int u = tid + it * 256;           // 0..1023
        int row = u >> 3, ck = u & 7;
        int half = row >> 6, lr_ = row & 63;
        uint32_t dst = sb + OB0 + buf*BUFB + (2*half)*KVB + (uint32_t)(lr_*SRK + ck*8)*2;
        cp_async16(dst, g_kh + ((size_t)bh*Tt + k0 + row)*HD + ck*8);
    }
    // V: 64 d-rows x 128 t (two 64-t subtiles)
    #pragma unroll
    for (int it = 0; it < 4; ++it) {
        int u = tid + it * 256;
        int d = u >> 4, ct = u & 15;
        int thalf = ct >> 3, tc = ct & 7;
        uint32_t dst = sb + OB0 + buf*BUFB + (2*thalf+1)*KVB + (uint32_t)(d*SRK + tc*8)*2;
        cp_async16(dst, g_vth + ((size_t)bh*HD + d)*Tt + k0 + ct*8);
    }
    CP_COMMIT();
}

__global__ __launch_bounds__(256, 2) void flash_mma(const unsigned* __restrict__ amask) {
    extern __shared__ char smf[];
    uint32_t sb = smem_u32(smf);
    int tid = threadIdx.x, wid = tid >> 5, lane = tid & 31;
    int qr = lane >> 2, qc = lane & 3;
    int g = lane >> 3, lr = lane & 7;
    int bh = blockIdx.y;

    uint32_t qaoff = (uint32_t)(((wid*16 + lr + (g & 1)*8) * SRK + (g >> 1)*8) * 2);
    uint32_t bofff[4];
    #pragma unroll
    for (int jp = 0; jp < 4; ++jp)
        bofff[jp] = (uint32_t)(((jp*16 + lr + (g >> 1)*8) * SRK + (g & 1)*8) * 2);

    int r = wid * 16 + qr;                  // q row within tile

    for (int ph = 0; ph < 2; ++ph) {
        int qb = ph ? (int)blockIdx.x : (NQB - 1 - (int)blockIdx.x);
        int q0 = qb * 128;
        int nkt = qb + 1;                   // 128-wide tiles
        int rowmax = q0 + wid * 16 + 15;
        const unsigned* mrow0 = amask + ((size_t)bh*Tt + q0 + r)*Tt + qc*2;
        const unsigned* mrow1 = mrow0 + (size_t)8*Tt;

        // Q pair tile load — same cp.async group as tile 0
        #pragma unroll
        for (int it = 0; it < 8; ++it) {
            int u = tid + it * 256;
            int arr = u >> 10;
            int rem = u & 1023;
            int row = rem >> 3;
            int ck = rem & 7;
            const __half* src = arr ? g_ql : g_qh;
            uint32_t dst = sb + (arr ? OQL : OQH) + (uint32_t)(row*SRK + ck*8)*2;
            cp_async16(dst, src + ((size_t)bh*Tt + q0 + row)*HD + ck*8);
        }
        flash_issue(sb, 0, bh, 0, tid);

        float acc[8][4] = {};
        float m0 = -INFINITY, m1 = -INFINITY, l0 = 0.f, l1 = 0.f;

        for (int kt = 0; kt < nkt; ++kt) {
            int buf = kt & 1;
            if (kt + 1 < nkt) {
                flash_issue(sb, buf ^ 1, bh, (kt+1)*128, tid);
                CP_WAIT(1);
            } else {
                CP_WAIT(0);
            }
            __syncthreads();

            #pragma unroll
            for (int half = 0; half < 2; ++half) {
                int k0 = kt * 128 + half * 64;
                if (k0 > rowmax) continue;
                uint32_t kb = sb + OB0 + buf*BUFB + (2*half)*KVB;
                uint32_t vb = kb + KVB;

                // ---- mask prefetch (gmem -> regs), consumed at softmax ----
                uint2 km0[8], km1[8];
                #pragma unroll
                for (int j = 0; j < 8; ++j) {
                    km0[j] = *(const uint2*)(mrow0 + k0 + j*8);
                    km1[j] = *(const uint2*)(mrow1 + k0 + j*8);
                }

                // ---- S = (Qh+Ql) K^T ----
                float s[8][4] = {};
                #pragma unroll
                for (int ks = 0; ks < 4; ++ks) {
                    uint32_t ksb = ks * 32;
                    uint32_t ah[4], al[4];
                    ldsm4(ah, sb + OQH + qaoff + ksb);
                    ldsm4(al, sb + OQL + qaoff + ksb);
                    #pragma unroll
                    for (int jp2 = 0; jp2 < 2; ++jp2) {
                        uint32_t k4[2][4];
                        ldsm4(k4[0], kb + bofff[2*jp2]     + ksb);
                        ldsm4(k4[1], kb + bofff[2*jp2 + 1] + ksb);
                        #pragma unroll
                        for (int p = 0; p < 2; ++p)
                            #pragma unroll
                            for (int jj = 0; jj < 2; ++jj)
                                mma16816(s[(2*jp2+p)*2+jj], ah, k4[p] + jj*2);
                        #pragma unroll
                        for (int p = 0; p < 2; ++p)
                            #pragma unroll
                            for (int jj = 0; jj < 2; ++jj)
                                mma16816(s[(2*jp2+p)*2+jj], al, k4[p] + jj*2);
                    }
                }

                // ---- causal mask ----
                int row0 = q0 + r, row1 = row0 + 8;
                #pragma unroll
                for (int j = 0; j < 8; ++j) {
                    int cg = k0 + j*8 + qc*2;
                    if (cg     > row0) s[j][0] = -INFINITY;
                    if (cg + 1 > row0) s[j][1] = -INFINITY;
                    if (cg     > row1) s[j][2] = -INFINITY;
                    if (cg + 1 > row1) s[j][3] = -INFINITY;
                }

                // ---- online softmax (undropped denominator) ----
                float mx0 = -INFINITY, mx1 = -INFINITY;
                #pragma unroll
                for (int j = 0; j < 8; ++j) {
                    mx0 = fmaxf(mx0, fmaxf(s[j][0], s[j][1]));
                    mx1 = fmaxf(mx1, fmaxf(s[j][2], s[j][3]));
                }
                mx0 = fmaxf(mx0, __shfl_xor_sync(0xffffffffu, mx0, 1));
                mx0 = fmaxf(mx0, __shfl_xor_sync(0xffffffffu, mx0, 2));
                mx1 = fmaxf(mx1, __shfl_xor_sync(0xffffffffu, mx1, 1));
                mx1 = fmaxf(mx1, __shfl_xor_sync(0xffffffffu, mx1, 2));
                float m0n = fmaxf(m0, mx0), m1n = fmaxf(m1, mx1);
                float a0 = __expf(m0 - m0n), a1 = __expf(m1 - m1n);
                float sum0 = 0.f, sum1 = 0.f;
                #pragma unroll
                for (int j = 0; j < 8; ++j) {
                    float p0 = __expf(s[j][0] - m0n); sum0 += p0;
                    float p1 = __expf(s[j][1] - m0n); sum0 += p1;
                    float p2 = __expf(s[j][2] - m1n); sum1 += p2;
                    float p3 = __expf(s[j][3] - m1n); sum1 += p3;
                    s[j][0] = km0[j].x ? p0 * KEEP_INV : 0.f;
                    s[j][1] = km0[j].y ? p1 * KEEP_INV : 0.f;
                    s[j][2] = km1[j].x ? p2 * KEEP_INV : 0.f;
                    s[j][3] = km1[j].y ? p3 * KEEP_INV : 0.f;
                }
                sum0 += __shfl_xor_sync(0xffffffffu, sum0, 1);
                sum0 += __shfl_xor_sync(0xffffffffu, sum0, 2);
                sum1 += __shfl_xor_sync(0xffffffffu, sum1, 1);
                sum1 += __shfl_xor_sync(0xffffffffu, sum1, 2);
                l0 = l0 * a0 + sum0;
                l1 = l1 * a1 + sum1;
                m0 = m0n; m1 = m1n;

                // ---- acc scale + (Ph+Pl) V ----
                #pragma unroll
                for (int j = 0; j < 8; ++j) {
                    acc[j][0] *= a0; acc[j][1] *= a0;
                    acc[j][2] *= a1; acc[j][3] *= a1;
                }
                #pragma unroll
                for (int s4 = 0; s4 < 4; ++s4) {
                    uint32_t ph_[4], pl_[4];
                    split2h(s[2*s4][0],   s[2*s4][1],   ph_[0], pl_[0]);
                    split2h(s[2*s4][2],   s[2*s4][3],   ph_[1], pl_[1]);
                    split2h(s[2*s4+1][0], s[2*s4+1][1], ph_[2], pl_[2]);
                    split2h(s[2*s4+1][2], s[2*s4+1][3], ph_[3], pl_[3]);
                    uint32_t ksb = s4 * 32;
                    #pragma unroll
                    for (int jp2 = 0; jp2 < 2; ++jp2) {
                        uint32_t v4[2][4];
                        ldsm4(v4[0], vb + bofff[2*jp2]     + ksb);
                        ldsm4(v4[1], vb + bofff[2*jp2 + 1] + ksb);
                        #pragma unroll
                        for (int p = 0; p < 2; ++p)
                            #pragma unroll
                            for (int jj = 0; jj < 2; ++jj)
                                mma16816(acc[(2*jp2+p)*2+jj], ph_, v4[p] + jj*2);
                        #pragma unroll
                        for (int p = 0; p < 2; ++p)
                            #pragma unroll
                            for (int jj = 0; jj < 2; ++jj)
                                mma16816(acc[(2*jp2+p)*2+jj], pl_, v4[p] + jj*2);
                    }
                }
            }
            __syncthreads();
        }

        // ---- epilogue: y = acc / l, write split fp16 pair [tok][C] ----
        int b = bh >> 4, h = bh & 15;
        float inv0 = 1.f / l0, inv1 = 1.f / l1;
        size_t tok0 = (size_t)b*Tt + q0 + r;
        size_t tok1 = tok0 + 8;
        #pragma unroll
        for (int j = 0; j < 8; ++j) {
            int col = h*HD + j*8 + qc*2;
            uint32_t hi, lo;
            split2h(acc[j][0]*inv0, acc[j][1]*inv0, hi, lo);
            *(uint32_t*)&g_yh[tok0*Cc + col] = hi;
            *(uint32_t*)&g_yl[tok0*Cc + col] = lo;
            split2h(acc[j][2]*inv1, acc[j][3]*inv1, hi, lo);
            *(uint32_t*)&g_yh[tok1*Cc + col] = hi;
            *(uint32_t*)&g_yl[tok1*Cc + col] = lo;
        }
    }
}

// ---------------------------------------------------------------------------
extern "C" void kernel_launch(void* const* d_in, const int* in_sizes, int n_in,
                              void* d_out, int out_size) {
    const float* x     = (const float*)d_in[0];
    const float* Wqkv  = (const float*)d_in[1];
    const float* bqkv  = (const float*)d_in[2];
    const float* Wproj = (const float*)d_in[3];
    const float* bproj = (const float*)d_in[4];
    const unsigned* amask = (const unsigned*)d_in[5];
    const unsigned* rmask = (const unsigned*)d_in[6];
    float* out = (float*)d_out;

    cudaFuncSetAttribute(gemm_mma<0,1>, cudaFuncAttributeMaxDynamicSharedMemorySize, GEMM_SMEM(1));
    cudaFuncSetAttribute(gemm_mma<1,2>, cudaFuncAttributeMaxDynamicSharedMemorySize, GEMM_SMEM(2));
    cudaFuncSetAttribute(flash_mma, cudaFuncAttributeMaxDynamicSharedMemorySize, FLASH_SMEM);

    __half *xh, *wqh, *wph, *yh, *yl;
    cudaGetSymbolAddress((void**)&xh,  g_xh);
    cudaGetSymbolAddress((void**)&wqh, g_wqh); cudaGetSymbolAddress((void**)&wph, g_wph);
    cudaGetSymbolAddress((void**)&yh,  g_yh);  cudaGetSymbolAddress((void**)&yl,  g_yl);

    cvt_trunc<<<(NTOK*Cc/4 + 255)/256, 256>>>((const float4*)x, (__half2*)xh, NTOK*Cc/4);
    cvt_trunc_T<<<dim3(C3/32, Cc/32), dim3(32,8)>>>(Wqkv, wqh, Cc, C3);
    cvt_trunc_T<<<dim3(Cc/32, Cc/32), dim3(32,8)>>>(Wproj, wph, Cc, Cc);

    gemm_mma<0,1><<<dim3(C3/128, NTOK/128), 256, GEMM_SMEM(1)>>>(xh, nullptr, wqh, bqkv, nullptr, nullptr, Cc);

    flash_mma<<<dim3(NQB/2, Bsz*Hh), 256, FLASH_SMEM>>>(amask);

    gemm_mma<1,2><<<dim3(Cc/128, NTOK/128), 256, GEMM_SMEM(2)>>>(yh, yl, wph, bproj, rmask, out, Cc);
}

// round 14
// speedup vs baseline: 2.3798x; 1.1587x over previous
#include <cuda_runtime.h>
#include <cuda_fp16.h>
#include <math.h>
#include <cstdint>

// Problem constants
#define Bsz 2
#define Tt 2048
#define Cc 1024
#define Hh 16
#define HD 64
#define NTOK (Bsz*Tt)   // 4096
#define C3 (3*Cc)       // 3072
#define KEEP_INV (1.0f/0.9f)
#define NQB 16          // q-tiles of 128

// ---------------- scratch (device globals; no allocs allowed) ---------------
__device__ __half g_xh[(size_t)NTOK*Cc];                   // x truncated
__device__ __half g_wqh[(size_t)C3*Cc];                    // [N,K] transposed, truncated
__device__ __half g_wph[(size_t)Cc*Cc];                    // [N,K] transposed, truncated
__device__ __half g_yh[(size_t)NTOK*Cc];                   // attention out, truncated
__device__ __half g_qh[(size_t)32*Tt*HD], g_ql[(size_t)32*Tt*HD];  // q split, scaled
__device__ __half g_kh[(size_t)32*Tt*HD];                  // k truncated
__device__ __half g_vth[(size_t)32*HD*Tt];                 // v transposed, truncated

// ---------------- helpers ----------------
__device__ __forceinline__ uint32_t smem_u32(const void* p) {
    uint32_t a;
    asm("{ .reg .u64 t; cvta.to.shared.u64 t, %1; cvt.u32.u64 %0, t; }" : "=r"(a) : "l"(p));
    return a;
}
__device__ __forceinline__ void cp_async16(uint32_t dst, const void* src) {
    asm volatile("cp.async.cg.shared.global [%0], [%1], 16;" :: "r"(dst), "l"(src) : "memory");
}
#define CP_COMMIT() asm volatile("cp.async.commit_group;" ::: "memory")
#define CP_WAIT(n)  asm volatile("cp.async.wait_group %0;" :: "n"(n) : "memory")

__device__ __forceinline__ void mma16816(float* c, const uint32_t* a, const uint32_t* b) {
    asm volatile("mma.sync.aligned.m16n8k16.row.col.f32.f16.f16.f32 "
        "{%0,%1,%2,%3}, {%4,%5,%6,%7}, {%8,%9}, {%0,%1,%2,%3};"
        : "+f"(c[0]), "+f"(c[1]), "+f"(c[2]), "+f"(c[3])
        : "r"(a[0]), "r"(a[1]), "r"(a[2]), "r"(a[3]), "r"(b[0]), "r"(b[1]));
}
__device__ __forceinline__ void ldsm4(uint32_t* r, uint32_t a) {
    asm volatile("ldmatrix.sync.aligned.m8n8.x4.shared.b16 {%0,%1,%2,%3}, [%4];"
        : "=r"(r[0]), "=r"(r[1]), "=r"(r[2]), "=r"(r[3]) : "r"(a));
}
// pack two floats into hi/lo fp16x2 (split)
__device__ __forceinline__ void split2h(float a, float b, uint32_t& hi, uint32_t& lo) {
    __half ha = __float2half_rn(a), hb = __float2half_rn(b);
    __half2 H(ha, hb);
    hi = *(uint32_t*)&H;
    __half2 L(__float2half_rn(a - __half2float(ha)),
              __float2half_rn(b - __half2float(hb)));
    lo = *(uint32_t*)&L;
}
__device__ __forceinline__ uint32_t pack2h(float a, float b) {
    __half2 H(__float2half_rn(a), __float2half_rn(b));
    return *(uint32_t*)&H;
}

// ---------------------------------------------------------------------------
// fp32 -> truncated fp16 (row-major passthrough)
// ---------------------------------------------------------------------------
__global__ __launch_bounds__(256) void cvt_trunc(const float4* __restrict__ in,
                                                 __half2* __restrict__ hi,
                                                 int n4) {
    int i = blockIdx.x * 256 + threadIdx.x;
    if (i >= n4) return;
    float4 v = in[i];
    hi[2*i]   = __half2(__float2half_rn(v.x), __float2half_rn(v.y));
    hi[2*i+1] = __half2(__float2half_rn(v.z), __float2half_rn(v.w));
}

// fp32 W[K,N] -> transposed truncated fp16 [N,K]
__global__ __launch_bounds__(256) void cvt_trunc_T(const float* __restrict__ in,
                                                   __half* __restrict__ hi,
                                                   int K, int N) {
    __shared__ float t[32][33];
    int nx = blockIdx.x * 32, kx = blockIdx.y * 32;
    int tx = threadIdx.x, ty = threadIdx.y;  // (32,8)
    #pragma unroll
    for (int r = 0; r < 4; ++r)
        t[ty + 8*r][tx] = in[(size_t)(kx + ty + 8*r) * N + nx + tx];
    __syncthreads();
    #pragma unroll
    for (int r = 0; r < 4; ++r)
        hi[(size_t)(nx + ty + 8*r) * K + kx + tx] = __float2half_rn(t[tx][ty + 8*r]);
}

// ---------------------------------------------------------------------------
// mma.sync fp16 single-term GEMM: C = A[M,K] * Bt[N,K]^T (+bias, +epilogue)
// 128x128 tile, K-chunk 64, 2-stage cp.async, ldmatrix.x4. 72KB smem.
// MODE 0: qkv -> q split (scaled 1/8), k trunc, v smem-transpose.
// MODE 1: proj + resid dropout -> out (fp32).
// ---------------------------------------------------------------------------
#define SR 72                   // halves per row (64 + 8 pad) -> 144B stride
#define TILE_E (128*SR)
#define TILE_B (TILE_E*2)       // 18432 bytes
#define TSR 136                 // transpose smem stride in halves (272B)
#define GEMM_SMEM (4*TILE_B)    // 73728

__device__ __forceinline__ void gemm_issue(uint32_t sb, int buf,
                                           const __half* A, const __half* B,
                                           int m0, int n0, int K, int ch, int tid) {
    #pragma unroll
    for (int it = 0; it < 8; ++it) {
        int u = tid + it * 256;           // 0..2047
        int arr = u >> 10;                // 0..1
        int rem = u & 1023;
        int row = rem >> 3;
        int c16 = rem & 7;                // 16B unit (8 halves)
        const __half* src = (arr == 0) ? A : B;
        int grow = (arr == 0 ? m0 : n0) + row;
        uint32_t soff = (uint32_t)((buf * 2 * TILE_E + arr * TILE_E + row * SR + c16 * 8) * 2);
        cp_async16(sb + soff, src + (size_t)grow * K + ch * 64 + c16 * 8);
    }
    CP_COMMIT();
}

template<int MODE>
__global__ __launch_bounds__(256, 2) void gemm_mma(const __half* __restrict__ A,
                                                   const __half* __restrict__ B,
                                                   const float* __restrict__ bias,
                                                   const unsigned* __restrict__ rmask,
                                                   float* __restrict__ out,
                                                   int K) {
    extern __shared__ __half smg[];
    uint32_t sb = smem_u32(smg);
    int tid = threadIdx.x, wid = tid >> 5, lane = tid & 31;
    int m0 = blockIdx.y * 128, n0 = blockIdx.x * 128;
    int wm = (wid & 3) * 32, wn = (wid >> 2) * 64;
    int qr = lane >> 2, qc = lane & 3;
    int g = lane >> 3, lr = lane & 7;

    uint32_t aoff[2], boff[4];
    #pragma unroll
    for (int i = 0; i < 2; ++i)
        aoff[i] = (uint32_t)(((wm + i*16 + lr + (g & 1)*8) * SR + (g >> 1)*8) * 2);
    #pragma unroll
    for (int jp = 0; jp < 4; ++jp)
        boff[jp] = (uint32_t)(((wn + jp*16 + lr + (g >> 1)*8) * SR + (g & 1)*8) * 2);

    float acc[2][8][4] = {};
    int nch = K >> 6;

    gemm_issue(sb, 0, A, B, m0, n0, K, 0, tid);

    for (int ch = 0; ch < nch; ++ch) {
        int buf = ch & 1;
        if (ch + 1 < nch) {
            gemm_issue(sb, buf ^ 1, A, B, m0, n0, K, ch + 1, tid);
            CP_WAIT(1);
        } else {
            CP_WAIT(0);
        }
        __syncthreads();

        uint32_t bA = sb + buf * 2 * TILE_B;
        uint32_t bB = bA + TILE_B;

        #pragma unroll
        for (int ks = 0; ks < 4; ++ks) {
            uint32_t ksb = ks * 32;
            uint32_t a4[2][4];
            ldsm4(a4[0], bA + aoff[0] + ksb);
            ldsm4(a4[1], bA + aoff[1] + ksb);
            #pragma unroll
            for (int jp2 = 0; jp2 < 2; ++jp2) {
                uint32_t b4[2][4];
                ldsm4(b4[0], bB + boff[2*jp2]     + ksb);
                ldsm4(b4[1], bB + boff[2*jp2 + 1] + ksb);
                #pragma unroll
                for (int p = 0; p < 2; ++p)
                    #pragma unroll
                    for (int jj = 0; jj < 2; ++jj)
                        #pragma unroll
                        for (int i = 0; i < 2; ++i)
                            mma16816(acc[i][(2*jp2+p)*2+jj], a4[i], b4[p] + jj*2);
            }
        }
        __syncthreads();
    }

    if (MODE == 0 && n0 >= 2*Cc) {
        // ---- V block: smem-bounce transpose, coalesced [d][t] store ----
        #pragma unroll
        for (int i = 0; i < 2; ++i) {
            #pragma unroll
            for (int j = 0; j < 8; ++j) {
                int col0 = wn + j*8 + qc*2;
                float b0 = bias[n0 + col0], b1 = bias[n0 + col0 + 1];
                #pragma unroll
                for (int hrow = 0; hrow < 2; ++hrow) {
                    int rowl = wm + i*16 + qr + hrow*8;
                    smg[col0*TSR + rowl]     = __float2half_rn(acc[i][j][hrow*2+0] + b0);
                    smg[(col0+1)*TSR + rowl] = __float2half_rn(acc[i][j][hrow*2+1] + b1);
                }
            }
        }
        __syncthreads();
        int t0 = m0 & (Tt - 1);
        int b  = m0 >> 11;
        #pragma unroll
        for (int it = 0; it < 8; ++it) {
            int u = tid + it * 256;       // 0..2047
            int col = u >> 4, c8 = u & 15;
            uint4 val = *(uint4*)&smg[col*TSR + c8*8];
            int vcol = (n0 - 2*Cc) + col;
            int h = vcol >> 6, dd = vcol & 63;
            int bh = b*Hh + h;
            *(uint4*)&g_vth[((size_t)bh*HD + dd)*Tt + t0 + c8*8] = val;
        }
        return;
    }

    // Epilogue (q, k, proj)
    #pragma unroll
    for (int i = 0; i < 2; ++i) {
        int R0 = m0 + wm + i * 16 + qr;
        #pragma unroll
        for (int j = 0; j < 8; ++j) {
            int C0 = n0 + wn + j * 8 + qc * 2;
            float b0 = bias[C0], b1 = bias[C0 + 1];
            #pragma unroll
            for (int hrow = 0; hrow < 2; ++hrow) {
                int m = R0 + hrow * 8;
                float v0 = acc[i][j][hrow*2 + 0] + b0;
                float v1 = acc[i][j][hrow*2 + 1] + b1;
                if (MODE == 0) {
                    int bb = m >> 11, t = m & (Tt - 1);
                    int which = C0 >> 10, cidx = C0 & 1023;
                    int h = cidx >> 6, dd = cidx & 63;
                    int bh = bb * Hh + h;
                    if (which == 0) {
                        uint32_t hi, lo;
                        split2h(v0 * 0.125f, v1 * 0.125f, hi, lo);
                        size_t o = ((size_t)bh*Tt + t)*HD + dd;
                        *(uint32_t*)&g_qh[o] = hi;
                        *(uint32_t*)&g_ql[o] = lo;
                    } else {
                        size_t o = ((size_t)bh*Tt + t)*HD + dd;
                        *(uint32_t*)&g_kh[o] = pack2h(v0, v1);
                    }
                } else {
                    size_t idx = (size_t)m * Cc + C0;
                    out[idx]     = rmask[idx]     ? v0 * KEEP_INV : 0.f;
                    out[idx + 1] = rmask[idx + 1] ? v1 * KEEP_INV : 0.f;
                }
            }
        }
    }
}

// ---------------------------------------------------------------------------
// Flash attention: QK 2-term (Qh+Ql)*K, PV single-term P*V.
// 128-wide k-tiles, PAIRED q-tiles per CTA (qb = NQB-1-bx then bx):
// every CTA does exactly 17 tile-units; one balanced wave.
// ---------------------------------------------------------------------------
#define SRK 72                       // fp16 row stride for 64-col tiles
#define OQH 0
#define OQL (128*SRK*2)              // 18432
#define OB0 (2*128*SRK*2)            // 36864
#define KVB (64*SRK*2)               // 9216
#define BUFB (4*KVB)                 // 36864 : [K0,V0,K1,V1]
#define FLASH_SMEM (OB0 + 2*BUFB)    // 110592

__device__ __forceinline__ void flash_issue(uint32_t sb, int buf,
                                            int bh, int k0, int tid) {
    // K: 128 rows x 64 halves (two 64-row subtiles)
    #pragma unroll
    for (int it = 0; it < 4; ++it) {
        int u = tid + it * 256;           // 0..1023
        int row = u >> 3, ck = u & 7;
        int half = row >> 6, lr_ = row & 63;
        uint32_t dst = sb + OB0 + buf*BUFB + (2*half)*KVB + (uint32_t)(lr_*SRK + ck*8)*2;
        cp_async16(dst, g_kh + ((size_t)bh*Tt + k0 + row)*HD + ck*8);
    }
    // V: 64 d-rows x 128 t (two 64-t subtiles)
    #pragma unroll
    for (int it = 0; it < 4; ++it) {
        int u = tid + it * 256;
        int d = u >> 4, ct = u & 15;
        int thalf = ct >> 3, tc = ct & 7;
        uint32_t dst = sb + OB0 + buf*BUFB + (2*thalf+1)*KVB + (uint32_t)(d*SRK + tc*8)*2;
        cp_async16(dst, g_vth + ((size_t)bh*HD + d)*Tt + k0 + ct*8);
    }
    CP_COMMIT();
}

__global__ __launch_bounds__(256, 2) void flash_mma(const unsigned* __restrict__ amask) {
    extern __shared__ char smf[];
    uint32_t sb = smem_u32(smf);
    int tid = threadIdx.x, wid = tid >> 5, lane = tid & 31;
    int qr = lane >> 2, qc = lane & 3;
    int g = lane >> 3, lr = lane & 7;
    int bh = blockIdx.y;

    uint32_t qaoff = (uint32_t)(((wid*16 + lr + (g & 1)*8) * SRK + (g >> 1)*8) * 2);
    uint32_t bofff[4];
    #pragma unroll
    for (int jp = 0; jp < 4; ++jp)
        bofff[jp] = (uint32_t)(((jp*16 + lr + (g >> 1)*8) * SRK + (g & 1)*8) * 2);

    int r = wid * 16 + qr;                  // q row within tile

    for (int ph = 0; ph < 2; ++ph) {
        int qb = ph ? (int)blockIdx.x : (NQB - 1 - (int)blockIdx.x);
        int q0 = qb * 128;
        int nkt = qb + 1;                   // 128-wide tiles
        int rowmax = q0 + wid * 16 + 15;
        const unsigned* mrow0 = amask + ((size_t)bh*Tt + q0 + r)*Tt + qc*2;
        const unsigned* mrow1 = mrow0 + (size_t)8*Tt;

        // Q pair tile load — same cp.async group as tile 0
        #pragma unroll
        for (int it = 0; it < 8; ++it) {
            int u = tid + it * 256;
            int arr = u >> 10;
            int rem = u & 1023;
            int row = rem >> 3;
            int ck = rem & 7;
            const __half* src = arr ? g_ql : g_qh;
            uint32_t dst = sb + (arr ? OQL : OQH) + (uint32_t)(row*SRK + ck*8)*2;
            cp_async16(dst, src + ((size_t)bh*Tt + q0 + row)*HD + ck*8);
        }
        flash_issue(sb, 0, bh, 0, tid);

        float acc[8][4] = {};
        float m0 = -INFINITY, m1 = -INFINITY, l0 = 0.f, l1 = 0.f;

        for (int kt = 0; kt < nkt; ++kt) {
            int buf = kt & 1;
            if (kt + 1 < nkt) {
                flash_issue(sb, buf ^ 1, bh, (kt+1)*128, tid);
                CP_WAIT(1);
            } else {
                CP_WAIT(0);
            }
            __syncthreads();

            #pragma unroll
            for (int half = 0; half < 2; ++half) {
                int k0 = kt * 128 + half * 64;
                if (k0 > rowmax) continue;
                uint32_t kb = sb + OB0 + buf*BUFB + (2*half)*KVB;
                uint32_t vb = kb + KVB;

                // ---- mask prefetch (gmem -> regs), consumed at softmax ----
                uint2 km0[8], km1[8];
                #pragma unroll
                for (int j = 0; j < 8; ++j) {
                    km0[j] = *(const uint2*)(mrow0 + k0 + j*8);
                    km1[j] = *(const uint2*)(mrow1 + k0 + j*8);
                }

                // ---- S = (Qh+Ql) K^T ----
                float s[8][4] = {};
                #pragma unroll
                for (int ks = 0; ks < 4; ++ks) {
                    uint32_t ksb = ks * 32;
                    uint32_t ah[4], al[4];
                    ldsm4(ah, sb + OQH + qaoff + ksb);
                    ldsm4(al, sb + OQL + qaoff + ksb);
                    #pragma unroll
                    for (int jp2 = 0; jp2 < 2; ++jp2) {
                        uint32_t k4[2][4];
                        ldsm4(k4[0], kb + bofff[2*jp2]     + ksb);
                        ldsm4(k4[1], kb + bofff[2*jp2 + 1] + ksb);
                        #pragma unroll
                        for (int p = 0; p < 2; ++p)
                            #pragma unroll
                            for (int jj = 0; jj < 2; ++jj)
                                mma16816(s[(2*jp2+p)*2+jj], ah, k4[p] + jj*2);
                        #pragma unroll
                        for (int p = 0; p < 2; ++p)
                            #pragma unroll
                            for (int jj = 0; jj < 2; ++jj)
                                mma16816(s[(2*jp2+p)*2+jj], al, k4[p] + jj*2);
                    }
                }

                // ---- causal mask ----
                int row0 = q0 + r, row1 = row0 + 8;
                #pragma unroll
                for (int j = 0; j < 8; ++j) {
                    int cg = k0 + j*8 + qc*2;
                    if (cg     > row0) s[j][0] = -INFINITY;
                    if (cg + 1 > row0) s[j][1] = -INFINITY;
                    if (cg     > row1) s[j][2] = -INFINITY;
                    if (cg + 1 > row1) s[j][3] = -INFINITY;
                }

                // ---- online softmax (undropped denominator) ----
                float mx0 = -INFINITY, mx1 = -INFINITY;
                #pragma unroll
                for (int j = 0; j < 8; ++j) {
                    mx0 = fmaxf(mx0, fmaxf(s[j][0], s[j][1]));
                    mx1 = fmaxf(mx1, fmaxf(s[j][2], s[j][3]));
                }
                mx0 = fmaxf(mx0, __shfl_xor_sync(0xffffffffu, mx0, 1));
                mx0 = fmaxf(mx0, __shfl_xor_sync(0xffffffffu, mx0, 2));
                mx1 = fmaxf(mx1, __shfl_xor_sync(0xffffffffu, mx1, 1));
                mx1 = fmaxf(mx1, __shfl_xor_sync(0xffffffffu, mx1, 2));
                float m0n = fmaxf(m0, mx0), m1n = fmaxf(m1, mx1);
                float a0 = __expf(m0 - m0n), a1 = __expf(m1 - m1n);
                float sum0 = 0.f, sum1 = 0.f;
                #pragma unroll
                for (int j = 0; j < 8; ++j) {
                    float p0 = __expf(s[j][0] - m0n); sum0 += p0;
                    float p1 = __expf(s[j][1] - m0n); sum0 += p1;
                    float p2 = __expf(s[j][2] - m1n); sum1 += p2;
                    float p3 = __expf(s[j][3] - m1n); sum1 += p3;
                    s[j][0] = km0[j].x ? p0 * KEEP_INV : 0.f;
                    s[j][1] = km0[j].y ? p1 * KEEP_INV : 0.f;
                    s[j][2] = km1[j].x ? p2 * KEEP_INV : 0.f;
                    s[j][3] = km1[j].y ? p3 * KEEP_INV : 0.f;
                }
                sum0 += __shfl_xor_sync(0xffffffffu, sum0, 1);
                sum0 += __shfl_xor_sync(0xffffffffu, sum0, 2);
                sum1 += __shfl_xor_sync(0xffffffffu, sum1, 1);
                sum1 += __shfl_xor_sync(0xffffffffu, sum1, 2);
                l0 = l0 * a0 + sum0;
                l1 = l1 * a1 + sum1;
                m0 = m0n; m1 = m1n;

                // ---- acc scale + P V (single-term P) ----
                #pragma unroll
                for (int j = 0; j < 8; ++j) {
                    acc[j][0] *= a0; acc[j][1] *= a0;
                    acc[j][2] *= a1; acc[j][3] *= a1;
                }
                #pragma unroll
                for (int s4 = 0; s4 < 4; ++s4) {
                    uint32_t ph_[4];
                    ph_[0] = pack2h(s[2*s4][0],   s[2*s4][1]);
                    ph_[1] = pack2h(s[2*s4][2],   s[2*s4][3]);
                    ph_[2] = pack2h(s[2*s4+1][0], s[2*s4+1][1]);
                    ph_[3] = pack2h(s[2*s4+1][2], s[2*s4+1][3]);
                    uint32_t ksb = s4 * 32;
                    #pragma unroll
                    for (int jp2 = 0; jp2 < 2; ++jp2) {
                        uint32_t v4[2][4];
                        ldsm4(v4[0], vb + bofff[2*jp2]     + ksb);
                        ldsm4(v4[1], vb + bofff[2*jp2 + 1] + ksb);
                        #pragma unroll
                        for (int p = 0; p < 2; ++p)
                            #pragma unroll
                            for (int jj = 0; jj < 2; ++jj)
                                mma16816(acc[(2*jp2+p)*2+jj], ph_, v4[p] + jj*2);
                    }
                }
            }
            __syncthreads();
        }

        // ---- epilogue: y = acc / l, write truncated fp16 [tok][C] ----
        int b = bh >> 4, h = bh & 15;
        float inv0 = 1.f / l0, inv1 = 1.f / l1;
        size_t tok0 = (size_t)b*Tt + q0 + r;
        size_t tok1 = tok0 + 8;
        #pragma unroll
        for (int j = 0; j < 8; ++j) {
            int col = h*HD + j*8 + qc*2;
            *(uint32_t*)&g_yh[tok0*Cc + col] = pack2h(acc[j][0]*inv0, acc[j][1]*inv0);
            *(uint32_t*)&g_yh[tok1*Cc + col] = pack2h(acc[j][2]*inv1, acc[j][3]*inv1);
        }
    }
}

// ---------------------------------------------------------------------------
extern "C" void kernel_launch(void* const* d_in, const int* in_sizes, int n_in,
                              void* d_out, int out_size) {
    const float* x     = (const float*)d_in[0];
    const float* Wqkv  = (const float*)d_in[1];
    const float* bqkv  = (const float*)d_in[2];
    const float* Wproj = (const float*)d_in[3];
    const float* bproj = (const float*)d_in[4];
    const unsigned* amask = (const unsigned*)d_in[5];
    const unsigned* rmask = (const unsigned*)d_in[6];
    float* out = (float*)d_out;

    cudaFuncSetAttribute(gemm_mma<0>, cudaFuncAttributeMaxDynamicSharedMemorySize, GEMM_SMEM);
    cudaFuncSetAttribute(gemm_mma<1>, cudaFuncAttributeMaxDynamicSharedMemorySize, GEMM_SMEM);
    cudaFuncSetAttribute(flash_mma, cudaFuncAttributeMaxDynamicSharedMemorySize, FLASH_SMEM);

    __half *xh, *wqh, *wph, *yh;
    cudaGetSymbolAddress((void**)&xh,  g_xh);
    cudaGetSymbolAddress((void**)&wqh, g_wqh); cudaGetSymbolAddress((void**)&wph, g_wph);
    cudaGetSymbolAddress((void**)&yh,  g_yh);

    cvt_trunc<<<(NTOK*Cc/4 + 255)/256, 256>>>((const float4*)x, (__half2*)xh, NTOK*Cc/4);
    cvt_trunc_T<<<dim3(C3/32, Cc/32), dim3(32,8)>>>(Wqkv, wqh, Cc, C3);
    cvt_trunc_T<<<dim3(Cc/32, Cc/32), dim3(32,8)>>>(Wproj, wph, Cc, Cc);

    gemm_mma<0><<<dim3(C3/128, NTOK/128), 256, GEMM_SMEM>>>(xh, wqh, bqkv, nullptr, nullptr, Cc);

    flash_mma<<<dim3(NQB/2, Bsz*Hh), 256, FLASH_SMEM>>>(amask);

    gemm_mma<1><<<dim3(Cc/128, NTOK/128), 256, GEMM_SMEM>>>(yh, wph, bproj, rmask, out, Cc);
}

// round 15
// speedup vs baseline: 2.5519x; 1.0723x over previous
#include <cuda_runtime.h>
#include <cuda_fp16.h>
#include <math.h>
#include <cstdint>

// Problem constants
#define Bsz 2
#define Tt 2048
#define Cc 1024
#define Hh 16
#define HD 64
#define NTOK (Bsz*Tt)   // 4096
#define C3 (3*Cc)       // 3072
#define KEEP_INV (1.0f/0.9f)
#define NQB 16          // q-tiles of 128

// ---------------- scratch (device globals; no allocs allowed) ---------------
__device__ __half g_xh[(size_t)NTOK*Cc];                   // x truncated
__device__ __half g_wqh[(size_t)C3*Cc];                    // [N,K] transposed, truncated
__device__ __half g_wph[(size_t)Cc*Cc];                    // [N,K] transposed, truncated
__device__ __half g_yh[(size_t)NTOK*Cc];                   // attention out, truncated
__device__ __half g_qh[(size_t)32*Tt*HD];                  // q truncated, scaled 1/8
__device__ __half g_kh[(size_t)32*Tt*HD];                  // k truncated
__device__ __half g_vth[(size_t)32*HD*Tt];                 // v transposed, truncated

// ---------------- helpers ----------------
__device__ __forceinline__ uint32_t smem_u32(const void* p) {
    uint32_t a;
    asm("{ .reg .u64 t; cvta.to.shared.u64 t, %1; cvt.u32.u64 %0, t; }" : "=r"(a) : "l"(p));
    return a;
}
__device__ __forceinline__ void cp_async16(uint32_t dst, const void* src) {
    asm volatile("cp.async.cg.shared.global [%0], [%1], 16;" :: "r"(dst), "l"(src) : "memory");
}
#define CP_COMMIT() asm volatile("cp.async.commit_group;" ::: "memory")
#define CP_WAIT(n)  asm volatile("cp.async.wait_group %0;" :: "n"(n) : "memory")

__device__ __forceinline__ void mma16816(float* c, const uint32_t* a, const uint32_t* b) {
    asm volatile("mma.sync.aligned.m16n8k16.row.col.f32.f16.f16.f32 "
        "{%0,%1,%2,%3}, {%4,%5,%6,%7}, {%8,%9}, {%0,%1,%2,%3};"
        : "+f"(c[0]), "+f"(c[1]), "+f"(c[2]), "+f"(c[3])
        : "r"(a[0]), "r"(a[1]), "r"(a[2]), "r"(a[3]), "r"(b[0]), "r"(b[1]));
}
__device__ __forceinline__ void ldsm4(uint32_t* r, uint32_t a) {
    asm volatile("ldmatrix.sync.aligned.m8n8.x4.shared.b16 {%0,%1,%2,%3}, [%4];"
        : "=r"(r[0]), "=r"(r[1]), "=r"(r[2]), "=r"(r[3]) : "r"(a));
}
__device__ __forceinline__ uint32_t pack2h(float a, float b) {
    __half2 H(__float2half_rn(a), __float2half_rn(b));
    return *(uint32_t*)&H;
}

// ---------------------------------------------------------------------------
// fp32 -> truncated fp16 (row-major passthrough)
// ---------------------------------------------------------------------------
__global__ __launch_bounds__(256) void cvt_trunc(const float4* __restrict__ in,
                                                 __half2* __restrict__ hi,
                                                 int n4) {
    int i = blockIdx.x * 256 + threadIdx.x;
    if (i >= n4) return;
    float4 v = in[i];
    hi[2*i]   = __half2(__float2half_rn(v.x), __float2half_rn(v.y));
    hi[2*i+1] = __half2(__float2half_rn(v.z), __float2half_rn(v.w));
}

// fp32 W[K,N] -> transposed truncated fp16 [N,K]
__global__ __launch_bounds__(256) void cvt_trunc_T(const float* __restrict__ in,
                                                   __half* __restrict__ hi,
                                                   int K, int N) {
    __shared__ float t[32][33];
    int nx = blockIdx.x * 32, kx = blockIdx.y * 32;
    int tx = threadIdx.x, ty = threadIdx.y;  // (32,8)
    #pragma unroll
    for (int r = 0; r < 4; ++r)
        t[ty + 8*r][tx] = in[(size_t)(kx + ty + 8*r) * N + nx + tx];
    __syncthreads();
    #pragma unroll
    for (int r = 0; r < 4; ++r)
        hi[(size_t)(nx + ty + 8*r) * K + kx + tx] = __float2half_rn(t[tx][ty + 8*r]);
}

// ---------------------------------------------------------------------------
// mma.sync fp16 single-term GEMM: C = A[M,K] * Bt[N,K]^T (+bias, +epilogue)
// 128x128 tile, K-chunk 64, 2-stage cp.async, ldmatrix.x4. 72KB smem.
// MODE 0: qkv -> q trunc (scaled 1/8), k trunc, v smem-transpose.
// MODE 1: proj + resid dropout -> out (fp32).
// ---------------------------------------------------------------------------
#define SR 72                   // halves per row (64 + 8 pad) -> 144B stride
#define TILE_E (128*SR)
#define TILE_B (TILE_E*2)       // 18432 bytes
#define TSR 136                 // transpose smem stride in halves (272B)
#define GEMM_SMEM (4*TILE_B)    // 73728

__device__ __forceinline__ void gemm_issue(uint32_t sb, int buf,
                                           const __half* A, const __half* B,
                                           int m0, int n0, int K, int ch, int tid) {
    #pragma unroll
    for (int it = 0; it < 8; ++it) {
        int u = tid + it * 256;           // 0..2047
        int arr = u >> 10;                // 0..1
        int rem = u & 1023;
        int row = rem >> 3;
        int c16 = rem & 7;                // 16B unit (8 halves)
        const __half* src = (arr == 0) ? A : B;
        int grow = (arr == 0 ? m0 : n0) + row;
        uint32_t soff = (uint32_t)((buf * 2 * TILE_E + arr * TILE_E + row * SR + c16 * 8) * 2);
        cp_async16(sb + soff, src + (size_t)grow * K + ch * 64 + c16 * 8);
    }
    CP_COMMIT();
}

template<int MODE>
__global__ __launch_bounds__(256, 2) void gemm_mma(const __half* __restrict__ A,
                                                   const __half* __restrict__ B,
                                                   const float* __restrict__ bias,
                                                   const unsigned* __restrict__ rmask,
                                                   float* __restrict__ out,
                                                   int K) {
    extern __shared__ __half smg[];
    uint32_t sb = smem_u32(smg);
    int tid = threadIdx.x, wid = tid >> 5, lane = tid & 31;
    int m0 = blockIdx.y * 128, n0 = blockIdx.x * 128;
    int wm = (wid & 3) * 32, wn = (wid >> 2) * 64;
    int qr = lane >> 2, qc = lane & 3;
    int g = lane >> 3, lr = lane & 7;

    uint32_t aoff[2], boff[4];
    #pragma unroll
    for (int i = 0; i < 2; ++i)
        aoff[i] = (uint32_t)(((wm + i*16 + lr + (g & 1)*8) * SR + (g >> 1)*8) * 2);
    #pragma unroll
    for (int jp = 0; jp < 4; ++jp)
        boff[jp] = (uint32_t)(((wn + jp*16 + lr + (g >> 1)*8) * SR + (g & 1)*8) * 2);

    float acc[2][8][4] = {};
    int nch = K >> 6;

    gemm_issue(sb, 0, A, B, m0, n0, K, 0, tid);

    for (int ch = 0; ch < nch; ++ch) {
        int buf = ch & 1;
        if (ch + 1 < nch) {
            gemm_issue(sb, buf ^ 1, A, B, m0, n0, K, ch + 1, tid);
            CP_WAIT(1);
        } else {
            CP_WAIT(0);
        }
        __syncthreads();

        uint32_t bA = sb + buf * 2 * TILE_B;
        uint32_t bB = bA + TILE_B;

        #pragma unroll
        for (int ks = 0; ks < 4; ++ks) {
            uint32_t ksb = ks * 32;
            uint32_t a4[2][4];
            ldsm4(a4[0], bA + aoff[0] + ksb);
            ldsm4(a4[1], bA + aoff[1] + ksb);
            #pragma unroll
            for (int jp2 = 0; jp2 < 2; ++jp2) {
                uint32_t b4[2][4];
                ldsm4(b4[0], bB + boff[2*jp2]     + ksb);
                ldsm4(b4[1], bB + boff[2*jp2 + 1] + ksb);
                #pragma unroll
                for (int p = 0; p < 2; ++p)
                    #pragma unroll
                    for (int jj = 0; jj < 2; ++jj)
                        #pragma unroll
                        for (int i = 0; i < 2; ++i)
                            mma16816(acc[i][(2*jp2+p)*2+jj], a4[i], b4[p] + jj*2);
            }
        }
        __syncthreads();
    }

    if (MODE == 0 && n0 >= 2*Cc) {
        // ---- V block: smem-bounce transpose, coalesced [d][t] store ----
        #pragma unroll
        for (int i = 0; i < 2; ++i) {
            #pragma unroll
            for (int j = 0; j < 8; ++j) {
                int col0 = wn + j*8 + qc*2;
                float b0 = bias[n0 + col0], b1 = bias[n0 + col0 + 1];
                #pragma unroll
                for (int hrow = 0; hrow < 2; ++hrow) {
                    int rowl = wm + i*16 + qr + hrow*8;
                    smg[col0*TSR + rowl]     = __float2half_rn(acc[i][j][hrow*2+0] + b0);
                    smg[(col0+1)*TSR + rowl] = __float2half_rn(acc[i][j][hrow*2+1] + b1);
                }
            }
        }
        __syncthreads();
        int t0 = m0 & (Tt - 1);
        int b  = m0 >> 11;
        #pragma unroll
        for (int it = 0; it < 8; ++it) {
            int u = tid + it * 256;       // 0..2047
            int col = u >> 4, c8 = u & 15;
            uint4 val = *(uint4*)&smg[col*TSR + c8*8];
            int vcol = (n0 - 2*Cc) + col;
            int h = vcol >> 6, dd = vcol & 63;
            int bh = b*Hh + h;
            *(uint4*)&g_vth[((size_t)bh*HD + dd)*Tt + t0 + c8*8] = val;
        }
        return;
    }

    // Epilogue (q, k, proj)
    #pragma unroll
    for (int i = 0; i < 2; ++i) {
        int R0 = m0 + wm + i * 16 + qr;
        #pragma unroll
        for (int j = 0; j < 8; ++j) {
            int C0 = n0 + wn + j * 8 + qc * 2;
            float b0 = bias[C0], b1 = bias[C0 + 1];
            #pragma unroll
            for (int hrow = 0; hrow < 2; ++hrow) {
                int m = R0 + hrow * 8;
                float v0 = acc[i][j][hrow*2 + 0] + b0;
                float v1 = acc[i][j][hrow*2 + 1] + b1;
                if (MODE == 0) {
                    int bb = m >> 11, t = m & (Tt - 1);
                    int which = C0 >> 10, cidx = C0 & 1023;
                    int h = cidx >> 6, dd = cidx & 63;
                    int bh = bb * Hh + h;
                    size_t o = ((size_t)bh*Tt + t)*HD + dd;
                    if (which == 0) {
                        *(uint32_t*)&g_qh[o] = pack2h(v0 * 0.125f, v1 * 0.125f);
                    } else {
                        *(uint32_t*)&g_kh[o] = pack2h(v0, v1);
                    }
                } else {
                    size_t idx = (size_t)m * Cc + C0;
                    out[idx]     = rmask[idx]     ? v0 * KEEP_INV : 0.f;
                    out[idx + 1] = rmask[idx + 1] ? v1 * KEEP_INV : 0.f;
                }
            }
        }
    }
}

// ---------------------------------------------------------------------------
// Flash attention: QK single-term Q*K, PV single-term P*V (all fp16 trunc).
// 128-wide k-tiles, PAIRED q-tiles per CTA (qb = NQB-1-bx then bx):
// every CTA does exactly 17 tile-units; one balanced wave. 90KB smem.
// ---------------------------------------------------------------------------
#define SRK 72                       // fp16 row stride for 64-col tiles
#define OQH 0
#define OB0 (128*SRK*2)              // 18432
#define KVB (64*SRK*2)               // 9216
#define BUFB (4*KVB)                 // 36864 : [K0,V0,K1,V1]
#define FLASH_SMEM (OB0 + 2*BUFB)    // 92160

__device__ __forceinline__ void flash_issue(uint32_t sb, int buf,
                                            int bh, int k0, int tid) {
    // K: 128 rows x 64 halves (two 64-row subtiles)
    #pragma unroll
    for (int it = 0; it < 4; ++it) {
        int u = tid + it * 256;           // 0..1023
        int row = u >> 3, ck = u & 7;
        int half = row >> 6, lr_ = row & 63;
        uint32_t dst = sb + OB0 + buf*BUFB + (2*half)*KVB + (uint32_t)(lr_*SRK + ck*8)*2;
        cp_async16(dst, g_kh + ((size_t)bh*Tt + k0 + row)*HD + ck*8);
    }
    // V: 64 d-rows x 128 t (two 64-t subtiles)
    #pragma unroll
    for (int it = 0; it < 4; ++it) {
        int u = tid + it * 256;
        int d = u >> 4, ct = u & 15;
        int thalf = ct >> 3, tc = ct & 7;
        uint32_t dst = sb + OB0 + buf*BUFB + (2*thalf+1)*KVB + (uint32_t)(d*SRK + tc*8)*2;
        cp_async16(dst, g_vth + ((size_t)bh*HD + d)*Tt + k0 + ct*8);
    }
    CP_COMMIT();
}

__global__ __launch_bounds__(256, 2) void flash_mma(const unsigned* __restrict__ amask) {
    extern __shared__ char smf[];
    uint32_t sb = smem_u32(smf);
    int tid = threadIdx.x, wid = tid >> 5, lane = tid & 31;
    int qr = lane >> 2, qc = lane & 3;
    int g = lane >> 3, lr = lane & 7;
    int bh = blockIdx.y;

    uint32_t qaoff = (uint32_t)(((wid*16 + lr + (g & 1)*8) * SRK + (g >> 1)*8) * 2);
    uint32_t bofff[4];
    #pragma unroll
    for (int jp = 0; jp < 4; ++jp)
        bofff[jp] = (uint32_t)(((jp*16 + lr + (g >> 1)*8) * SRK + (g & 1)*8) * 2);

    int r = wid * 16 + qr;                  // q row within tile

    for (int ph = 0; ph < 2; ++ph) {
        int qb = ph ? (int)blockIdx.x : (NQB - 1 - (int)blockIdx.x);
        int q0 = qb * 128;
        int nkt = qb + 1;                   // 128-wide tiles
        int rowmax = q0 + wid * 16 + 15;
        const unsigned* mrow0 = amask + ((size_t)bh*Tt + q0 + r)*Tt + qc*2;
        const unsigned* mrow1 = mrow0 + (size_t)8*Tt;

        // Q tile load (truncated single array) — same cp.async group as tile 0
        #pragma unroll
        for (int it = 0; it < 4; ++it) {
            int u = tid + it * 256;       // 0..1023
            int row = u >> 3;
            int ck = u & 7;
            uint32_t dst = sb + OQH + (uint32_t)(row*SRK + ck*8)*2;
            cp_async16(dst, g_qh + ((size_t)bh*Tt + q0 + row)*HD + ck*8);
        }
        flash_issue(sb, 0, bh, 0, tid);

        float acc[8][4] = {};
        float m0 = -INFINITY, m1 = -INFINITY, l0 = 0.f, l1 = 0.f;

        for (int kt = 0; kt < nkt; ++kt) {
            int buf = kt & 1;
            if (kt + 1 < nkt) {
                flash_issue(sb, buf ^ 1, bh, (kt+1)*128, tid);
                CP_WAIT(1);
            } else {
                CP_WAIT(0);
            }
            __syncthreads();

            #pragma unroll
            for (int half = 0; half < 2; ++half) {
                int k0 = kt * 128 + half * 64;
                if (k0 > rowmax) continue;
                uint32_t kb = sb + OB0 + buf*BUFB + (2*half)*KVB;
                uint32_t vb = kb + KVB;

                // ---- mask prefetch (gmem -> regs), consumed at softmax ----
                uint2 km0[8], km1[8];
                #pragma unroll
                for (int j = 0; j < 8; ++j) {
                    km0[j] = *(const uint2*)(mrow0 + k0 + j*8);
                    km1[j] = *(const uint2*)(mrow1 + k0 + j*8);
                }

                // ---- S = Q K^T (single-term) ----
                float s[8][4] = {};
                #pragma unroll
                for (int ks = 0; ks < 4; ++ks) {
                    uint32_t ksb = ks * 32;
                    uint32_t ah[4];
                    ldsm4(ah, sb + OQH + qaoff + ksb);
                    #pragma unroll
                    for (int jp2 = 0; jp2 < 2; ++jp2) {
                        uint32_t k4[2][4];
                        ldsm4(k4[0], kb + bofff[2*jp2]     + ksb);
                        ldsm4(k4[1], kb + bofff[2*jp2 + 1] + ksb);
                        #pragma unroll
                        for (int p = 0; p < 2; ++p)
                            #pragma unroll
                            for (int jj = 0; jj < 2; ++jj)
                                mma16816(s[(2*jp2+p)*2+jj], ah, k4[p] + jj*2);
                    }
                }

                // ---- causal mask ----
                int row0 = q0 + r, row1 = row0 + 8;
                #pragma unroll
                for (int j = 0; j < 8; ++j) {
                    int cg = k0 + j*8 + qc*2;
                    if (cg     > row0) s[j][0] = -INFINITY;
                    if (cg + 1 > row0) s[j][1] = -INFINITY;
                    if (cg     > row1) s[j][2] = -INFINITY;
                    if (cg + 1 > row1) s[j][3] = -INFINITY;
                }

                // ---- online softmax (undropped denominator) ----
                float mx0 = -INFINITY, mx1 = -INFINITY;
                #pragma unroll
                for (int j = 0; j < 8; ++j) {
                    mx0 = fmaxf(mx0, fmaxf(s[j][0], s[j][1]));
                    mx1 = fmaxf(mx1, fmaxf(s[j][2], s[j][3]));
                }
                mx0 = fmaxf(mx0, __shfl_xor_sync(0xffffffffu, mx0, 1));
                mx0 = fmaxf(mx0, __shfl_xor_sync(0xffffffffu, mx0, 2));
                mx1 = fmaxf(mx1, __shfl_xor_sync(0xffffffffu, mx1, 1));
                mx1 = fmaxf(mx1, __shfl_xor_sync(0xffffffffu, mx1, 2));
                float m0n = fmaxf(m0, mx0), m1n = fmaxf(m1, mx1);
                float a0 = __expf(m0 - m0n), a1 = __expf(m1 - m1n);
                float sum0 = 0.f, sum1 = 0.f;
                #pragma unroll
                for (int j = 0; j < 8; ++j) {
                    float p0 = __expf(s[j][0] - m0n); sum0 += p0;
                    float p1 = __expf(s[j][1] - m0n); sum0 += p1;
                    float p2 = __expf(s[j][2] - m1n); sum1 += p2;
                    float p3 = __expf(s[j][3] - m1n); sum1 += p3;
                    s[j][0] = km0[j].x ? p0 * KEEP_INV : 0.f;
                    s[j][1] = km0[j].y ? p1 * KEEP_INV : 0.f;
                    s[j][2] = km1[j].x ? p2 * KEEP_INV : 0.f;
                    s[j][3] = km1[j].y ? p3 * KEEP_INV : 0.f;
                }
                sum0 += __shfl_xor_sync(0xffffffffu, sum0, 1);
                sum0 += __shfl_xor_sync(0xffffffffu, sum0, 2);
                sum1 += __shfl_xor_sync(0xffffffffu, sum1, 1);
                sum1 += __shfl_xor_sync(0xffffffffu, sum1, 2);
                l0 = l0 * a0 + sum0;
                l1 = l1 * a1 + sum1;
                m0 = m0n; m1 = m1n;

                // ---- acc scale + P V (single-term P) ----
                #pragma unroll
                for (int j = 0; j < 8; ++j) {
                    acc[j][0] *= a0; acc[j][1] *= a0;
                    acc[j][2] *= a1; acc[j][3] *= a1;
                }
                #pragma unroll
                for (int s4 = 0; s4 < 4; ++s4) {
                    uint32_t ph_[4];
                    ph_[0] = pack2h(s[2*s4][0],   s[2*s4][1]);
                    ph_[1] = pack2h(s[2*s4][2],   s[2*s4][3]);
                    ph_[2] = pack2h(s[2*s4+1][0], s[2*s4+1][1]);
                    ph_[3] = pack2h(s[2*s4+1][2], s[2*s4+1][3]);
                    uint32_t ksb = s4 * 32;
                    #pragma unroll
                    for (int jp2 = 0; jp2 < 2; ++jp2) {
                        uint32_t v4[2][4];
                        ldsm4(v4[0], vb + bofff[2*jp2]     + ksb);
                        ldsm4(v4[1], vb + bofff[2*jp2 + 1] + ksb);
                        #pragma unroll
                        for (int p = 0; p < 2; ++p)
                            #pragma unroll
                            for (int jj = 0; jj < 2; ++jj)
                                mma16816(acc[(2*jp2+p)*2+jj], ph_, v4[p] + jj*2);
                    }
                }
            }
            __syncthreads();
        }

        // ---- epilogue: y = acc / l, write truncated fp16 [tok][C] ----
        int b = bh >> 4, h = bh & 15;
        float inv0 = 1.f / l0, inv1 = 1.f / l1;
        size_t tok0 = (size_t)b*Tt + q0 + r;
        size_t tok1 = tok0 + 8;
        #pragma unroll
        for (int j = 0; j < 8; ++j) {
            int col = h*HD + j*8 + qc*2;
            *(uint32_t*)&g_yh[tok0*Cc + col] = pack2h(acc[j][0]*inv0, acc[j][1]*inv0);
            *(uint32_t*)&g_yh[tok1*Cc + col] = pack2h(acc[j][2]*inv1, acc[j][3]*inv1);
        }
    }
}

// ---------------------------------------------------------------------------
extern "C" void kernel_launch(void* const* d_in, const int* in_sizes, int n_in,
                              void* d_out, int out_size) {
    const float* x     = (const float*)d_in[0];
    const float* Wqkv  = (const float*)d_in[1];
    const float* bqkv  = (const float*)d_in[2];
    const float* Wproj = (const float*)d_in[3];
    const float* bproj = (const float*)d_in[4];
    const unsigned* amask = (const unsigned*)d_in[5];
    const unsigned* rmask = (const unsigned*)d_in[6];
    float* out = (float*)d_out;

    cudaFuncSetAttribute(gemm_mma<0>, cudaFuncAttributeMaxDynamicSharedMemorySize, GEMM_SMEM);
    cudaFuncSetAttribute(gemm_mma<1>, cudaFuncAttributeMaxDynamicSharedMemorySize, GEMM_SMEM);
    cudaFuncSetAttribute(flash_mma, cudaFuncAttributeMaxDynamicSharedMemorySize, FLASH_SMEM);

    __half *xh, *wqh, *wph, *yh;
    cudaGetSymbolAddress((void**)&xh,  g_xh);
    cudaGetSymbolAddress((void**)&wqh, g_wqh); cudaGetSymbolAddress((void**)&wph, g_wph);
    cudaGetSymbolAddress((void**)&yh,  g_yh);

    cvt_trunc<<<(NTOK*Cc/4 + 255)/256, 256>>>((const float4*)x, (__half2*)xh, NTOK*Cc/4);
    cvt_trunc_T<<<dim3(C3/32, Cc/32), dim3(32,8)>>>(Wqkv, wqh, Cc, C3);
    cvt_trunc_T<<<dim3(Cc/32, Cc/32), dim3(32,8)>>>(Wproj, wph, Cc, Cc);

    gemm_mma<0><<<dim3(C3/128, NTOK/128), 256, GEMM_SMEM>>>(xh, wqh, bqkv, nullptr, nullptr, Cc);

    flash_mma<<<dim3(NQB/2, Bsz*Hh), 256, FLASH_SMEM>>>(amask);

    gemm_mma<1><<<dim3(Cc/128, NTOK/128), 256, GEMM_SMEM>>>(yh, wph, bproj, rmask, out, Cc);
}

// round 16
// speedup vs baseline: 2.6785x; 1.0496x over previous
#include <cuda_runtime.h>
#include <cuda_fp16.h>
#include <math.h>
#include <cstdint>

// Problem constants
#define Bsz 2
#define Tt 2048
#define Cc 1024
#define Hh 16
#define HD 64
#define NTOK (Bsz*Tt)   // 4096
#define C3 (3*Cc)       // 3072
#define KEEP_INV (1.0f/0.9f)
#define NQB 16          // q-tiles of 128

// ---------------- scratch (device globals; no allocs allowed) ---------------
__device__ __half g_xh[(size_t)NTOK*Cc];                   // x truncated
__device__ __half g_wqh[(size_t)C3*Cc];                    // [N,K] transposed, truncated
__device__ __half g_wph[(size_t)Cc*Cc];                    // [N,K] transposed, truncated
__device__ __half g_yh[(size_t)NTOK*Cc];                   // attention out, truncated
__device__ __half g_qh[(size_t)32*Tt*HD];                  // q truncated, scaled 1/8
__device__ __half g_kh[(size_t)32*Tt*HD];                  // k truncated
__device__ __half g_vth[(size_t)32*HD*Tt];                 // v transposed, truncated

// ---------------- helpers ----------------
__device__ __forceinline__ uint32_t smem_u32(const void* p) {
    uint32_t a;
    asm("{ .reg .u64 t; cvta.to.shared.u64 t, %1; cvt.u32.u64 %0, t; }" : "=r"(a) : "l"(p));
    return a;
}
__device__ __forceinline__ void cp_async16(uint32_t dst, const void* src) {
    asm volatile("cp.async.cg.shared.global [%0], [%1], 16;" :: "r"(dst), "l"(src) : "memory");
}
#define CP_COMMIT() asm volatile("cp.async.commit_group;" ::: "memory")
#define CP_WAIT(n)  asm volatile("cp.async.wait_group %0;" :: "n"(n) : "memory")

__device__ __forceinline__ void mma16816(float* c, const uint32_t* a, const uint32_t* b) {
    asm volatile("mma.sync.aligned.m16n8k16.row.col.f32.f16.f16.f32 "
        "{%0,%1,%2,%3}, {%4,%5,%6,%7}, {%8,%9}, {%0,%1,%2,%3};"
        : "+f"(c[0]), "+f"(c[1]), "+f"(c[2]), "+f"(c[3])
        : "r"(a[0]), "r"(a[1]), "r"(a[2]), "r"(a[3]), "r"(b[0]), "r"(b[1]));
}
__device__ __forceinline__ void ldsm4(uint32_t* r, uint32_t a) {
    asm volatile("ldmatrix.sync.aligned.m8n8.x4.shared.b16 {%0,%1,%2,%3}, [%4];"
        : "=r"(r[0]), "=r"(r[1]), "=r"(r[2]), "=r"(r[3]) : "r"(a));
}
__device__ __forceinline__ uint32_t pack2h(float a, float b) {
    __half2 H(__float2half_rn(a), __float2half_rn(b));
    return *(uint32_t*)&H;
}

// ---------------------------------------------------------------------------
// Fused conversion kernel: x trunc + Wqkv transpose-trunc + Wproj transpose-trunc
// ---------------------------------------------------------------------------
__device__ void tile_T(const float* __restrict__ in, __half* __restrict__ out,
                       int K, int N, int bx, int by, int tid) {
    __shared__ float t[32][33];
    int tx = tid & 31, ty = tid >> 5;     // (32, 8)
    int nx = bx * 32, kx = by * 32;
    #pragma unroll
    for (int r = 0; r < 4; ++r)
        t[ty + 8*r][tx] = in[(size_t)(kx + ty + 8*r) * N + nx + tx];
    __syncthreads();
    #pragma unroll
    for (int r = 0; r < 4; ++r)
        out[(size_t)(nx + ty + 8*r) * K + kx + tx] = __float2half_rn(t[tx][ty + 8*r]);
}

__global__ __launch_bounds__(256) void cvt_all(const float* __restrict__ x,
                                               const float* __restrict__ Wq,
                                               const float* __restrict__ Wp) {
    int blk = blockIdx.x, tid = threadIdx.x;
    if (blk < 4096) {
        int i = blk * 256 + tid;                      // float4 index (1M total)
        float4 v = ((const float4*)x)[i];
        __half2* hi = (__half2*)g_xh;
        hi[2*i]   = __half2(__float2half_rn(v.x), __float2half_rn(v.y));
        hi[2*i+1] = __half2(__float2half_rn(v.z), __float2half_rn(v.w));
    } else if (blk < 4096 + 3072) {
        int b = blk - 4096;
        tile_T(Wq, g_wqh, Cc, C3, b % 96, b / 96, tid);
    } else {
        int b = blk - 7168;
        tile_T(Wp, g_wph, Cc, Cc, b % 32, b / 32, tid);
    }
}

// ---------------------------------------------------------------------------
// mma.sync fp16 single-term GEMM: C = A[M,K] * Bt[N,K]^T (+bias, +epilogue)
// 128x128 tile, K-chunk 64, 3-stage cp.async, ONE barrier per chunk
// (cutlass-multistage ordering: wait -> sync -> issue(ch+2) -> compute).
// 108KB smem -> 2 CTAs/SM.
// MODE 0: qkv -> q trunc (scaled 1/8), k trunc, v smem-transpose.
// MODE 1: proj + resid dropout -> out (fp32).
// ---------------------------------------------------------------------------
#define SR 72                   // halves per row (64 + 8 pad) -> 144B stride
#define TILE_E (128*SR)
#define TILE_B (TILE_E*2)       // 18432 bytes
#define TSR 136                 // transpose smem stride in halves (272B)
#define GEMM_SMEM (6*TILE_B)    // 110592 (3 stages x (A,B))

__device__ __forceinline__ void gemm_issue(uint32_t sb, int buf,
                                           const __half* A, const __half* B,
                                           int m0, int n0, int K, int ch, int tid) {
    #pragma unroll
    for (int it = 0; it < 8; ++it) {
        int u = tid + it * 256;           // 0..2047
        int arr = u >> 10;                // 0..1
        int rem = u & 1023;
        int row = rem >> 3;
        int c16 = rem & 7;                // 16B unit (8 halves)
        const __half* src = (arr == 0) ? A : B;
        int grow = (arr == 0 ? m0 : n0) + row;
        uint32_t soff = (uint32_t)((buf * 2 * TILE_E + arr * TILE_E + row * SR + c16 * 8) * 2);
        cp_async16(sb + soff, src + (size_t)grow * K + ch * 64 + c16 * 8);
    }
    CP_COMMIT();
}

template<int MODE>
__global__ __launch_bounds__(256, 2) void gemm_mma(const __half* __restrict__ A,
                                                   const __half* __restrict__ B,
                                                   const float* __restrict__ bias,
                                                   const unsigned* __restrict__ rmask,
                                                   float* __restrict__ out,
                                                   int K) {
    extern __shared__ __half smg[];
    uint32_t sb = smem_u32(smg);
    int tid = threadIdx.x, wid = tid >> 5, lane = tid & 31;
    int m0 = blockIdx.y * 128, n0 = blockIdx.x * 128;
    int wm = (wid & 3) * 32, wn = (wid >> 2) * 64;
    int qr = lane >> 2, qc = lane & 3;
    int g = lane >> 3, lr = lane & 7;

    uint32_t aoff[2], boff[4];
    #pragma unroll
    for (int i = 0; i < 2; ++i)
        aoff[i] = (uint32_t)(((wm + i*16 + lr + (g & 1)*8) * SR + (g >> 1)*8) * 2);
    #pragma unroll
    for (int jp = 0; jp < 4; ++jp)
        boff[jp] = (uint32_t)(((wn + jp*16 + lr + (g >> 1)*8) * SR + (g & 1)*8) * 2);

    float acc[2][8][4] = {};
    int nch = K >> 6;

    gemm_issue(sb, 0, A, B, m0, n0, K, 0, tid);
    gemm_issue(sb, 1, A, B, m0, n0, K, 1, tid);

    int buf = 0;
    for (int ch = 0; ch < nch; ++ch) {
        // wait for chunk ch's data (own groups), then make it visible + prove
        // all warps finished chunk ch-1 (whose buffer the next issue reuses)
        if (ch + 1 < nch) { CP_WAIT(1); } else { CP_WAIT(0); }
        __syncthreads();
        if (ch + 2 < nch) {
            int nb = buf + 2; if (nb >= 3) nb -= 3;
            gemm_issue(sb, nb, A, B, m0, n0, K, ch + 2, tid);
        }

        uint32_t bA = sb + buf * 2 * TILE_B;
        uint32_t bB = bA + TILE_B;

        #pragma unroll
        for (int ks = 0; ks < 4; ++ks) {
            uint32_t ksb = ks * 32;
            uint32_t a4[2][4];
            ldsm4(a4[0], bA + aoff[0] + ksb);
            ldsm4(a4[1], bA + aoff[1] + ksb);
            #pragma unroll
            for (int jp2 = 0; jp2 < 2; ++jp2) {
                uint32_t b4[2][4];
                ldsm4(b4[0], bB + boff[2*jp2]     + ksb);
                ldsm4(b4[1], bB + boff[2*jp2 + 1] + ksb);
                #pragma unroll
                for (int p = 0; p < 2; ++p)
                    #pragma unroll
                    for (int jj = 0; jj < 2; ++jj)
                        #pragma unroll
                        for (int i = 0; i < 2; ++i)
                            mma16816(acc[i][(2*jp2+p)*2+jj], a4[i], b4[p] + jj*2);
            }
        }
        if (++buf == 3) buf = 0;
    }

    if (MODE == 0 && n0 >= 2*Cc) {
        // ---- V block: smem-bounce transpose, coalesced [d][t] store ----
        __syncthreads();   // all warps done reading the last compute buffer
        #pragma unroll
        for (int i = 0; i < 2; ++i) {
            #pragma unroll
            for (int j = 0; j < 8; ++j) {
                int col0 = wn + j*8 + qc*2;
                float b0 = bias[n0 + col0], b1 = bias[n0 + col0 + 1];
                #pragma unroll
                for (int hrow = 0; hrow < 2; ++hrow) {
                    int rowl = wm + i*16 + qr + hrow*8;
                    smg[col0*TSR + rowl]     = __float2half_rn(acc[i][j][hrow*2+0] + b0);
                    smg[(col0+1)*TSR + rowl] = __float2half_rn(acc[i][j][hrow*2+1] + b1);
                }
            }
        }
        __syncthreads();
        int t0 = m0 & (Tt - 1);
        int b  = m0 >> 11;
        #pragma unroll
        for (int it = 0; it < 8; ++it) {
            int u = tid + it * 256;       // 0..2047
            int col = u >> 4, c8 = u & 15;
            uint4 val = *(uint4*)&smg[col*TSR + c8*8];
            int vcol = (n0 - 2*Cc) + col;
            int h = vcol >> 6, dd = vcol & 63;
            int bh = b*Hh + h;
            *(uint4*)&g_vth[((size_t)bh*HD + dd)*Tt + t0 + c8*8] = val;
        }
        return;
    }

    // Epilogue (q, k, proj)
    #pragma unroll
    for (int i = 0; i < 2; ++i) {
        int R0 = m0 + wm + i * 16 + qr;
        #pragma unroll
        for (int j = 0; j < 8; ++j) {
            int C0 = n0 + wn + j * 8 + qc * 2;
            float b0 = bias[C0], b1 = bias[C0 + 1];
            #pragma unroll
            for (int hrow = 0; hrow < 2; ++hrow) {
                int m = R0 + hrow * 8;
                float v0 = acc[i][j][hrow*2 + 0] + b0;
                float v1 = acc[i][j][hrow*2 + 1] + b1;
                if (MODE == 0) {
                    int bb = m >> 11, t = m & (Tt - 1);
                    int which = C0 >> 10, cidx = C0 & 1023;
                    int h = cidx >> 6, dd = cidx & 63;
                    int bh = bb * Hh + h;
                    size_t o = ((size_t)bh*Tt + t)*HD + dd;
                    if (which == 0) {
                        *(uint32_t*)&g_qh[o] = pack2h(v0 * 0.125f, v1 * 0.125f);
                    } else {
                        *(uint32_t*)&g_kh[o] = pack2h(v0, v1);
                    }
                } else {
                    size_t idx = (size_t)m * Cc + C0;
                    out[idx]     = rmask[idx]     ? v0 * KEEP_INV : 0.f;
                    out[idx + 1] = rmask[idx + 1] ? v1 * KEEP_INV : 0.f;
                }
            }
        }
    }
}

// ---------------------------------------------------------------------------
// Flash attention: QK single-term, PV single-term, 128-wide k-tiles,
// PAIRED q-tiles per CTA (17 units each, one balanced wave).
// ONE barrier per k-tile (wait -> sync -> issue(kt+1) -> compute). 90KB smem.
// ---------------------------------------------------------------------------
#define SRK 72                       // fp16 row stride for 64-col tiles
#define OQH 0
#define OB0 (128*SRK*2)              // 18432
#define KVB (64*SRK*2)               // 9216
#define BUFB (4*KVB)                 // 36864 : [K0,V0,K1,V1]
#define FLASH_SMEM (OB0 + 2*BUFB)    // 92160

__device__ __forceinline__ void flash_issue(uint32_t sb, int buf,
                                            int bh, int k0, int tid) {
    // K: 128 rows x 64 halves (two 64-row subtiles)
    #pragma unroll
    for (int it = 0; it < 4; ++it) {
        int u = tid + it * 256;           // 0..1023
        int row = u >> 3, ck = u & 7;
        int half = row >> 6, lr_ = row & 63;
        uint32_t dst = sb + OB0 + buf*BUFB + (2*half)*KVB + (uint32_t)(lr_*SRK + ck*8)*2;
        cp_async16(dst, g_kh + ((size_t)bh*Tt + k0 + row)*HD + ck*8);
    }
    // V: 64 d-rows x 128 t (two 64-t subtiles)
    #pragma unroll
    for (int it = 0; it < 4; ++it) {
        int u = tid + it * 256;
        int d = u >> 4, ct = u & 15;
        int thalf = ct >> 3, tc = ct & 7;
        uint32_t dst = sb + OB0 + buf*BUFB + (2*thalf+1)*KVB + (uint32_t)(d*SRK + tc*8)*2;
        cp_async16(dst, g_vth + ((size_t)bh*HD + d)*Tt + k0 + ct*8);
    }
    CP_COMMIT();
}

__global__ __launch_bounds__(256, 2) void flash_mma(const unsigned* __restrict__ amask) {
    extern __shared__ char smf[];
    uint32_t sb = smem_u32(smf);
    int tid = threadIdx.x, wid = tid >> 5, lane = tid & 31;
    int qr = lane >> 2, qc = lane & 3;
    int g = lane >> 3, lr = lane & 7;
    int bh = blockIdx.y;

    uint32_t qaoff = (uint32_t)(((wid*16 + lr + (g & 1)*8) * SRK + (g >> 1)*8) * 2);
    uint32_t bofff[4];
    #pragma unroll
    for (int jp = 0; jp < 4; ++jp)
        bofff[jp] = (uint32_t)(((jp*16 + lr + (g >> 1)*8) * SRK + (g & 1)*8) * 2);

    int r = wid * 16 + qr;                  // q row within tile

    for (int ph = 0; ph < 2; ++ph) {
        int qb = ph ? (int)blockIdx.x : (NQB - 1 - (int)blockIdx.x);
        int q0 = qb * 128;
        int nkt = qb + 1;                   // 128-wide tiles
        int rowmax = q0 + wid * 16 + 15;
        const unsigned* mrow0 = amask + ((size_t)bh*Tt + q0 + r)*Tt + qc*2;
        const unsigned* mrow1 = mrow0 + (size_t)8*Tt;

        // Q tile load (truncated single array) — same cp.async group as tile 0
        #pragma unroll
        for (int it = 0; it < 4; ++it) {
            int u = tid + it * 256;       // 0..1023
            int row = u >> 3;
            int ck = u & 7;
            uint32_t dst = sb + OQH + (uint32_t)(row*SRK + ck*8)*2;
            cp_async16(dst, g_qh + ((size_t)bh*Tt + q0 + row)*HD + ck*8);
        }
        flash_issue(sb, 0, bh, 0, tid);

        float acc[8][4] = {};
        float m0 = -INFINITY, m1 = -INFINITY, l0 = 0.f, l1 = 0.f;

        for (int kt = 0; kt < nkt; ++kt) {
            int buf = kt & 1;
            CP_WAIT(0);                   // drain group for tile kt
            __syncthreads();              // data visible + all warps done with kt-1
            if (kt + 1 < nkt)
                flash_issue(sb, buf ^ 1, bh, (kt+1)*128, tid);

            #pragma unroll
            for (int half = 0; half < 2; ++half) {
                int k0 = kt * 128 + half * 64;
                if (k0 > rowmax) continue;
                uint32_t kb = sb + OB0 + buf*BUFB + (2*half)*KVB;
                uint32_t vb = kb + KVB;

                // ---- mask prefetch (gmem -> regs), consumed at softmax ----
                uint2 km0[8], km1[8];
                #pragma unroll
                for (int j = 0; j < 8; ++j) {
                    km0[j] = *(const uint2*)(mrow0 + k0 + j*8);
                    km1[j] = *(const uint2*)(mrow1 + k0 + j*8);
                }

                // ---- S = Q K^T (single-term) ----
                float s[8][4] = {};
                #pragma unroll
                for (int ks = 0; ks < 4; ++ks) {
                    uint32_t ksb = ks * 32;
                    uint32_t ah[4];
                    ldsm4(ah, sb + OQH + qaoff + ksb);
                    #pragma unroll
                    for (int jp2 = 0; jp2 < 2; ++jp2) {
                        uint32_t k4[2][4];
                        ldsm4(k4[0], kb + bofff[2*jp2]     + ksb);
                        ldsm4(k4[1], kb + bofff[2*jp2 + 1] + ksb);
                        #pragma unroll
                        for (int p = 0; p < 2; ++p)
                            #pragma unroll
                            for (int jj = 0; jj < 2; ++jj)
                                mma16816(s[(2*jp2+p)*2+jj], ah, k4[p] + jj*2);
                    }
                }

                // ---- causal mask ----
                int row0 = q0 + r, row1 = row0 + 8;
                #pragma unroll
                for (int j = 0; j < 8; ++j) {
                    int cg = k0 + j*8 + qc*2;
                    if (cg     > row0) s[j][0] = -INFINITY;
                    if (cg + 1 > row0) s[j][1] = -INFINITY;
                    if (cg     > row1) s[j][2] = -INFINITY;
                    if (cg + 1 > row1) s[j][3] = -INFINITY;
                }

                // ---- online softmax (undropped denominator) ----
                float mx0 = -INFINITY, mx1 = -INFINITY;
                #pragma unroll
                for (int j = 0; j < 8; ++j) {
                    mx0 = fmaxf(mx0, fmaxf(s[j][0], s[j][1]));
                    mx1 = fmaxf(mx1, fmaxf(s[j][2], s[j][3]));
                }
                mx0 = fmaxf(mx0, __shfl_xor_sync(0xffffffffu, mx0, 1));
                mx0 = fmaxf(mx0, __shfl_xor_sync(0xffffffffu, mx0, 2));
                mx1 = fmaxf(mx1, __shfl_xor_sync(0xffffffffu, mx1, 1));
                mx1 = fmaxf(mx1, __shfl_xor_sync(0xffffffffu, mx1, 2));
                float m0n = fmaxf(m0, mx0), m1n = fmaxf(m1, mx1);
                float a0 = __expf(m0 - m0n), a1 = __expf(m1 - m1n);
                float sum0 = 0.f, sum1 = 0.f;
                #pragma unroll
                for (int j = 0; j < 8; ++j) {
                    float p0 = __expf(s[j][0] - m0n); sum0 += p0;
                    float p1 = __expf(s[j][1] - m0n); sum0 += p1;
                    float p2 = __expf(s[j][2] - m1n); sum1 += p2;
                    float p3 = __expf(s[j][3] - m1n); sum1 += p3;
                    s[j][0] = km0[j].x ? p0 * KEEP_INV : 0.f;
                    s[j][1] = km0[j].y ? p1 * KEEP_INV : 0.f;
                    s[j][2] = km1[j].x ? p2 * KEEP_INV : 0.f;
                    s[j][3] = km1[j].y ? p3 * KEEP_INV : 0.f;
                }
                sum0 += __shfl_xor_sync(0xffffffffu, sum0, 1);
                sum0 += __shfl_xor_sync(0xffffffffu, sum0, 2);
                sum1 += __shfl_xor_sync(0xffffffffu, sum1, 1);
                sum1 += __shfl_xor_sync(0xffffffffu, sum1, 2);
                l0 = l0 * a0 + sum0;
                l1 = l1 * a1 + sum1;
                m0 = m0n; m1 = m1n;

                // ---- acc scale + P V (single-term P) ----
                #pragma unroll
                for (int j = 0; j < 8; ++j) {
                    acc[j][0] *= a0; acc[j][1] *= a0;
                    acc[j][2] *= a1; acc[j][3] *= a1;
                }
                #pragma unroll
                for (int s4 = 0; s4 < 4; ++s4) {
                    uint32_t ph_[4];
                    ph_[0] = pack2h(s[2*s4][0],   s[2*s4][1]);
                    ph_[1] = pack2h(s[2*s4][2],   s[2*s4][3]);
                    ph_[2] = pack2h(s[2*s4+1][0], s[2*s4+1][1]);
                    ph_[3] = pack2h(s[2*s4+1][2], s[2*s4+1][3]);
                    uint32_t ksb = s4 * 32;
                    #pragma unroll
                    for (int jp2 = 0; jp2 < 2; ++jp2) {
                        uint32_t v4[2][4];
                        ldsm4(v4[0], vb + bofff[2*jp2]     + ksb);
                        ldsm4(v4[1], vb + bofff[2*jp2 + 1] + ksb);
                        #pragma unroll
                        for (int p = 0; p < 2; ++p)
                            #pragma unroll
                            for (int jj = 0; jj < 2; ++jj)
                                mma16816(acc[(2*jp2+p)*2+jj], ph_, v4[p] + jj*2);
                    }
                }
            }
        }
        __syncthreads();   // all warps done with this phase's smem before Q reload

        // ---- epilogue: y = acc / l, write truncated fp16 [tok][C] ----
        int b = bh >> 4, h = bh & 15;
        float inv0 = 1.f / l0, inv1 = 1.f / l1;
        size_t tok0 = (size_t)b*Tt + q0 + r;
        size_t tok1 = tok0 + 8;
        #pragma unroll
        for (int j = 0; j < 8; ++j) {
            int col = h*HD + j*8 + qc*2;
            *(uint32_t*)&g_yh[tok0*Cc + col] = pack2h(acc[j][0]*inv0, acc[j][1]*inv0);
            *(uint32_t*)&g_yh[tok1*Cc + col] = pack2h(acc[j][2]*inv1, acc[j][3]*inv1);
        }
    }
}

// ---------------------------------------------------------------------------
extern "C" void kernel_launch(void* const* d_in, const int* in_sizes, int n_in,
                              void* d_out, int out_size) {
    const float* x     = (const float*)d_in[0];
    const float* Wqkv  = (const float*)d_in[1];
    const float* bqkv  = (const float*)d_in[2];
    const float* Wproj = (const float*)d_in[3];
    const float* bproj = (const float*)d_in[4];
    const unsigned* amask = (const unsigned*)d_in[5];
    const unsigned* rmask = (const unsigned*)d_in[6];
    float* out = (float*)d_out;

    cudaFuncSetAttribute(gemm_mma<0>, cudaFuncAttributeMaxDynamicSharedMemorySize, GEMM_SMEM);
    cudaFuncSetAttribute(gemm_mma<1>, cudaFuncAttributeMaxDynamicSharedMemorySize, GEMM_SMEM);
    cudaFuncSetAttribute(flash_mma, cudaFuncAttributeMaxDynamicSharedMemorySize, FLASH_SMEM);

    __half *xh, *wqh, *wph, *yh;
    cudaGetSymbolAddress((void**)&xh,  g_xh);
    cudaGetSymbolAddress((void**)&wqh, g_wqh); cudaGetSymbolAddress((void**)&wph, g_wph);
    cudaGetSymbolAddress((void**)&yh,  g_yh);

    cvt_all<<<8192, 256>>>(x, Wqkv, Wproj);

    gemm_mma<0><<<dim3(C3/128, NTOK/128), 256, GEMM_SMEM>>>(xh, wqh, bqkv, nullptr, nullptr, Cc);

    flash_mma<<<dim3(NQB/2, Bsz*Hh), 256, FLASH_SMEM>>>(amask);

    gemm_mma<1><<<dim3(Cc/128, NTOK/128), 256, GEMM_SMEM>>>(yh, wph, bproj, rmask, out, Cc);
}